// round 1
// baseline (speedup 1.0000x reference)
#include <cuda_runtime.h>
#include <math.h>

#define B_     32
#define C_     256
#define H_     56
#define W_     56
#define HW_    3136
#define TOK    100352          // B_*H_*W_
#define NWIN   2048            // B_ * 8 * 8
#define NHEAD  8
#define HID    1024

// ---------------- scratch (device globals; no allocations allowed) ----------
__device__ float g_short[(size_t)TOK * C_];        // shortcut, (B,HW,C)
__device__ float g_bufA [(size_t)TOK * C_];        // ln1 out -> attn out -> mlp out
__device__ float g_qkv  [(size_t)TOK * 3 * C_];    // qkv; later reused for ln2 out
__device__ float g_xres [(size_t)TOK * C_];        // x after attention residual
__device__ float g_hid  [(size_t)TOK * HID];       // mlp hidden

// roll(-3) + window partition row map: window-order row m -> spatial token.
// Same map serves the inverse scatter (roll back) in the proj epilogue.
__device__ __forceinline__ int win_token(int m) {
    int win = m / 49;
    int n   = m - win * 49;
    int b   = win >> 6;
    int r   = win & 63;
    int i   = n / 7;
    int j   = n - i * 7;
    int h = (r >> 3) * 7 + i + 3; if (h >= H_) h -= H_;
    int w = (r & 7)  * 7 + j + 3; if (w >= W_) w -= W_;
    return (b * H_ + h) * W_ + w;
}

// ---------------- transpose (B,C,HW) <-> (B,HW,C) ---------------------------
__global__ void k_transpose_in(const float* __restrict__ x) {
    __shared__ float tile[32][33];
    int b = blockIdx.z;
    int hw0 = blockIdx.x * 32;
    int c0  = blockIdx.y * 32;
    int tx = threadIdx.x, ty = threadIdx.y;
    const float* src = x + ((size_t)b * C_ + c0) * HW_ + hw0;
    #pragma unroll
    for (int j = ty; j < 32; j += 8)
        tile[j][tx] = src[(size_t)j * HW_ + tx];        // tile[c][hw]
    __syncthreads();
    float* dst = g_short + ((size_t)b * HW_ + hw0) * C_ + c0;
    #pragma unroll
    for (int j = ty; j < 32; j += 8)
        dst[(size_t)j * C_ + tx] = tile[tx][j];
}

__global__ void k_transpose_out(float* __restrict__ out) {
    __shared__ float tile[32][33];
    int b = blockIdx.z;
    int hw0 = blockIdx.x * 32;
    int c0  = blockIdx.y * 32;
    int tx = threadIdx.x, ty = threadIdx.y;
    const float* src = g_bufA + ((size_t)b * HW_ + hw0) * C_ + c0;
    #pragma unroll
    for (int j = ty; j < 32; j += 8)
        tile[j][tx] = src[(size_t)j * C_ + tx];         // tile[hw][c]
    __syncthreads();
    float* dst = out + ((size_t)b * C_ + c0) * HW_ + hw0;
    #pragma unroll
    for (int j = ty; j < 32; j += 8)
        dst[(size_t)j * HW_ + tx] = tile[tx][j];
}

// ---------------- layernorm over C=256 per token (64 threads, float4) -------
__global__ void k_ln(const float* __restrict__ x, const float* __restrict__ g,
                     const float* __restrict__ bb, float* __restrict__ out) {
    int token = blockIdx.x;
    int tid = threadIdx.x;                // 64 threads
    float4 v = ((const float4*)(x + (size_t)token * C_))[tid];
    float s  = v.x + v.y + v.z + v.w;
    float ss = v.x * v.x + v.y * v.y + v.z * v.z + v.w * v.w;
    #pragma unroll
    for (int o = 16; o; o >>= 1) {
        s  += __shfl_xor_sync(0xffffffffu, s, o);
        ss += __shfl_xor_sync(0xffffffffu, ss, o);
    }
    __shared__ float sh[4];
    if ((tid & 31) == 0) { sh[tid >> 5] = s; sh[2 + (tid >> 5)] = ss; }
    __syncthreads();
    s = sh[0] + sh[1]; ss = sh[2] + sh[3];
    float mean = s * (1.0f / C_);
    float var  = ss * (1.0f / C_) - mean * mean;
    float rstd = rsqrtf(var + 1e-5f);
    float4 gg = ((const float4*)g)[tid];
    float4 bv = ((const float4*)bb)[tid];
    float4 o4;
    o4.x = (v.x - mean) * rstd * gg.x + bv.x;
    o4.y = (v.y - mean) * rstd * gg.y + bv.y;
    o4.z = (v.z - mean) * rstd * gg.z + bv.z;
    o4.w = (v.w - mean) * rstd * gg.w + bv.w;
    ((float4*)(out + (size_t)token * C_))[tid] = o4;
}

// ---------------- SGEMM 128x128x8, 256 thr, 8x8 microtile -------------------
// EPI: 0 = bias                 (qkv)
//      1 = bias + exact GELU    (mlp1)
//      2 = bias + scatter via win_token + add extra[scattered]   (proj)
//      3 = bias + add extra[row]                                  (mlp2)
// GATHER: A rows indexed through win_token (qkv input gather)
template<int EPI, bool GATHER>
__global__ __launch_bounds__(256, 2)
void k_gemm(const float* __restrict__ A, const float* __restrict__ Bm,
            const float* __restrict__ bias, const float* __restrict__ extra,
            float* __restrict__ Cout, int N, int K)
{
    const int BK = 8;
    __shared__ float As[BK][128];
    __shared__ float Bs[BK][128];
    int tid = threadIdx.x;
    int bm = blockIdx.x * 128;
    int bn = blockIdx.y * 128;

    int aRow = tid >> 1;
    int aCol = (tid & 1) * 4;
    int gRowA = bm + aRow;
    int srcRow = GATHER ? win_token(gRowA) : gRowA;
    const float* aPtr = A + (size_t)srcRow * K + aCol;

    int bRow = tid >> 5;
    int bCol = (tid & 31) * 4;
    const float* bPtr = Bm + (size_t)bRow * N + bn + bCol;

    int tRow = (tid >> 4) * 8;
    int tCol = (tid & 15) * 8;

    float acc[8][8];
    #pragma unroll
    for (int i = 0; i < 8; i++)
        #pragma unroll
        for (int j = 0; j < 8; j++) acc[i][j] = 0.f;

    for (int k0 = 0; k0 < K; k0 += BK) {
        float4 a  = *(const float4*)(aPtr + k0);
        float4 bv = *(const float4*)(bPtr + (size_t)k0 * N);
        As[aCol + 0][aRow] = a.x;
        As[aCol + 1][aRow] = a.y;
        As[aCol + 2][aRow] = a.z;
        As[aCol + 3][aRow] = a.w;
        *(float4*)(&Bs[bRow][bCol]) = bv;
        __syncthreads();
        #pragma unroll
        for (int kk = 0; kk < BK; kk++) {
            float ra[8], rb[8];
            #pragma unroll
            for (int i = 0; i < 8; i++) ra[i] = As[kk][tRow + i];
            #pragma unroll
            for (int j = 0; j < 8; j++) rb[j] = Bs[kk][tCol + j];
            #pragma unroll
            for (int i = 0; i < 8; i++)
                #pragma unroll
                for (int j = 0; j < 8; j++)
                    acc[i][j] += ra[i] * rb[j];
        }
        __syncthreads();
    }

    float bcol[8];
    #pragma unroll
    for (int j = 0; j < 8; j++) bcol[j] = bias[bn + tCol + j];

    #pragma unroll
    for (int i = 0; i < 8; i++) {
        int gr = bm + tRow + i;
        size_t orow = (EPI == 2) ? (size_t)win_token(gr) : (size_t)gr;
        float* op = Cout + orow * N + bn + tCol;
        float ex[8];
        if (EPI == 2 || EPI == 3) {
            const float* ep = extra + orow * N + bn + tCol;
            #pragma unroll
            for (int j = 0; j < 8; j++) ex[j] = ep[j];
        }
        float vo[8];
        #pragma unroll
        for (int j = 0; j < 8; j++) {
            float v = acc[i][j] + bcol[j];
            if (EPI == 1) v = 0.5f * v * (1.0f + erff(v * 0.7071067811865475f));
            if (EPI == 2 || EPI == 3) v += ex[j];
            vo[j] = v;
        }
        *(float4*)(op)     = make_float4(vo[0], vo[1], vo[2], vo[3]);
        *(float4*)(op + 4) = make_float4(vo[4], vo[5], vo[6], vo[7]);
    }
}

// ---------------- windowed attention: one block per (window, head) ----------
__global__ void __launch_bounds__(128)
k_attn(const float* __restrict__ qkv, float* __restrict__ out) {
    __shared__ float qs[49][33], ks[49][33], vs[49][33];
    __shared__ float S[49][50];
    int win  = blockIdx.x >> 3;
    int head = blockIdx.x & 7;
    int tid = threadIdx.x;
    int base = win * 49;

    for (int idx = tid; idx < 49 * 32; idx += 128) {
        int n = idx >> 5, d = idx & 31;
        const float* p = qkv + (size_t)(base + n) * 768 + head * 32 + d;
        qs[n][d] = p[0];
        ks[n][d] = p[256];
        vs[n][d] = p[512];
    }
    __syncthreads();

    const float scale = 0.1767766952966369f;   // 1/sqrt(32)
    for (int idx = tid; idx < 49 * 49; idx += 128) {
        int n = idx / 49, m = idx - n * 49;
        float acc = 0.f;
        #pragma unroll
        for (int d = 0; d < 32; d++) acc += qs[n][d] * ks[m][d];
        S[n][m] = acc * scale;
    }
    __syncthreads();

    if (tid < 49) {
        float mx = -1e30f;
        #pragma unroll 7
        for (int m = 0; m < 49; m++) mx = fmaxf(mx, S[tid][m]);
        float sum = 0.f;
        #pragma unroll 7
        for (int m = 0; m < 49; m++) { float e = __expf(S[tid][m] - mx); S[tid][m] = e; sum += e; }
        float inv = 1.0f / sum;
        #pragma unroll 7
        for (int m = 0; m < 49; m++) S[tid][m] *= inv;
    }
    __syncthreads();

    for (int idx = tid; idx < 49 * 32; idx += 128) {
        int n = idx >> 5, d = idx & 31;
        float acc = 0.f;
        #pragma unroll
        for (int m = 0; m < 49; m++) acc += S[n][m] * vs[m][d];
        out[(size_t)(base + n) * C_ + head * 32 + d] = acc;
    }
}

// ---------------- launch ----------------------------------------------------
extern "C" void kernel_launch(void* const* d_in, const int* in_sizes, int n_in,
                              void* d_out, int out_size) {
    const float* x      = (const float*)d_in[0];
    const float* n1_g   = (const float*)d_in[1];
    const float* n1_b   = (const float*)d_in[2];
    const float* qkv_w  = (const float*)d_in[3];
    const float* qkv_b  = (const float*)d_in[4];
    const float* proj_w = (const float*)d_in[5];
    const float* proj_b = (const float*)d_in[6];
    const float* n2_g   = (const float*)d_in[7];
    const float* n2_b   = (const float*)d_in[8];
    const float* mlp_w1 = (const float*)d_in[9];
    const float* mlp_b1 = (const float*)d_in[10];
    const float* mlp_w2 = (const float*)d_in[11];
    const float* mlp_b2 = (const float*)d_in[12];
    float* out = (float*)d_out;

    float *p_short, *p_bufA, *p_qkv, *p_xres, *p_hid;
    cudaGetSymbolAddress((void**)&p_short, g_short);
    cudaGetSymbolAddress((void**)&p_bufA,  g_bufA);
    cudaGetSymbolAddress((void**)&p_qkv,   g_qkv);
    cudaGetSymbolAddress((void**)&p_xres,  g_xres);
    cudaGetSymbolAddress((void**)&p_hid,   g_hid);

    dim3 tb(32, 8);
    // 1. (B,C,HW) -> (B,HW,C) shortcut
    k_transpose_in<<<dim3(98, 8, 32), tb>>>(x);
    // 2. LN1
    k_ln<<<TOK, 64>>>(p_short, n1_g, n1_b, p_bufA);
    // 3. qkv = gather(ln1) @ qkv_w + b      (gather = roll + window partition)
    k_gemm<0, true ><<<dim3(784, 6), 256>>>(p_bufA, qkv_w, qkv_b, nullptr, p_qkv, 768, 256);
    // 4. windowed MHSA
    k_attn<<<NWIN * NHEAD, 128>>>(p_qkv, p_bufA);
    // 5. xres = shortcut + scatter(attn_o @ proj_w + b)
    k_gemm<2, false><<<dim3(784, 2), 256>>>(p_bufA, proj_w, proj_b, p_short, p_xres, 256, 256);
    // 6. LN2 (reuse qkv buffer)
    k_ln<<<TOK, 64>>>(p_xres, n2_g, n2_b, p_qkv);
    // 7. hid = gelu(ln2 @ w1 + b1)
    k_gemm<1, false><<<dim3(784, 8), 256>>>(p_qkv, mlp_w1, mlp_b1, nullptr, p_hid, 1024, 256);
    // 8. y = xres + hid @ w2 + b2
    k_gemm<3, false><<<dim3(784, 2), 256>>>(p_hid, mlp_w2, mlp_b2, p_xres, p_bufA, 256, 1024);
    // 9. (B,HW,C) -> (B,C,HW)
    k_transpose_out<<<dim3(98, 8, 32), tb>>>(out);
}

// round 4
// speedup vs baseline: 1.4448x; 1.4448x over previous
#include <cuda_runtime.h>
#include <math.h>
#include <stdint.h>

#define B_     32
#define C_     256
#define H_     56
#define W_     56
#define HW_    3136
#define TOK    100352          // B_*H_*W_
#define NWIN   2048            // B_ * 8 * 8
#define NHEAD  8
#define HID    1024

// ---------------- scratch (device globals; no allocations allowed) ----------
__device__ float g_short[(size_t)TOK * C_];        // shortcut, (B,HW,C)
__device__ float g_bufA [(size_t)TOK * C_];        // ln1 out -> attn out -> mlp out
__device__ float g_qkv  [(size_t)TOK * 3 * C_];    // qkv; later reused for ln2 out
__device__ float g_xres [(size_t)TOK * C_];        // x after attention residual
__device__ float g_hid  [(size_t)TOK * HID];       // mlp hidden

// roll(-3) + window partition row map: window-order row m -> spatial token.
__device__ __forceinline__ int win_token(int m) {
    int win = m / 49;
    int n   = m - win * 49;
    int b   = win >> 6;
    int r   = win & 63;
    int i   = n / 7;
    int j   = n - i * 7;
    int h = (r >> 3) * 7 + i + 3; if (h >= H_) h -= H_;
    int w = (r & 7)  * 7 + j + 3; if (w >= W_) w -= W_;
    return (b * H_ + h) * W_ + w;
}

// ---------------- tf32 helpers ----------------------------------------------
__device__ __forceinline__ float cvt_tf32(float x) {
    uint32_t u;
    asm("cvt.rna.tf32.f32 %0, %1;" : "=r"(u) : "f"(x));
    return __uint_as_float(u);
}

__device__ __forceinline__ void mma_tf32(float (&d)[4],
                                         uint32_t a0, uint32_t a1, uint32_t a2, uint32_t a3,
                                         uint32_t b0, uint32_t b1) {
    asm volatile(
        "mma.sync.aligned.m16n8k8.row.col.f32.tf32.tf32.f32 "
        "{%0,%1,%2,%3}, {%4,%5,%6,%7}, {%8,%9}, {%0,%1,%2,%3};\n"
        : "+f"(d[0]), "+f"(d[1]), "+f"(d[2]), "+f"(d[3])
        : "r"(a0), "r"(a1), "r"(a2), "r"(a3), "r"(b0), "r"(b1));
}

// ---------------- transpose (B,C,HW) <-> (B,HW,C) ---------------------------
__global__ void k_transpose_in(const float* __restrict__ x) {
    __shared__ float tile[32][33];
    int b = blockIdx.z;
    int hw0 = blockIdx.x * 32;
    int c0  = blockIdx.y * 32;
    int tx = threadIdx.x, ty = threadIdx.y;
    const float* src = x + ((size_t)b * C_ + c0) * HW_ + hw0;
    #pragma unroll
    for (int j = ty; j < 32; j += 8)
        tile[j][tx] = src[(size_t)j * HW_ + tx];
    __syncthreads();
    float* dst = g_short + ((size_t)b * HW_ + hw0) * C_ + c0;
    #pragma unroll
    for (int j = ty; j < 32; j += 8)
        dst[(size_t)j * C_ + tx] = tile[tx][j];
}

__global__ void k_transpose_out(float* __restrict__ out) {
    __shared__ float tile[32][33];
    int b = blockIdx.z;
    int hw0 = blockIdx.x * 32;
    int c0  = blockIdx.y * 32;
    int tx = threadIdx.x, ty = threadIdx.y;
    const float* src = g_bufA + ((size_t)b * HW_ + hw0) * C_ + c0;
    #pragma unroll
    for (int j = ty; j < 32; j += 8)
        tile[j][tx] = src[(size_t)j * C_ + tx];
    __syncthreads();
    float* dst = out + ((size_t)b * C_ + c0) * HW_ + hw0;
    #pragma unroll
    for (int j = ty; j < 32; j += 8)
        dst[(size_t)j * HW_ + tx] = tile[tx][j];
}

// ---------------- layernorm over C=256 per token (64 threads, float4) -------
__global__ void k_ln(const float* __restrict__ x, const float* __restrict__ g,
                     const float* __restrict__ bb, float* __restrict__ out) {
    int token = blockIdx.x;
    int tid = threadIdx.x;
    float4 v = ((const float4*)(x + (size_t)token * C_))[tid];
    float s  = v.x + v.y + v.z + v.w;
    float ss = v.x * v.x + v.y * v.y + v.z * v.z + v.w * v.w;
    #pragma unroll
    for (int o = 16; o; o >>= 1) {
        s  += __shfl_xor_sync(0xffffffffu, s, o);
        ss += __shfl_xor_sync(0xffffffffu, ss, o);
    }
    __shared__ float sh[4];
    if ((tid & 31) == 0) { sh[tid >> 5] = s; sh[2 + (tid >> 5)] = ss; }
    __syncthreads();
    s = sh[0] + sh[1]; ss = sh[2] + sh[3];
    float mean = s * (1.0f / C_);
    float var  = ss * (1.0f / C_) - mean * mean;
    float rstd = rsqrtf(var + 1e-5f);
    float4 gg = ((const float4*)g)[tid];
    float4 bv = ((const float4*)bb)[tid];
    float4 o4;
    o4.x = (v.x - mean) * rstd * gg.x + bv.x;
    o4.y = (v.y - mean) * rstd * gg.y + bv.y;
    o4.z = (v.z - mean) * rstd * gg.z + bv.z;
    o4.w = (v.w - mean) * rstd * gg.w + bv.w;
    ((float4*)(out + (size_t)token * C_))[tid] = o4;
}

// ---------------- tf32 tensor-core GEMM 128x64, BK=32, 256 thr --------------
// EPI: 0 bias | 1 bias+GELU | 2 bias+scatter(win_token)+extra | 3 bias+extra
// GATHER: A rows through win_token
#define AS_STRIDE 36
#define BS_STRIDE 68
template<int EPI, bool GATHER>
__global__ __launch_bounds__(256, 2)
void k_gemm(const float* __restrict__ A, const float* __restrict__ Bm,
            const float* __restrict__ bias, const float* __restrict__ extra,
            float* __restrict__ Cout, int N, int K)
{
    __shared__ float As[128 * AS_STRIDE];   // [row][k]
    __shared__ float Bs[32 * BS_STRIDE];    // [k][n]

    int tid = threadIdx.x;
    int bm = blockIdx.x * 128;
    int bn = blockIdx.y * 64;

    int lane = tid & 31;
    int wid  = tid >> 5;
    int warpM = wid & 3;          // 4 warps over M  -> 32-row tiles
    int warpN = wid >> 2;         // 2 warps over N  -> 32-col tiles

    // global load mapping
    int arow = tid >> 1;
    int acol = (tid & 1) * 16;
    int aSrcRow = GATHER ? win_token(bm + arow) : (bm + arow);
    const float* aPtr = A + (size_t)aSrcRow * K + acol;

    int brow = tid & 31;
    int bcol = (tid >> 5) * 8;
    const float* bPtr = Bm + (size_t)brow * N + bn + bcol;

    float4 ra[4], rb[2];
    #pragma unroll
    for (int i = 0; i < 4; i++) ra[i] = *(const float4*)(aPtr + 4 * i);
    #pragma unroll
    for (int i = 0; i < 2; i++) rb[i] = *(const float4*)(bPtr + 4 * i);

    float acc[2][4][4];
    #pragma unroll
    for (int mt = 0; mt < 2; mt++)
        #pragma unroll
        for (int nt = 0; nt < 4; nt++)
            #pragma unroll
            for (int e = 0; e < 4; e++) acc[mt][nt][e] = 0.f;

    int qrow = lane >> 2;     // 0..7
    int qcol = lane & 3;      // 0..3

    for (int k0 = 0; k0 < K; k0 += 32) {
        // store prefetched regs to smem (tf32-rounded)
        #pragma unroll
        for (int i = 0; i < 4; i++) {
            float4 t;
            t.x = cvt_tf32(ra[i].x); t.y = cvt_tf32(ra[i].y);
            t.z = cvt_tf32(ra[i].z); t.w = cvt_tf32(ra[i].w);
            *(float4*)&As[arow * AS_STRIDE + acol + 4 * i] = t;
        }
        #pragma unroll
        for (int i = 0; i < 2; i++) {
            float4 t;
            t.x = cvt_tf32(rb[i].x); t.y = cvt_tf32(rb[i].y);
            t.z = cvt_tf32(rb[i].z); t.w = cvt_tf32(rb[i].w);
            *(float4*)&Bs[brow * BS_STRIDE + bcol + 4 * i] = t;
        }
        __syncthreads();

        if (k0 + 32 < K) {
            #pragma unroll
            for (int i = 0; i < 4; i++) ra[i] = *(const float4*)(aPtr + k0 + 32 + 4 * i);
            #pragma unroll
            for (int i = 0; i < 2; i++) rb[i] = *(const float4*)(bPtr + (size_t)(k0 + 32) * N + 4 * i);
        }

        #pragma unroll
        for (int ks = 0; ks < 4; ks++) {
            int k = ks * 8;
            uint32_t af[2][4], bf[4][2];
            #pragma unroll
            for (int mt = 0; mt < 2; mt++) {
                int r0 = warpM * 32 + mt * 16 + qrow;
                af[mt][0] = __float_as_uint(As[(r0    ) * AS_STRIDE + k + qcol]);
                af[mt][1] = __float_as_uint(As[(r0 + 8) * AS_STRIDE + k + qcol]);
                af[mt][2] = __float_as_uint(As[(r0    ) * AS_STRIDE + k + 4 + qcol]);
                af[mt][3] = __float_as_uint(As[(r0 + 8) * AS_STRIDE + k + 4 + qcol]);
            }
            #pragma unroll
            for (int nt = 0; nt < 4; nt++) {
                int n0 = warpN * 32 + nt * 8 + qrow;
                bf[nt][0] = __float_as_uint(Bs[(k + qcol    ) * BS_STRIDE + n0]);
                bf[nt][1] = __float_as_uint(Bs[(k + 4 + qcol) * BS_STRIDE + n0]);
            }
            #pragma unroll
            for (int mt = 0; mt < 2; mt++)
                #pragma unroll
                for (int nt = 0; nt < 4; nt++)
                    mma_tf32(acc[mt][nt], af[mt][0], af[mt][1], af[mt][2], af[mt][3],
                             bf[nt][0], bf[nt][1]);
        }
        __syncthreads();
    }

    // -------- epilogue --------
    #pragma unroll
    for (int mt = 0; mt < 2; mt++) {
        #pragma unroll
        for (int half = 0; half < 2; half++) {       // c0,c1 then c2,c3 (row+8)
            int gr = bm + warpM * 32 + mt * 16 + qrow + half * 8;
            size_t orow = (EPI == 2) ? (size_t)win_token(gr) : (size_t)gr;
            #pragma unroll
            for (int nt = 0; nt < 4; nt++) {
                int col = bn + warpN * 32 + nt * 8 + 2 * qcol;
                float v0 = acc[mt][nt][2 * half + 0] + bias[col];
                float v1 = acc[mt][nt][2 * half + 1] + bias[col + 1];
                if (EPI == 1) {
                    v0 = 0.5f * v0 * (1.0f + erff(v0 * 0.7071067811865475f));
                    v1 = 0.5f * v1 * (1.0f + erff(v1 * 0.7071067811865475f));
                }
                if (EPI == 2 || EPI == 3) {
                    const float* ep = extra + orow * N + col;
                    v0 += ep[0];
                    v1 += ep[1];
                }
                *(float2*)(Cout + orow * N + col) = make_float2(v0, v1);
            }
        }
    }
}

// ---------------- windowed attention: one block per (window, head) ----------
__global__ void __launch_bounds__(128)
k_attn(const float* __restrict__ qkv, float* __restrict__ out) {
    __shared__ float qs[49][33], ks[49][33], vs[49][33];
    __shared__ float S[49][50];
    int win  = blockIdx.x >> 3;
    int head = blockIdx.x & 7;
    int tid = threadIdx.x;
    int base = win * 49;

    for (int idx = tid; idx < 49 * 32; idx += 128) {
        int n = idx >> 5, d = idx & 31;
        const float* p = qkv + (size_t)(base + n) * 768 + head * 32 + d;
        qs[n][d] = p[0];
        ks[n][d] = p[256];
        vs[n][d] = p[512];
    }
    __syncthreads();

    const float scale = 0.1767766952966369f;
    for (int idx = tid; idx < 49 * 49; idx += 128) {
        int n = idx / 49, m = idx - n * 49;
        float acc = 0.f;
        #pragma unroll
        for (int d = 0; d < 32; d++) acc += qs[n][d] * ks[m][d];
        S[n][m] = acc * scale;
    }
    __syncthreads();

    if (tid < 49) {
        float mx = -1e30f;
        #pragma unroll 7
        for (int m = 0; m < 49; m++) mx = fmaxf(mx, S[tid][m]);
        float sum = 0.f;
        #pragma unroll 7
        for (int m = 0; m < 49; m++) { float e = __expf(S[tid][m] - mx); S[tid][m] = e; sum += e; }
        float inv = 1.0f / sum;
        #pragma unroll 7
        for (int m = 0; m < 49; m++) S[tid][m] *= inv;
    }
    __syncthreads();

    for (int idx = tid; idx < 49 * 32; idx += 128) {
        int n = idx >> 5, d = idx & 31;
        float acc = 0.f;
        #pragma unroll
        for (int m = 0; m < 49; m++) acc += S[n][m] * vs[m][d];
        out[(size_t)(base + n) * C_ + head * 32 + d] = acc;
    }
}

// ---------------- launch ----------------------------------------------------
extern "C" void kernel_launch(void* const* d_in, const int* in_sizes, int n_in,
                              void* d_out, int out_size) {
    const float* x      = (const float*)d_in[0];
    const float* n1_g   = (const float*)d_in[1];
    const float* n1_b   = (const float*)d_in[2];
    const float* qkv_w  = (const float*)d_in[3];
    const float* qkv_b  = (const float*)d_in[4];
    const float* proj_w = (const float*)d_in[5];
    const float* proj_b = (const float*)d_in[6];
    const float* n2_g   = (const float*)d_in[7];
    const float* n2_b   = (const float*)d_in[8];
    const float* mlp_w1 = (const float*)d_in[9];
    const float* mlp_b1 = (const float*)d_in[10];
    const float* mlp_w2 = (const float*)d_in[11];
    const float* mlp_b2 = (const float*)d_in[12];
    float* out = (float*)d_out;

    float *p_short, *p_bufA, *p_qkv, *p_xres, *p_hid;
    cudaGetSymbolAddress((void**)&p_short, g_short);
    cudaGetSymbolAddress((void**)&p_bufA,  g_bufA);
    cudaGetSymbolAddress((void**)&p_qkv,   g_qkv);
    cudaGetSymbolAddress((void**)&p_xres,  g_xres);
    cudaGetSymbolAddress((void**)&p_hid,   g_hid);

    dim3 tb(32, 8);
    k_transpose_in<<<dim3(98, 8, 32), tb>>>(x);
    k_ln<<<TOK, 64>>>(p_short, n1_g, n1_b, p_bufA);
    k_gemm<0, true ><<<dim3(784, 12), 256>>>(p_bufA, qkv_w, qkv_b, nullptr, p_qkv, 768, 256);
    k_attn<<<NWIN * NHEAD, 128>>>(p_qkv, p_bufA);
    k_gemm<2, false><<<dim3(784, 4), 256>>>(p_bufA, proj_w, proj_b, p_short, p_xres, 256, 256);
    k_ln<<<TOK, 64>>>(p_xres, n2_g, n2_b, p_qkv);
    k_gemm<1, false><<<dim3(784, 16), 256>>>(p_qkv, mlp_w1, mlp_b1, nullptr, p_hid, 1024, 256);
    k_gemm<3, false><<<dim3(784, 4), 256>>>(p_hid, mlp_w2, mlp_b2, p_xres, p_bufA, 256, 1024);
    k_transpose_out<<<dim3(98, 8, 32), tb>>>(out);
}

// round 7
// speedup vs baseline: 2.4519x; 1.6970x over previous
#include <cuda_runtime.h>
#include <math.h>
#include <stdint.h>

#define B_     32
#define C_     256
#define H_     56
#define W_     56
#define HW_    3136
#define TOK    100352          // B_*H_*W_
#define NWIN   2048
#define NHEAD  8
#define HID    1024

// ---------------- scratch (device globals) ----------------------------------
__device__ float g_short[(size_t)TOK * C_];
__device__ float g_bufA [(size_t)TOK * C_];
__device__ float g_qkv  [(size_t)TOK * 3 * C_];
__device__ float g_xres [(size_t)TOK * C_];
__device__ float g_hid  [(size_t)TOK * HID];
__device__ float g_wts  [786432];              // tf32-rounded weights

#define WOFF_QKV  0
#define WOFF_PROJ 196608
#define WOFF_W1   262144
#define WOFF_W2   524288

// roll(-3) + window partition row map
__device__ __forceinline__ int win_token(int m) {
    int win = m / 49;
    int n   = m - win * 49;
    int b   = win >> 6;
    int r   = win & 63;
    int i   = n / 7;
    int j   = n - i * 7;
    int h = (r >> 3) * 7 + i + 3; if (h >= H_) h -= H_;
    int w = (r & 7)  * 7 + j + 3; if (w >= W_) w -= W_;
    return (b * H_ + h) * W_ + w;
}

// ---------------- tf32 / mma / cp.async helpers ------------------------------
__device__ __forceinline__ float cvt_tf32(float x) {
    uint32_t u;
    asm("cvt.rna.tf32.f32 %0, %1;" : "=r"(u) : "f"(x));
    return __uint_as_float(u);
}
__device__ __forceinline__ void mma_tf32(float (&d)[4],
                                         uint32_t a0, uint32_t a1, uint32_t a2, uint32_t a3,
                                         uint32_t b0, uint32_t b1) {
    asm volatile(
        "mma.sync.aligned.m16n8k8.row.col.f32.tf32.tf32.f32 "
        "{%0,%1,%2,%3}, {%4,%5,%6,%7}, {%8,%9}, {%0,%1,%2,%3};\n"
        : "+f"(d[0]), "+f"(d[1]), "+f"(d[2]), "+f"(d[3])
        : "r"(a0), "r"(a1), "r"(a2), "r"(a3), "r"(b0), "r"(b1));
}
__device__ __forceinline__ void cp_async16(uint32_t s, const void* g) {
    asm volatile("cp.async.cg.shared.global [%0], [%1], 16;\n" :: "r"(s), "l"(g));
}
__device__ __forceinline__ void cp_commit() { asm volatile("cp.async.commit_group;\n"); }
__device__ __forceinline__ void cp_wait1()  { asm volatile("cp.async.wait_group 1;\n"); }
__device__ __forceinline__ void cp_wait0()  { asm volatile("cp.async.wait_group 0;\n"); }

// ---------------- weight rounding -------------------------------------------
__global__ void k_round(const float* __restrict__ src, float* __restrict__ dst, int n) {
    int i = blockIdx.x * 256 + threadIdx.x;
    if (i < n) dst[i] = cvt_tf32(src[i]);
}

// ---------------- transposes -------------------------------------------------
__global__ void k_transpose_in(const float* __restrict__ x) {
    __shared__ float tile[32][33];
    int b = blockIdx.z, hw0 = blockIdx.x * 32, c0 = blockIdx.y * 32;
    int tx = threadIdx.x, ty = threadIdx.y;
    const float* src = x + ((size_t)b * C_ + c0) * HW_ + hw0;
    #pragma unroll
    for (int j = ty; j < 32; j += 8) tile[j][tx] = src[(size_t)j * HW_ + tx];
    __syncthreads();
    float* dst = g_short + ((size_t)b * HW_ + hw0) * C_ + c0;
    #pragma unroll
    for (int j = ty; j < 32; j += 8) dst[(size_t)j * C_ + tx] = tile[tx][j];
}
__global__ void k_transpose_out(float* __restrict__ out) {
    __shared__ float tile[32][33];
    int b = blockIdx.z, hw0 = blockIdx.x * 32, c0 = blockIdx.y * 32;
    int tx = threadIdx.x, ty = threadIdx.y;
    const float* src = g_bufA + ((size_t)b * HW_ + hw0) * C_ + c0;
    #pragma unroll
    for (int j = ty; j < 32; j += 8) tile[j][tx] = src[(size_t)j * C_ + tx];
    __syncthreads();
    float* dst = out + ((size_t)b * C_ + c0) * HW_ + hw0;
    #pragma unroll
    for (int j = ty; j < 32; j += 8) dst[(size_t)j * HW_ + tx] = tile[tx][j];
}

// ---------------- layernorm (ROUND: tf32-round output for GEMM-A) ------------
template<bool ROUND>
__global__ void k_ln(const float* __restrict__ x, const float* __restrict__ g,
                     const float* __restrict__ bb, float* __restrict__ out) {
    int token = blockIdx.x;
    int tid = threadIdx.x;
    float4 v = ((const float4*)(x + (size_t)token * C_))[tid];
    float s  = v.x + v.y + v.z + v.w;
    float ss = v.x * v.x + v.y * v.y + v.z * v.z + v.w * v.w;
    #pragma unroll
    for (int o = 16; o; o >>= 1) {
        s  += __shfl_xor_sync(0xffffffffu, s, o);
        ss += __shfl_xor_sync(0xffffffffu, ss, o);
    }
    __shared__ float sh[4];
    if ((tid & 31) == 0) { sh[tid >> 5] = s; sh[2 + (tid >> 5)] = ss; }
    __syncthreads();
    s = sh[0] + sh[1]; ss = sh[2] + sh[3];
    float mean = s * (1.0f / C_);
    float var  = ss * (1.0f / C_) - mean * mean;
    float rstd = rsqrtf(var + 1e-5f);
    float4 gg = ((const float4*)g)[tid];
    float4 bv = ((const float4*)bb)[tid];
    float4 o4;
    o4.x = (v.x - mean) * rstd * gg.x + bv.x;
    o4.y = (v.y - mean) * rstd * gg.y + bv.y;
    o4.z = (v.z - mean) * rstd * gg.z + bv.z;
    o4.w = (v.w - mean) * rstd * gg.w + bv.w;
    if (ROUND) {
        o4.x = cvt_tf32(o4.x); o4.y = cvt_tf32(o4.y);
        o4.z = cvt_tf32(o4.z); o4.w = cvt_tf32(o4.w);
    }
    ((float4*)(out + (size_t)token * C_))[tid] = o4;
}

// ---------------- tf32 GEMM 128x128, BK=16, cp.async double-buffered ---------
// Inputs A and Bm must already be tf32-rounded.
// EPI: 0 bias | 1 bias+GELU(+tf32 round) | 2 bias+scatter+extra | 3 bias+extra
#define AS_STRIDE 20            // 16 data + 4 pad  -> conflict-free frags
#define BS_STRIDE 136           // 128 data + 8 pad -> conflict-free frags
#define ABUF (128 * AS_STRIDE)  // floats per buffer
#define BBUF (16 * BS_STRIDE)

template<int EPI, bool GATHER>
__global__ __launch_bounds__(256, 2)
void k_gemm(const float* __restrict__ A, const float* __restrict__ Bm,
            const float* __restrict__ bias, const float* __restrict__ extra,
            float* __restrict__ Cout, int N, int K)
{
    __shared__ float As[2 * ABUF];
    __shared__ float Bs[2 * BBUF];

    int tid = threadIdx.x;
    int bm = blockIdx.x * 128;
    int bn = blockIdx.y * 128;
    int lane = tid & 31, wid = tid >> 5;
    int warpM = wid >> 1;          // 0..3 (32-row tiles)
    int warpN = wid & 1;           // 0..1 (64-col tiles)
    int qrow = lane >> 2, qcol = lane & 3;

    // A: thread owns one row (t&127), 32B chunk pair selected by t>>7
    int arow = tid & 127;
    int aoff = (tid >> 7) * 8;                       // float offset 0 or 8
    int aSrc = GATHER ? win_token(bm + arow) : (bm + arow);
    const float* aPtr = A + (size_t)aSrc * K + aoff;
    uint32_t aDst = (uint32_t)__cvta_generic_to_shared(As) + (arow * AS_STRIDE + aoff) * 4;

    // B: thread t -> row t>>4 (0..15), float col (t&15)*4 and +64
    int brow = tid >> 4;
    int bcol = (tid & 15) * 4;
    const float* bPtr = Bm + (size_t)brow * N + bn + bcol;
    uint32_t bDst = (uint32_t)__cvta_generic_to_shared(Bs) + (brow * BS_STRIDE + bcol) * 4;

    // prologue: tile 0 -> buffer 0
    cp_async16(aDst,      aPtr);
    cp_async16(aDst + 16, aPtr + 4);
    cp_async16(bDst,        bPtr);
    cp_async16(bDst + 256,  bPtr + 64);     // +64 floats
    cp_commit();

    float acc[2][8][4];
    #pragma unroll
    for (int mt = 0; mt < 2; mt++)
        #pragma unroll
        for (int nt = 0; nt < 8; nt++)
            #pragma unroll
            for (int e = 0; e < 4; e++) acc[mt][nt][e] = 0.f;

    int buf = 0;
    for (int k0 = 0; k0 < K; k0 += 16) {
        int nbuf = buf ^ 1;
        if (k0 + 16 < K) {
            uint32_t ad = aDst + nbuf * (ABUF * 4);
            uint32_t bd = bDst + nbuf * (BBUF * 4);
            const float* ap = aPtr + k0 + 16;
            const float* bp = bPtr + (size_t)(k0 + 16) * N;
            cp_async16(ad,      ap);
            cp_async16(ad + 16, ap + 4);
            cp_async16(bd,       bp);
            cp_async16(bd + 256, bp + 64);
            cp_commit();
            cp_wait1();
        } else {
            cp_wait0();
        }
        __syncthreads();

        const float* as = As + buf * ABUF;
        const float* bs = Bs + buf * BBUF;
        #pragma unroll
        for (int ks = 0; ks < 2; ks++) {
            int k = ks * 8;
            uint32_t af[2][4], bf[8][2];
            #pragma unroll
            for (int mt = 0; mt < 2; mt++) {
                int r0 = warpM * 32 + mt * 16 + qrow;
                af[mt][0] = __float_as_uint(as[(r0    ) * AS_STRIDE + k + qcol]);
                af[mt][1] = __float_as_uint(as[(r0 + 8) * AS_STRIDE + k + qcol]);
                af[mt][2] = __float_as_uint(as[(r0    ) * AS_STRIDE + k + 4 + qcol]);
                af[mt][3] = __float_as_uint(as[(r0 + 8) * AS_STRIDE + k + 4 + qcol]);
            }
            #pragma unroll
            for (int nt = 0; nt < 8; nt++) {
                int n0 = warpN * 64 + nt * 8 + qrow;
                bf[nt][0] = __float_as_uint(bs[(k + qcol    ) * BS_STRIDE + n0]);
                bf[nt][1] = __float_as_uint(bs[(k + 4 + qcol) * BS_STRIDE + n0]);
            }
            #pragma unroll
            for (int mt = 0; mt < 2; mt++)
                #pragma unroll
                for (int nt = 0; nt < 8; nt++)
                    mma_tf32(acc[mt][nt], af[mt][0], af[mt][1], af[mt][2], af[mt][3],
                             bf[nt][0], bf[nt][1]);
        }
        __syncthreads();   // protect buf before next iteration's cp.async overwrites it
        buf = nbuf;
    }

    // -------- epilogue --------
    #pragma unroll
    for (int mt = 0; mt < 2; mt++) {
        #pragma unroll
        for (int half = 0; half < 2; half++) {
            int gr = bm + warpM * 32 + mt * 16 + qrow + half * 8;
            size_t orow = (EPI == 2) ? (size_t)win_token(gr) : (size_t)gr;
            #pragma unroll
            for (int nt = 0; nt < 8; nt++) {
                int col = bn + warpN * 64 + nt * 8 + 2 * qcol;
                float v0 = acc[mt][nt][2 * half + 0] + bias[col];
                float v1 = acc[mt][nt][2 * half + 1] + bias[col + 1];
                if (EPI == 1) {
                    v0 = 0.5f * v0 * (1.0f + erff(v0 * 0.7071067811865475f));
                    v1 = 0.5f * v1 * (1.0f + erff(v1 * 0.7071067811865475f));
                    v0 = cvt_tf32(v0);       // feeds mlp2 as A
                    v1 = cvt_tf32(v1);
                }
                if (EPI == 2 || EPI == 3) {
                    const float* ep = extra + orow * N + col;
                    v0 += ep[0];
                    v1 += ep[1];
                }
                *(float2*)(Cout + orow * N + col) = make_float2(v0, v1);
            }
        }
    }
}

// ---------------- windowed attention: register-resident K / V ----------------
// Block = (window, head), 128 threads = 4 warps.
// QK: lane = key index m, K row in registers, q via broadcast LDS.
// SV: lane = dim d, V column in registers, S via broadcast LDS.
__global__ void __launch_bounds__(128)
k_attn(const float* __restrict__ qkv, float* __restrict__ out) {
    __shared__ float qs[49][36];       // float4-aligned rows for broadcast
    __shared__ float ks[49][33];       // stride 33: conflict-free column loads
    __shared__ float vs[49][33];
    __shared__ float S[49][50];
    int win  = blockIdx.x >> 3;
    int head = blockIdx.x & 7;
    int tid  = threadIdx.x;
    int lane = tid & 31;
    int wj   = tid >> 5;               // warp id 0..3
    int base = win * 49;

    for (int idx = tid; idx < 49 * 32; idx += 128) {
        int n = idx >> 5, d = idx & 31;
        const float* p = qkv + (size_t)(base + n) * 768 + head * 32 + d;
        qs[n][d] = p[0];
        ks[n][d] = p[256];
        vs[n][d] = p[512];
    }
    __syncthreads();

    const float scale = 0.1767766952966369f;   // 1/sqrt(32)

    // ---- QK^T ----
    #pragma unroll
    for (int pass = 0; pass < 2; pass++) {
        int m = pass * 32 + lane;
        bool act = (m < 49);
        int mm = act ? m : 48;
        float kreg[32];
        #pragma unroll
        for (int d = 0; d < 32; d++) kreg[d] = ks[mm][d];
        for (int n = wj; n < 49; n += 4) {
            float acc = 0.f;
            #pragma unroll
            for (int dq = 0; dq < 8; dq++) {
                float4 q4 = *(const float4*)&qs[n][dq * 4];   // broadcast
                acc += q4.x * kreg[dq * 4 + 0];
                acc += q4.y * kreg[dq * 4 + 1];
                acc += q4.z * kreg[dq * 4 + 2];
                acc += q4.w * kreg[dq * 4 + 3];
            }
            if (act) S[n][m] = acc * scale;
        }
    }
    __syncthreads();

    // ---- softmax rows ----
    if (tid < 49) {
        float mx = -1e30f;
        #pragma unroll 7
        for (int m = 0; m < 49; m++) mx = fmaxf(mx, S[tid][m]);
        float sum = 0.f;
        #pragma unroll 7
        for (int m = 0; m < 49; m++) { float e = __expf(S[tid][m] - mx); S[tid][m] = e; sum += e; }
        float inv = 1.0f / sum;
        #pragma unroll 7
        for (int m = 0; m < 49; m++) S[tid][m] *= inv;
    }
    __syncthreads();

    // ---- S @ V ----  (lane = d)
    float vreg[49];
    #pragma unroll
    for (int m = 0; m < 49; m++) vreg[m] = vs[m][lane];
    for (int n = wj; n < 49; n += 4) {
        float acc = 0.f;
        #pragma unroll
        for (int m = 0; m < 49; m++) acc += S[n][m] * vreg[m];   // S broadcast
        out[(size_t)(base + n) * C_ + head * 32 + lane] = cvt_tf32(acc);  // feeds proj
    }
}

// ---------------- launch ----------------------------------------------------
extern "C" void kernel_launch(void* const* d_in, const int* in_sizes, int n_in,
                              void* d_out, int out_size) {
    const float* x      = (const float*)d_in[0];
    const float* n1_g   = (const float*)d_in[1];
    const float* n1_b   = (const float*)d_in[2];
    const float* qkv_w  = (const float*)d_in[3];
    const float* qkv_b  = (const float*)d_in[4];
    const float* proj_w = (const float*)d_in[5];
    const float* proj_b = (const float*)d_in[6];
    const float* n2_g   = (const float*)d_in[7];
    const float* n2_b   = (const float*)d_in[8];
    const float* mlp_w1 = (const float*)d_in[9];
    const float* mlp_b1 = (const float*)d_in[10];
    const float* mlp_w2 = (const float*)d_in[11];
    const float* mlp_b2 = (const float*)d_in[12];
    float* out = (float*)d_out;

    float *p_short, *p_bufA, *p_qkv, *p_xres, *p_hid, *p_wts;
    cudaGetSymbolAddress((void**)&p_short, g_short);
    cudaGetSymbolAddress((void**)&p_bufA,  g_bufA);
    cudaGetSymbolAddress((void**)&p_qkv,   g_qkv);
    cudaGetSymbolAddress((void**)&p_xres,  g_xres);
    cudaGetSymbolAddress((void**)&p_hid,   g_hid);
    cudaGetSymbolAddress((void**)&p_wts,   g_wts);

    // round weights to tf32 once per launch (tiny)
    k_round<<<196608 / 256, 256>>>(qkv_w,  p_wts + WOFF_QKV,  196608);
    k_round<<< 65536 / 256, 256>>>(proj_w, p_wts + WOFF_PROJ,  65536);
    k_round<<<262144 / 256, 256>>>(mlp_w1, p_wts + WOFF_W1,   262144);
    k_round<<<262144 / 256, 256>>>(mlp_w2, p_wts + WOFF_W2,   262144);

    dim3 tb(32, 8);
    k_transpose_in<<<dim3(98, 8, 32), tb>>>(x);
    k_ln<true ><<<TOK, 64>>>(p_short, n1_g, n1_b, p_bufA);
    k_gemm<0, true ><<<dim3(784, 6), 256>>>(p_bufA, p_wts + WOFF_QKV, qkv_b, nullptr, p_qkv, 768, 256);
    k_attn<<<NWIN * NHEAD, 128>>>(p_qkv, p_bufA);
    k_gemm<2, false><<<dim3(784, 2), 256>>>(p_bufA, p_wts + WOFF_PROJ, proj_b, p_short, p_xres, 256, 256);
    k_ln<true ><<<TOK, 64>>>(p_xres, n2_g, n2_b, p_qkv);
    k_gemm<1, false><<<dim3(784, 8), 256>>>(p_qkv, p_wts + WOFF_W1, mlp_b1, nullptr, p_hid, 1024, 256);
    k_gemm<3, false><<<dim3(784, 2), 256>>>(p_hid, p_wts + WOFF_W2, mlp_b2, p_xres, p_bufA, 256, 1024);
    k_transpose_out<<<dim3(98, 8, 32), tb>>>(out);
}

// round 9
// speedup vs baseline: 3.5140x; 1.4332x over previous
#include <cuda_runtime.h>
#include <cuda.h>
#include <math.h>
#include <stdint.h>

#define B_     32
#define C_     256
#define H_     56
#define W_     56
#define HW_    3136
#define TOK    100352          // B_*H_*W_
#define NWIN   2048
#define NHEAD  8
#define HID    1024

// ---------------- scratch (device globals) ----------------------------------
__device__ float g_short[(size_t)TOK * C_];
__device__ float g_bufA [(size_t)TOK * C_];
__device__ float g_qkv  [(size_t)TOK * 3 * C_];
__device__ float g_xres [(size_t)TOK * C_];
__device__ float g_hid  [(size_t)TOK * HID];
__device__ float g_wts  [786432];              // tf32-rounded, TRANSPOSED weights [N][K]

#define WOFF_QKV  0
#define WOFF_PROJ 196608
#define WOFF_W1   262144
#define WOFF_W2   524288

// window-order row m -> spatial token (for proj scatter epilogue)
__device__ __forceinline__ int win_token(int m) {
    int win = m / 49;
    int n   = m - win * 49;
    int b   = win >> 6;
    int r   = win & 63;
    int i   = n / 7;
    int j   = n - i * 7;
    int h = (r >> 3) * 7 + i + 3; if (h >= H_) h -= H_;
    int w = (r & 7)  * 7 + j + 3; if (w >= W_) w -= W_;
    return (b * H_ + h) * W_ + w;
}

// ---------------- ptx helpers ------------------------------------------------
__device__ __forceinline__ float cvt_tf32(float x) {
    uint32_t u;
    asm("cvt.rna.tf32.f32 %0, %1;" : "=r"(u) : "f"(x));
    return __uint_as_float(u);
}
__device__ __forceinline__ void mma_tf32(float (&d)[4],
                                         uint32_t a0, uint32_t a1, uint32_t a2, uint32_t a3,
                                         uint32_t b0, uint32_t b1) {
    asm volatile(
        "mma.sync.aligned.m16n8k8.row.col.f32.tf32.tf32.f32 "
        "{%0,%1,%2,%3}, {%4,%5,%6,%7}, {%8,%9}, {%0,%1,%2,%3};\n"
        : "+f"(d[0]), "+f"(d[1]), "+f"(d[2]), "+f"(d[3])
        : "r"(a0), "r"(a1), "r"(a2), "r"(a3), "r"(b0), "r"(b1));
}
__device__ __forceinline__ uint32_t swz64(uint32_t b) { return b ^ ((b >> 3) & 0x30); }
__device__ __forceinline__ void ldsm4(uint32_t& r0, uint32_t& r1, uint32_t& r2, uint32_t& r3,
                                      uint32_t a) {
    asm volatile("ldmatrix.sync.aligned.m8n8.x4.shared.b16 {%0,%1,%2,%3}, [%4];"
                 : "=r"(r0), "=r"(r1), "=r"(r2), "=r"(r3) : "r"(a));
}
__device__ __forceinline__ void mbar_init(uint32_t a, uint32_t cnt) {
    asm volatile("mbarrier.init.shared.b64 [%0], %1;" :: "r"(a), "r"(cnt) : "memory");
}
__device__ __forceinline__ void mbar_expect(uint32_t a, uint32_t tx) {
    asm volatile("mbarrier.arrive.expect_tx.shared.b64 _, [%0], %1;" :: "r"(a), "r"(tx) : "memory");
}
__device__ __forceinline__ void mbar_wait(uint32_t a, uint32_t ph) {
    asm volatile(
        "{\n\t.reg .pred P1;\n\t"
        "WL%=:\n\t"
        "mbarrier.try_wait.parity.acquire.cta.shared::cta.b64 P1, [%0], %1, 0x989680;\n\t"
        "@P1 bra WD%=;\n\t"
        "bra WL%=;\n\t"
        "WD%=:\n\t}"
        :: "r"(a), "r"(ph) : "memory");
}
__device__ __forceinline__ void tma2d(uint32_t dst, const void* map, int x, int y, uint32_t mbar) {
    asm volatile(
        "cp.async.bulk.tensor.2d.shared::cta.global.tile.mbarrier::complete_tx::bytes "
        "[%0], [%1, {%2, %3}], [%4];"
        :: "r"(dst), "l"(map), "r"(x), "r"(y), "r"(mbar) : "memory");
}

// ---------------- weight round + transpose: dst[n][k] = tf32(src[k][n]) -----
__global__ void k_wt(const float* __restrict__ src, float* __restrict__ dst, int K, int N) {
    __shared__ float t[32][33];
    int k0 = blockIdx.x * 32, n0 = blockIdx.y * 32;
    int tx = threadIdx.x, ty = threadIdx.y;
    #pragma unroll
    for (int j = ty; j < 32; j += 8)
        t[j][tx] = src[(size_t)(k0 + j) * N + n0 + tx];
    __syncthreads();
    #pragma unroll
    for (int j = ty; j < 32; j += 8)
        dst[(size_t)(n0 + j) * K + k0 + tx] = cvt_tf32(t[tx][j]);
}

// ---------------- fused transpose + LN1, output in WINDOW order --------------
__global__ __launch_bounds__(256)
void k_tr_ln(const float* __restrict__ x, const float* __restrict__ gam,
             const float* __restrict__ bet) {
    __shared__ float tile[256][33];
    int b = blockIdx.y, hw0 = blockIdx.x * 32;
    int tid = threadIdx.x;
    int tx = tid & 31, ty = tid >> 5;
    for (int c = ty; c < 256; c += 8)
        tile[c][tx] = x[((size_t)(b * 256 + c)) * HW_ + hw0 + tx];
    __syncthreads();

    int lane = tx;
    #pragma unroll
    for (int q = 0; q < 4; q++) {
        int tk = ty * 4 + q;               // local token 0..31
        float s = 0.f, ss = 0.f;
        #pragma unroll
        for (int ci = 0; ci < 8; ci++) {
            float v = tile[lane + ci * 32][tk];
            s += v; ss += v * v;
        }
        #pragma unroll
        for (int o = 16; o; o >>= 1) {
            s  += __shfl_xor_sync(0xffffffffu, s, o);
            ss += __shfl_xor_sync(0xffffffffu, ss, o);
        }
        float mean = s * (1.0f / C_);
        float var  = ss * (1.0f / C_) - mean * mean;
        float rstd = rsqrtf(var + 1e-5f);

        int hw = hw0 + tk;
        int t  = b * HW_ + hw;
        int h  = hw / W_, w = hw - h * W_;
        int hs = (h >= 3) ? h - 3 : h + 53;
        int ws = (w >= 3) ? w - 3 : w + 53;
        int m  = (b * 64 + (hs / 7) * 8 + (ws / 7)) * 49 + (hs % 7) * 7 + (ws % 7);

        for (int c = lane; c < 256; c += 32) {
            float v = tile[c][tk];
            g_short[(size_t)t * C_ + c] = v;
            g_bufA[(size_t)m * C_ + c] = cvt_tf32((v - mean) * rstd * gam[c] + bet[c]);
        }
    }
}

// ---------------- output transpose (B,HW,C) -> (B,C,HW) ----------------------
__global__ void k_transpose_out(float* __restrict__ out) {
    __shared__ float tile[32][33];
    int b = blockIdx.z, hw0 = blockIdx.x * 32, c0 = blockIdx.y * 32;
    int tx = threadIdx.x, ty = threadIdx.y;
    const float* src = g_bufA + ((size_t)b * HW_ + hw0) * C_ + c0;
    #pragma unroll
    for (int j = ty; j < 32; j += 8) tile[j][tx] = src[(size_t)j * C_ + tx];
    __syncthreads();
    float* dst = out + ((size_t)b * C_ + c0) * HW_ + hw0;
    #pragma unroll
    for (int j = ty; j < 32; j += 8) dst[(size_t)j * HW_ + tx] = tile[tx][j];
}

// ---------------- LN2 (64 threads/token, tf32-rounded output) ----------------
__global__ void k_ln(const float* __restrict__ x, const float* __restrict__ g,
                     const float* __restrict__ bb, float* __restrict__ out) {
    int token = blockIdx.x;
    int tid = threadIdx.x;
    float4 v = ((const float4*)(x + (size_t)token * C_))[tid];
    float s  = v.x + v.y + v.z + v.w;
    float ss = v.x * v.x + v.y * v.y + v.z * v.z + v.w * v.w;
    #pragma unroll
    for (int o = 16; o; o >>= 1) {
        s  += __shfl_xor_sync(0xffffffffu, s, o);
        ss += __shfl_xor_sync(0xffffffffu, ss, o);
    }
    __shared__ float sh[4];
    if ((tid & 31) == 0) { sh[tid >> 5] = s; sh[2 + (tid >> 5)] = ss; }
    __syncthreads();
    s = sh[0] + sh[1]; ss = sh[2] + sh[3];
    float mean = s * (1.0f / C_);
    float var  = ss * (1.0f / C_) - mean * mean;
    float rstd = rsqrtf(var + 1e-5f);
    float4 gg = ((const float4*)g)[tid];
    float4 bv = ((const float4*)bb)[tid];
    float4 o4;
    o4.x = cvt_tf32((v.x - mean) * rstd * gg.x + bv.x);
    o4.y = cvt_tf32((v.y - mean) * rstd * gg.y + bv.y);
    o4.z = cvt_tf32((v.z - mean) * rstd * gg.z + bv.z);
    o4.w = cvt_tf32((v.w - mean) * rstd * gg.w + bv.w);
    ((float4*)(out + (size_t)token * C_))[tid] = o4;
}

// ---------------- TMA-fed tf32 GEMM 128x128, BK=16, 4-stage pipeline ---------
// A global: [Mrows][K] tf32-rounded. B global: transposed weights [N][K].
// Both tiles: [128 rows][16 floats] SW64 in smem; 2 TMA ops/stage.
// k-step offset within a row is applied with XOR (swizzle-safe), never ADD.
// EPI: 0 bias | 1 bias+GELU+round | 2 bias+scatter+extra | 3 bias+extra
#define NS 4
#define STG_BYTES 8192                     // 128*16*4 per side per stage
#define GEMM_SMEM (NS * 2 * STG_BYTES + 64)

template<int EPI>
__global__ __launch_bounds__(256, 2)
void k_gemm(const __grid_constant__ CUtensorMap dA,
            const __grid_constant__ CUtensorMap dB,
            const float* __restrict__ bias, const float* __restrict__ extra,
            float* __restrict__ Cout, int N, int K)
{
    extern __shared__ __align__(1024) char smem[];
    uint32_t aBase = (uint32_t)__cvta_generic_to_shared(smem);
    uint32_t bBase = aBase + NS * STG_BYTES;
    uint32_t mBase = bBase + NS * STG_BYTES;

    int tid = threadIdx.x;
    int lane = tid & 31, wid = tid >> 5;
    int warpM = wid >> 1, warpN = wid & 1;
    int qrow = lane >> 2, qcol = lane & 3;
    int bm = blockIdx.x * 128, bn = blockIdx.y * 128;
    int niters = K >> 4;

    if (tid == 0) {
        #pragma unroll
        for (int s = 0; s < NS; s++) mbar_init(mBase + 8 * s, 1);
    }
    __syncthreads();

    if (tid == 0) {
        #pragma unroll
        for (int j = 0; j < NS - 1; j++) {
            mbar_expect(mBase + 8 * j, 2 * STG_BYTES);
            tma2d(aBase + j * STG_BYTES, &dA, j * 16, bm, mBase + 8 * j);
            tma2d(bBase + j * STG_BYTES, &dB, j * 16, bn, mBase + 8 * j);
        }
    }

    // per-thread ldmatrix base addresses (stage 0, k-step 0); byte-col in {0,16}
    uint32_t aAddr[2], bAddr[4];
    {
        int lr = lane & 7;
        #pragma unroll
        for (int mt = 0; mt < 2; mt++) {
            int row = warpM * 32 + mt * 16 + lr + ((lane & 8) ? 8 : 0);
            int c4  = (lane & 16) ? 16 : 0;
            aAddr[mt] = aBase + swz64((uint32_t)(row * 64 + c4));
        }
        int mq = lane >> 3;
        #pragma unroll
        for (int np = 0; np < 4; np++) {
            int row = warpN * 64 + (np * 2 + (mq >> 1)) * 8 + lr;
            int c4  = (mq & 1) * 16;
            bAddr[np] = bBase + swz64((uint32_t)(row * 64 + c4));
        }
    }

    float acc[2][8][4];
    #pragma unroll
    for (int mt = 0; mt < 2; mt++)
        #pragma unroll
        for (int nt = 0; nt < 8; nt++)
            #pragma unroll
            for (int e = 0; e < 4; e++) acc[mt][nt][e] = 0.f;

    for (int i = 0; i < niters; i++) {
        int s = i & (NS - 1);
        mbar_wait(mBase + 8 * s, (i >> 2) & 1);
        uint32_t so = (uint32_t)s * STG_BYTES;

        #pragma unroll
        for (int ks = 0; ks < 2; ks++) {
            uint32_t kx = (uint32_t)(ks * 32);   // applied via XOR: swizzle-safe
            uint32_t af[2][4], bf[8][2];
            #pragma unroll
            for (int mt = 0; mt < 2; mt++)
                ldsm4(af[mt][0], af[mt][1], af[mt][2], af[mt][3],
                      (aAddr[mt] + so) ^ kx);
            #pragma unroll
            for (int np = 0; np < 4; np++)
                ldsm4(bf[2 * np][0], bf[2 * np][1], bf[2 * np + 1][0], bf[2 * np + 1][1],
                      (bAddr[np] + so) ^ kx);
            #pragma unroll
            for (int mt = 0; mt < 2; mt++)
                #pragma unroll
                for (int nt = 0; nt < 8; nt++)
                    mma_tf32(acc[mt][nt], af[mt][0], af[mt][1], af[mt][2], af[mt][3],
                             bf[nt][0], bf[nt][1]);
        }
        __syncthreads();

        int j = i + NS - 1;
        if (j < niters && tid == 0) {
            int s2 = j & (NS - 1);
            mbar_expect(mBase + 8 * s2, 2 * STG_BYTES);
            tma2d(aBase + s2 * STG_BYTES, &dA, j * 16, bm, mBase + 8 * s2);
            tma2d(bBase + s2 * STG_BYTES, &dB, j * 16, bn, mBase + 8 * s2);
        }
    }

    // -------- epilogue --------
    #pragma unroll
    for (int mt = 0; mt < 2; mt++) {
        #pragma unroll
        for (int half = 0; half < 2; half++) {
            int gr = bm + warpM * 32 + mt * 16 + qrow + half * 8;
            size_t orow = (EPI == 2) ? (size_t)win_token(gr) : (size_t)gr;
            #pragma unroll
            for (int nt = 0; nt < 8; nt++) {
                int col = bn + warpN * 64 + nt * 8 + 2 * qcol;
                float v0 = acc[mt][nt][2 * half + 0] + bias[col];
                float v1 = acc[mt][nt][2 * half + 1] + bias[col + 1];
                if (EPI == 1) {
                    v0 = 0.5f * v0 * (1.0f + erff(v0 * 0.7071067811865475f));
                    v1 = 0.5f * v1 * (1.0f + erff(v1 * 0.7071067811865475f));
                    v0 = cvt_tf32(v0);
                    v1 = cvt_tf32(v1);
                }
                if (EPI == 2 || EPI == 3) {
                    const float* ep = extra + orow * N + col;
                    v0 += ep[0];
                    v1 += ep[1];
                }
                *(float2*)(Cout + orow * N + col) = make_float2(v0, v1);
            }
        }
    }
}

// ---------------- windowed attention (register-resident K / V) ---------------
__global__ void __launch_bounds__(128)
k_attn(const float* __restrict__ qkv, float* __restrict__ out) {
    __shared__ float qs[49][36];
    __shared__ float ks[49][33];
    __shared__ float vs[49][33];
    __shared__ float S[49][50];
    int win  = blockIdx.x >> 3;
    int head = blockIdx.x & 7;
    int tid  = threadIdx.x;
    int lane = tid & 31;
    int wj   = tid >> 5;
    int base = win * 49;

    for (int idx = tid; idx < 49 * 32; idx += 128) {
        int n = idx >> 5, d = idx & 31;
        const float* p = qkv + (size_t)(base + n) * 768 + head * 32 + d;
        qs[n][d] = p[0];
        ks[n][d] = p[256];
        vs[n][d] = p[512];
    }
    __syncthreads();

    const float scale = 0.1767766952966369f;

    #pragma unroll
    for (int pass = 0; pass < 2; pass++) {
        int m = pass * 32 + lane;
        bool act = (m < 49);
        int mm = act ? m : 48;
        float kreg[32];
        #pragma unroll
        for (int d = 0; d < 32; d++) kreg[d] = ks[mm][d];
        for (int n = wj; n < 49; n += 4) {
            float acc = 0.f;
            #pragma unroll
            for (int dq = 0; dq < 8; dq++) {
                float4 q4 = *(const float4*)&qs[n][dq * 4];
                acc += q4.x * kreg[dq * 4 + 0];
                acc += q4.y * kreg[dq * 4 + 1];
                acc += q4.z * kreg[dq * 4 + 2];
                acc += q4.w * kreg[dq * 4 + 3];
            }
            if (act) S[n][m] = acc * scale;
        }
    }
    __syncthreads();

    if (tid < 49) {
        float mx = -1e30f;
        #pragma unroll 7
        for (int m = 0; m < 49; m++) mx = fmaxf(mx, S[tid][m]);
        float sum = 0.f;
        #pragma unroll 7
        for (int m = 0; m < 49; m++) { float e = __expf(S[tid][m] - mx); S[tid][m] = e; sum += e; }
        float inv = 1.0f / sum;
        #pragma unroll 7
        for (int m = 0; m < 49; m++) S[tid][m] *= inv;
    }
    __syncthreads();

    float vreg[49];
    #pragma unroll
    for (int m = 0; m < 49; m++) vreg[m] = vs[m][lane];
    for (int n = wj; n < 49; n += 4) {
        float acc = 0.f;
        #pragma unroll
        for (int m = 0; m < 49; m++) acc += S[n][m] * vreg[m];
        out[(size_t)(base + n) * C_ + head * 32 + lane] = cvt_tf32(acc);
    }
}

// ---------------- host: tensor-map encode ------------------------------------
typedef CUresult (*tmap_fn)(CUtensorMap*, CUtensorMapDataType, cuuint32_t, void*,
                            const cuuint64_t*, const cuuint64_t*, const cuuint32_t*,
                            const cuuint32_t*, CUtensorMapInterleave, CUtensorMapSwizzle,
                            CUtensorMapL2promotion, CUtensorMapFloatOOBfill);

static tmap_fn get_enc() {
    void* fn = nullptr;
    cudaDriverEntryPointQueryResult qr;
#if CUDART_VERSION >= 12050
    cudaGetDriverEntryPointByVersion("cuTensorMapEncodeTiled", &fn, 12000,
                                     cudaEnableDefault, &qr);
#else
    cudaGetDriverEntryPoint("cuTensorMapEncodeTiled", &fn, cudaEnableDefault, &qr);
#endif
    return (tmap_fn)fn;
}

static void enc2d(tmap_fn f, CUtensorMap* m, void* ptr, uint64_t innerK, uint64_t outerRows) {
    cuuint64_t dims[2]    = {innerK, outerRows};
    cuuint64_t strides[1] = {innerK * 4};
    cuuint32_t box[2]     = {16, 128};
    cuuint32_t el[2]      = {1, 1};
    f(m, CU_TENSOR_MAP_DATA_TYPE_FLOAT32, 2, ptr, dims, strides, box, el,
      CU_TENSOR_MAP_INTERLEAVE_NONE, CU_TENSOR_MAP_SWIZZLE_64B,
      CU_TENSOR_MAP_L2_PROMOTION_L2_128B, CU_TENSOR_MAP_FLOAT_OOB_FILL_NONE);
}

// ---------------- launch ----------------------------------------------------
extern "C" void kernel_launch(void* const* d_in, const int* in_sizes, int n_in,
                              void* d_out, int out_size) {
    const float* x      = (const float*)d_in[0];
    const float* n1_g   = (const float*)d_in[1];
    const float* n1_b   = (const float*)d_in[2];
    const float* qkv_w  = (const float*)d_in[3];
    const float* qkv_b  = (const float*)d_in[4];
    const float* proj_w = (const float*)d_in[5];
    const float* proj_b = (const float*)d_in[6];
    const float* n2_g   = (const float*)d_in[7];
    const float* n2_b   = (const float*)d_in[8];
    const float* mlp_w1 = (const float*)d_in[9];
    const float* mlp_b1 = (const float*)d_in[10];
    const float* mlp_w2 = (const float*)d_in[11];
    const float* mlp_b2 = (const float*)d_in[12];
    float* out = (float*)d_out;

    float *p_short, *p_bufA, *p_qkv, *p_xres, *p_hid, *p_wts;
    cudaGetSymbolAddress((void**)&p_short, g_short);
    cudaGetSymbolAddress((void**)&p_bufA,  g_bufA);
    cudaGetSymbolAddress((void**)&p_qkv,   g_qkv);
    cudaGetSymbolAddress((void**)&p_xres,  g_xres);
    cudaGetSymbolAddress((void**)&p_hid,   g_hid);
    cudaGetSymbolAddress((void**)&p_wts,   g_wts);

    tmap_fn enc = get_enc();
    CUtensorMap dA_bufA, dA_ln2, dA_hid, dB_qkv, dB_proj, dB_w1, dB_w2;
    enc2d(enc, &dA_bufA, p_bufA,            256,  TOK);
    enc2d(enc, &dA_ln2,  p_qkv,             256,  TOK);
    enc2d(enc, &dA_hid,  p_hid,             1024, TOK);
    enc2d(enc, &dB_qkv,  p_wts + WOFF_QKV,  256,  768);
    enc2d(enc, &dB_proj, p_wts + WOFF_PROJ, 256,  256);
    enc2d(enc, &dB_w1,   p_wts + WOFF_W1,   256,  1024);
    enc2d(enc, &dB_w2,   p_wts + WOFF_W2,   1024, 256);

    cudaFuncSetAttribute(k_gemm<0>, cudaFuncAttributeMaxDynamicSharedMemorySize, GEMM_SMEM);
    cudaFuncSetAttribute(k_gemm<1>, cudaFuncAttributeMaxDynamicSharedMemorySize, GEMM_SMEM);
    cudaFuncSetAttribute(k_gemm<2>, cudaFuncAttributeMaxDynamicSharedMemorySize, GEMM_SMEM);
    cudaFuncSetAttribute(k_gemm<3>, cudaFuncAttributeMaxDynamicSharedMemorySize, GEMM_SMEM);

    dim3 tb(32, 8);
    // weight round + transpose into [N][K]
    k_wt<<<dim3(8, 24),  tb>>>(qkv_w,  p_wts + WOFF_QKV,  256, 768);
    k_wt<<<dim3(8, 8),   tb>>>(proj_w, p_wts + WOFF_PROJ, 256, 256);
    k_wt<<<dim3(8, 32),  tb>>>(mlp_w1, p_wts + WOFF_W1,   256, 1024);
    k_wt<<<dim3(32, 8),  tb>>>(mlp_w2, p_wts + WOFF_W2,   1024, 256);

    // fused transpose + LN1 (shortcut spatial; LN1 out in window order, tf32)
    k_tr_ln<<<dim3(98, 32), 256>>>(x, n1_g, n1_b);
    // qkv = winLN1 @ qkv_w^T
    k_gemm<0><<<dim3(784, 6), 256, GEMM_SMEM>>>(dA_bufA, dB_qkv, qkv_b, nullptr, p_qkv, 768, 256);
    // windowed MHSA
    k_attn<<<NWIN * NHEAD, 128>>>(p_qkv, p_bufA);
    // xres = shortcut + scatter(attn_o @ proj_w^T + b)
    k_gemm<2><<<dim3(784, 2), 256, GEMM_SMEM>>>(dA_bufA, dB_proj, proj_b, p_short, p_xres, 256, 256);
    // LN2 -> dense rows in g_qkv scratch
    k_ln<<<TOK, 64>>>(p_xres, n2_g, n2_b, p_qkv);
    // hid = gelu(ln2 @ w1^T + b1)
    k_gemm<1><<<dim3(784, 8), 256, GEMM_SMEM>>>(dA_ln2, dB_w1, mlp_b1, nullptr, p_hid, 1024, 256);
    // y = xres + hid @ w2^T + b2
    k_gemm<3><<<dim3(784, 2), 256, GEMM_SMEM>>>(dA_hid, dB_w2, mlp_b2, p_xres, p_bufA, 256, 1024);
    // (B,HW,C) -> (B,C,HW)
    k_transpose_out<<<dim3(98, 8, 32), tb>>>(out);
}

// round 11
// speedup vs baseline: 4.6422x; 1.3211x over previous
#include <cuda_runtime.h>
#include <cuda.h>
#include <cuda_fp16.h>
#include <math.h>
#include <stdint.h>

#define B_     32
#define C_     256
#define H_     56
#define W_     56
#define HW_    3136
#define TOK    100352          // B_*H_*W_
#define NWIN   2048
#define NHEAD  8
#define HID    1024

// ---------------- scratch (device globals; fp16 views overlay float arrays) --
__device__ float g_short[(size_t)TOK * C_];        // f32: shortcut, then mlp2 out
__device__ float g_bufA [(size_t)TOK * C_];        // half: LN1(win order) -> attn out
__device__ float g_qkv  [(size_t)TOK * 3 * C_];    // half: qkv -> ln2 out
__device__ float g_xres [(size_t)TOK * C_];        // f32: x after attn residual
__device__ float g_hid  [(size_t)TOK * HID];       // half: mlp hidden
__device__ float g_wts  [786432];                  // half: transposed weights [N][K]

#define WOFF_QKV  0
#define WOFF_PROJ 196608
#define WOFF_W1   262144
#define WOFF_W2   524288

// window-order row m -> spatial token (for proj scatter epilogue)
__device__ __forceinline__ int win_token(int m) {
    int win = m / 49;
    int n   = m - win * 49;
    int b   = win >> 6;
    int r   = win & 63;
    int i   = n / 7;
    int j   = n - i * 7;
    int h = (r >> 3) * 7 + i + 3; if (h >= H_) h -= H_;
    int w = (r & 7)  * 7 + j + 3; if (w >= W_) w -= W_;
    return (b * H_ + h) * W_ + w;
}

// ---------------- ptx helpers ------------------------------------------------
__device__ __forceinline__ void mma_f16(float (&d)[4],
                                        uint32_t a0, uint32_t a1, uint32_t a2, uint32_t a3,
                                        uint32_t b0, uint32_t b1) {
    asm volatile(
        "mma.sync.aligned.m16n8k16.row.col.f32.f16.f16.f32 "
        "{%0,%1,%2,%3}, {%4,%5,%6,%7}, {%8,%9}, {%0,%1,%2,%3};\n"
        : "+f"(d[0]), "+f"(d[1]), "+f"(d[2]), "+f"(d[3])
        : "r"(a0), "r"(a1), "r"(a2), "r"(a3), "r"(b0), "r"(b1));
}
__device__ __forceinline__ uint32_t swz64(uint32_t b) { return b ^ ((b >> 3) & 0x30); }
__device__ __forceinline__ void ldsm4(uint32_t& r0, uint32_t& r1, uint32_t& r2, uint32_t& r3,
                                      uint32_t a) {
    asm volatile("ldmatrix.sync.aligned.m8n8.x4.shared.b16 {%0,%1,%2,%3}, [%4];"
                 : "=r"(r0), "=r"(r1), "=r"(r2), "=r"(r3) : "r"(a));
}
__device__ __forceinline__ void mbar_init(uint32_t a, uint32_t cnt) {
    asm volatile("mbarrier.init.shared.b64 [%0], %1;" :: "r"(a), "r"(cnt) : "memory");
}
__device__ __forceinline__ void mbar_expect(uint32_t a, uint32_t tx) {
    asm volatile("mbarrier.arrive.expect_tx.shared.b64 _, [%0], %1;" :: "r"(a), "r"(tx) : "memory");
}
__device__ __forceinline__ void mbar_wait(uint32_t a, uint32_t ph) {
    asm volatile(
        "{\n\t.reg .pred P1;\n\t"
        "WL%=:\n\t"
        "mbarrier.try_wait.parity.acquire.cta.shared::cta.b64 P1, [%0], %1, 0x989680;\n\t"
        "@P1 bra WD%=;\n\t"
        "bra WL%=;\n\t"
        "WD%=:\n\t}"
        :: "r"(a), "r"(ph) : "memory");
}
__device__ __forceinline__ void tma2d(uint32_t dst, const void* map, int x, int y, uint32_t mbar) {
    asm volatile(
        "cp.async.bulk.tensor.2d.shared::cta.global.tile.mbarrier::complete_tx::bytes "
        "[%0], [%1, {%2, %3}], [%4];"
        :: "r"(dst), "l"(map), "r"(x), "r"(y), "r"(mbar) : "memory");
}

// ---------------- weight round + transpose: dst[n][k] = fp16(src[k][n]) -----
__global__ void k_wt(const float* __restrict__ src, __half* __restrict__ dst, int K, int N) {
    __shared__ float t[32][33];
    int k0 = blockIdx.x * 32, n0 = blockIdx.y * 32;
    int tx = threadIdx.x, ty = threadIdx.y;
    #pragma unroll
    for (int j = ty; j < 32; j += 8)
        t[j][tx] = src[(size_t)(k0 + j) * N + n0 + tx];
    __syncthreads();
    #pragma unroll
    for (int j = ty; j < 32; j += 8)
        dst[(size_t)(n0 + j) * K + k0 + tx] = __float2half(t[tx][j]);
}

// ---------------- fused transpose + LN1, output fp16 in WINDOW order ---------
__global__ __launch_bounds__(256)
void k_tr_ln(const float* __restrict__ x, const float* __restrict__ gam,
             const float* __restrict__ bet) {
    __shared__ float tile[256][33];
    int b = blockIdx.y, hw0 = blockIdx.x * 32;
    int tid = threadIdx.x;
    int tx = tid & 31, ty = tid >> 5;
    for (int c = ty; c < 256; c += 8)
        tile[c][tx] = x[((size_t)(b * 256 + c)) * HW_ + hw0 + tx];
    __syncthreads();

    __half* winout = (__half*)g_bufA;
    int lane = tx;
    #pragma unroll
    for (int q = 0; q < 4; q++) {
        int tk = ty * 4 + q;
        float s = 0.f, ss = 0.f;
        #pragma unroll
        for (int ci = 0; ci < 8; ci++) {
            float v = tile[lane + ci * 32][tk];
            s += v; ss += v * v;
        }
        #pragma unroll
        for (int o = 16; o; o >>= 1) {
            s  += __shfl_xor_sync(0xffffffffu, s, o);
            ss += __shfl_xor_sync(0xffffffffu, ss, o);
        }
        float mean = s * (1.0f / C_);
        float var  = ss * (1.0f / C_) - mean * mean;
        float rstd = rsqrtf(var + 1e-5f);

        int hw = hw0 + tk;
        int t  = b * HW_ + hw;
        int h  = hw / W_, w = hw - h * W_;
        int hs = (h >= 3) ? h - 3 : h + 53;
        int ws = (w >= 3) ? w - 3 : w + 53;
        int m  = (b * 64 + (hs / 7) * 8 + (ws / 7)) * 49 + (hs % 7) * 7 + (ws % 7);

        for (int c = lane; c < 256; c += 32) {
            float v = tile[c][tk];
            g_short[(size_t)t * C_ + c] = v;
            winout[(size_t)m * C_ + c] = __float2half((v - mean) * rstd * gam[c] + bet[c]);
        }
    }
}

// ---------------- output transpose (B,HW,C) -> (B,C,HW), src g_short ---------
__global__ void k_transpose_out(float* __restrict__ out) {
    __shared__ float tile[32][33];
    int b = blockIdx.z, hw0 = blockIdx.x * 32, c0 = blockIdx.y * 32;
    int tx = threadIdx.x, ty = threadIdx.y;
    const float* src = g_short + ((size_t)b * HW_ + hw0) * C_ + c0;
    #pragma unroll
    for (int j = ty; j < 32; j += 8) tile[j][tx] = src[(size_t)j * C_ + tx];
    __syncthreads();
    float* dst = out + ((size_t)b * C_ + c0) * HW_ + hw0;
    #pragma unroll
    for (int j = ty; j < 32; j += 8) dst[(size_t)j * HW_ + tx] = tile[tx][j];
}

// ---------------- LN2 (f32 in, fp16 out) -------------------------------------
__global__ void k_ln(const float* __restrict__ x, const float* __restrict__ g,
                     const float* __restrict__ bb, __half* __restrict__ out) {
    int token = blockIdx.x;
    int tid = threadIdx.x;
    float4 v = ((const float4*)(x + (size_t)token * C_))[tid];
    float s  = v.x + v.y + v.z + v.w;
    float ss = v.x * v.x + v.y * v.y + v.z * v.z + v.w * v.w;
    #pragma unroll
    for (int o = 16; o; o >>= 1) {
        s  += __shfl_xor_sync(0xffffffffu, s, o);
        ss += __shfl_xor_sync(0xffffffffu, ss, o);
    }
    __shared__ float sh[4];
    if ((tid & 31) == 0) { sh[tid >> 5] = s; sh[2 + (tid >> 5)] = ss; }
    __syncthreads();
    s = sh[0] + sh[1]; ss = sh[2] + sh[3];
    float mean = s * (1.0f / C_);
    float var  = ss * (1.0f / C_) - mean * mean;
    float rstd = rsqrtf(var + 1e-5f);
    float4 gg = ((const float4*)g)[tid];
    float4 bv = ((const float4*)bb)[tid];
    __half2 h0 = __floats2half2_rn((v.x - mean) * rstd * gg.x + bv.x,
                                   (v.y - mean) * rstd * gg.y + bv.y);
    __half2 h1 = __floats2half2_rn((v.z - mean) * rstd * gg.z + bv.z,
                                   (v.w - mean) * rstd * gg.w + bv.w);
    __half2* op = (__half2*)(out + (size_t)token * C_);
    op[2 * tid]     = h0;
    op[2 * tid + 1] = h1;
}

// ---------------- TMA-fed fp16 GEMM 128x128, BK=32, 4-stage pipeline ---------
// A global: [Mrows][K] fp16. B global: transposed weights [N][K] fp16.
// Tiles: [128 rows][32 halfs] (64B rows) SW64 in smem; 2 TMA ops/stage.
// k-step offset within a row is XOR 32 bytes (swizzle-safe).
// EPI: 0 bias->half | 1 bias+GELU->half | 2 bias+scatter+extra->f32 | 3 bias+extra->f32
#define NS 4
#define STG_BYTES 8192                     // 128*64B per side per stage
#define GEMM_SMEM (NS * 2 * STG_BYTES + 64)

template<int EPI>
__global__ __launch_bounds__(256, 2)
void k_gemm(const __grid_constant__ CUtensorMap dA,
            const __grid_constant__ CUtensorMap dB,
            const float* __restrict__ bias, const float* __restrict__ extra,
            void* __restrict__ Cout, int N, int K)
{
    extern __shared__ __align__(1024) char smem[];
    uint32_t aBase = (uint32_t)__cvta_generic_to_shared(smem);
    uint32_t bBase = aBase + NS * STG_BYTES;
    uint32_t mBase = bBase + NS * STG_BYTES;

    int tid = threadIdx.x;
    int lane = tid & 31, wid = tid >> 5;
    int warpM = wid >> 1, warpN = wid & 1;
    int qrow = lane >> 2, qcol = lane & 3;
    int bm = blockIdx.x * 128, bn = blockIdx.y * 128;
    int niters = K >> 5;

    if (tid == 0) {
        #pragma unroll
        for (int s = 0; s < NS; s++) mbar_init(mBase + 8 * s, 1);
    }
    __syncthreads();

    if (tid == 0) {
        #pragma unroll
        for (int j = 0; j < NS - 1; j++) {
            mbar_expect(mBase + 8 * j, 2 * STG_BYTES);
            tma2d(aBase + j * STG_BYTES, &dA, j * 32, bm, mBase + 8 * j);
            tma2d(bBase + j * STG_BYTES, &dB, j * 32, bn, mBase + 8 * j);
        }
    }

    // per-thread ldmatrix base addresses (stage 0, k-step 0); byte-col in {0,16}
    uint32_t aAddr[2], bAddr[4];
    {
        int lr = lane & 7;
        #pragma unroll
        for (int mt = 0; mt < 2; mt++) {
            int row = warpM * 32 + mt * 16 + lr + ((lane & 8) ? 8 : 0);
            int c4  = (lane & 16) ? 16 : 0;
            aAddr[mt] = aBase + swz64((uint32_t)(row * 64 + c4));
        }
        int mq = lane >> 3;
        #pragma unroll
        for (int np = 0; np < 4; np++) {
            int row = warpN * 64 + (np * 2 + (mq >> 1)) * 8 + lr;
            int c4  = (mq & 1) * 16;
            bAddr[np] = bBase + swz64((uint32_t)(row * 64 + c4));
        }
    }

    float acc[2][8][4];
    #pragma unroll
    for (int mt = 0; mt < 2; mt++)
        #pragma unroll
        for (int nt = 0; nt < 8; nt++)
            #pragma unroll
            for (int e = 0; e < 4; e++) acc[mt][nt][e] = 0.f;

    for (int i = 0; i < niters; i++) {
        int s = i & (NS - 1);
        mbar_wait(mBase + 8 * s, (i >> 2) & 1);
        uint32_t so = (uint32_t)s * STG_BYTES;

        #pragma unroll
        for (int ks = 0; ks < 2; ks++) {        // 2 x k16 per stage (K=32)
            uint32_t kx = (uint32_t)(ks * 32);  // 16 halfs = 32B, applied via XOR
            uint32_t af[2][4], bf[8][2];
            #pragma unroll
            for (int mt = 0; mt < 2; mt++)
                ldsm4(af[mt][0], af[mt][1], af[mt][2], af[mt][3],
                      (aAddr[mt] + so) ^ kx);
            #pragma unroll
            for (int np = 0; np < 4; np++)
                ldsm4(bf[2 * np][0], bf[2 * np][1], bf[2 * np + 1][0], bf[2 * np + 1][1],
                      (bAddr[np] + so) ^ kx);
            #pragma unroll
            for (int mt = 0; mt < 2; mt++)
                #pragma unroll
                for (int nt = 0; nt < 8; nt++)
                    mma_f16(acc[mt][nt], af[mt][0], af[mt][1], af[mt][2], af[mt][3],
                            bf[nt][0], bf[nt][1]);
        }
        __syncthreads();

        int j = i + NS - 1;
        if (j < niters && tid == 0) {
            int s2 = j & (NS - 1);
            mbar_expect(mBase + 8 * s2, 2 * STG_BYTES);
            tma2d(aBase + s2 * STG_BYTES, &dA, j * 32, bm, mBase + 8 * s2);
            tma2d(bBase + s2 * STG_BYTES, &dB, j * 32, bn, mBase + 8 * s2);
        }
    }

    // -------- epilogue --------
    #pragma unroll
    for (int mt = 0; mt < 2; mt++) {
        #pragma unroll
        for (int half = 0; half < 2; half++) {
            int gr = bm + warpM * 32 + mt * 16 + qrow + half * 8;
            size_t orow = (EPI == 2) ? (size_t)win_token(gr) : (size_t)gr;
            #pragma unroll
            for (int nt = 0; nt < 8; nt++) {
                int col = bn + warpN * 64 + nt * 8 + 2 * qcol;
                float v0 = acc[mt][nt][2 * half + 0] + bias[col];
                float v1 = acc[mt][nt][2 * half + 1] + bias[col + 1];
                if (EPI == 1) {
                    v0 = 0.5f * v0 * (1.0f + erff(v0 * 0.7071067811865475f));
                    v1 = 0.5f * v1 * (1.0f + erff(v1 * 0.7071067811865475f));
                }
                if (EPI == 0 || EPI == 1) {
                    *(__half2*)((__half*)Cout + orow * N + col) = __floats2half2_rn(v0, v1);
                } else {
                    const float* ep = extra + orow * N + col;
                    v0 += ep[0];
                    v1 += ep[1];
                    *(float2*)((float*)Cout + orow * N + col) = make_float2(v0, v1);
                }
            }
        }
    }
}

// ---------------- windowed attention (fp16 IO, f32 math) ---------------------
__global__ void __launch_bounds__(128)
k_attn(const __half* __restrict__ qkv, __half* __restrict__ out) {
    __shared__ float qs[49][36];
    __shared__ float ks[49][33];
    __shared__ float vs[49][33];
    __shared__ float S[49][50];
    int win  = blockIdx.x >> 3;
    int head = blockIdx.x & 7;
    int tid  = threadIdx.x;
    int lane = tid & 31;
    int wj   = tid >> 5;
    int base = win * 49;

    for (int idx = tid; idx < 49 * 32; idx += 128) {
        int n = idx >> 5, d = idx & 31;
        const __half* p = qkv + (size_t)(base + n) * 768 + head * 32 + d;
        qs[n][d] = __half2float(p[0]);
        ks[n][d] = __half2float(p[256]);
        vs[n][d] = __half2float(p[512]);
    }
    __syncthreads();

    const float scale = 0.1767766952966369f;

    #pragma unroll
    for (int pass = 0; pass < 2; pass++) {
        int m = pass * 32 + lane;
        bool act = (m < 49);
        int mm = act ? m : 48;
        float kreg[32];
        #pragma unroll
        for (int d = 0; d < 32; d++) kreg[d] = ks[mm][d];
        for (int n = wj; n < 49; n += 4) {
            float acc = 0.f;
            #pragma unroll
            for (int dq = 0; dq < 8; dq++) {
                float4 q4 = *(const float4*)&qs[n][dq * 4];
                acc += q4.x * kreg[dq * 4 + 0];
                acc += q4.y * kreg[dq * 4 + 1];
                acc += q4.z * kreg[dq * 4 + 2];
                acc += q4.w * kreg[dq * 4 + 3];
            }
            if (act) S[n][m] = acc * scale;
        }
    }
    __syncthreads();

    if (tid < 49) {
        float mx = -1e30f;
        #pragma unroll 7
        for (int m = 0; m < 49; m++) mx = fmaxf(mx, S[tid][m]);
        float sum = 0.f;
        #pragma unroll 7
        for (int m = 0; m < 49; m++) { float e = __expf(S[tid][m] - mx); S[tid][m] = e; sum += e; }
        float inv = 1.0f / sum;
        #pragma unroll 7
        for (int m = 0; m < 49; m++) S[tid][m] *= inv;
    }
    __syncthreads();

    float vreg[49];
    #pragma unroll
    for (int m = 0; m < 49; m++) vreg[m] = vs[m][lane];
    for (int n = wj; n < 49; n += 4) {
        float acc = 0.f;
        #pragma unroll
        for (int m = 0; m < 49; m++) acc += S[n][m] * vreg[m];
        out[(size_t)(base + n) * C_ + head * 32 + lane] = __float2half(acc);
    }
}

// ---------------- host: tensor-map encode ------------------------------------
typedef CUresult (*tmap_fn)(CUtensorMap*, CUtensorMapDataType, cuuint32_t, void*,
                            const cuuint64_t*, const cuuint64_t*, const cuuint32_t*,
                            const cuuint32_t*, CUtensorMapInterleave, CUtensorMapSwizzle,
                            CUtensorMapL2promotion, CUtensorMapFloatOOBfill);

static tmap_fn get_enc() {
    void* fn = nullptr;
    cudaDriverEntryPointQueryResult qr;
#if CUDART_VERSION >= 12050
    cudaGetDriverEntryPointByVersion("cuTensorMapEncodeTiled", &fn, 12000,
                                     cudaEnableDefault, &qr);
#else
    cudaGetDriverEntryPoint("cuTensorMapEncodeTiled", &fn, cudaEnableDefault, &qr);
#endif
    return (tmap_fn)fn;
}

static void enc2d(tmap_fn f, CUtensorMap* m, void* ptr, uint64_t innerK, uint64_t outerRows) {
    cuuint64_t dims[2]    = {innerK, outerRows};
    cuuint64_t strides[1] = {innerK * 2};
    cuuint32_t box[2]     = {32, 128};
    cuuint32_t el[2]      = {1, 1};
    f(m, CU_TENSOR_MAP_DATA_TYPE_FLOAT16, 2, ptr, dims, strides, box, el,
      CU_TENSOR_MAP_INTERLEAVE_NONE, CU_TENSOR_MAP_SWIZZLE_64B,
      CU_TENSOR_MAP_L2_PROMOTION_L2_128B, CU_TENSOR_MAP_FLOAT_OOB_FILL_NONE);
}

// ---------------- launch ----------------------------------------------------
extern "C" void kernel_launch(void* const* d_in, const int* in_sizes, int n_in,
                              void* d_out, int out_size) {
    const float* x      = (const float*)d_in[0];
    const float* n1_g   = (const float*)d_in[1];
    const float* n1_b   = (const float*)d_in[2];
    const float* qkv_w  = (const float*)d_in[3];
    const float* qkv_b  = (const float*)d_in[4];
    const float* proj_w = (const float*)d_in[5];
    const float* proj_b = (const float*)d_in[6];
    const float* n2_g   = (const float*)d_in[7];
    const float* n2_b   = (const float*)d_in[8];
    const float* mlp_w1 = (const float*)d_in[9];
    const float* mlp_b1 = (const float*)d_in[10];
    const float* mlp_w2 = (const float*)d_in[11];
    const float* mlp_b2 = (const float*)d_in[12];
    float* out = (float*)d_out;

    float *p_short, *p_bufA, *p_qkv, *p_xres, *p_hid, *p_wts_f;
    cudaGetSymbolAddress((void**)&p_short, g_short);
    cudaGetSymbolAddress((void**)&p_bufA,  g_bufA);
    cudaGetSymbolAddress((void**)&p_qkv,   g_qkv);
    cudaGetSymbolAddress((void**)&p_xres,  g_xres);
    cudaGetSymbolAddress((void**)&p_hid,   g_hid);
    cudaGetSymbolAddress((void**)&p_wts_f, g_wts);
    __half* p_wts = (__half*)p_wts_f;

    tmap_fn enc = get_enc();
    CUtensorMap dA_bufA, dA_ln2, dA_hid, dB_qkv, dB_proj, dB_w1, dB_w2;
    enc2d(enc, &dA_bufA, p_bufA,            256,  TOK);   // LN1win / attn-out (half)
    enc2d(enc, &dA_ln2,  p_qkv,             256,  TOK);   // LN2 out (half)
    enc2d(enc, &dA_hid,  p_hid,             1024, TOK);   // hidden (half)
    enc2d(enc, &dB_qkv,  p_wts + WOFF_QKV,  256,  768);
    enc2d(enc, &dB_proj, p_wts + WOFF_PROJ, 256,  256);
    enc2d(enc, &dB_w1,   p_wts + WOFF_W1,   256,  1024);
    enc2d(enc, &dB_w2,   p_wts + WOFF_W2,   1024, 256);

    cudaFuncSetAttribute(k_gemm<0>, cudaFuncAttributeMaxDynamicSharedMemorySize, GEMM_SMEM);
    cudaFuncSetAttribute(k_gemm<1>, cudaFuncAttributeMaxDynamicSharedMemorySize, GEMM_SMEM);
    cudaFuncSetAttribute(k_gemm<2>, cudaFuncAttributeMaxDynamicSharedMemorySize, GEMM_SMEM);
    cudaFuncSetAttribute(k_gemm<3>, cudaFuncAttributeMaxDynamicSharedMemorySize, GEMM_SMEM);

    dim3 tb(32, 8);
    // weight round + transpose into fp16 [N][K]
    k_wt<<<dim3(8, 24),  tb>>>(qkv_w,  p_wts + WOFF_QKV,  256, 768);
    k_wt<<<dim3(8, 8),   tb>>>(proj_w, p_wts + WOFF_PROJ, 256, 256);
    k_wt<<<dim3(8, 32),  tb>>>(mlp_w1, p_wts + WOFF_W1,   256, 1024);
    k_wt<<<dim3(32, 8),  tb>>>(mlp_w2, p_wts + WOFF_W2,   1024, 256);

    // fused transpose + LN1 (shortcut f32 spatial; LN1 fp16 window order)
    k_tr_ln<<<dim3(98, 32), 256>>>(x, n1_g, n1_b);
    // qkv = winLN1 @ qkv_w^T + b  (fp16 out)
    k_gemm<0><<<dim3(784, 6), 256, GEMM_SMEM>>>(dA_bufA, dB_qkv, qkv_b, nullptr, p_qkv, 768, 256);
    // windowed MHSA (fp16 io)
    k_attn<<<NWIN * NHEAD, 128>>>((const __half*)p_qkv, (__half*)p_bufA);
    // xres = shortcut + scatter(attn_o @ proj_w^T + b)   (f32 out)
    k_gemm<2><<<dim3(784, 2), 256, GEMM_SMEM>>>(dA_bufA, dB_proj, proj_b, p_short, p_xres, 256, 256);
    // LN2 (fp16 out into g_qkv scratch)
    k_ln<<<TOK, 64>>>(p_xres, n2_g, n2_b, (__half*)p_qkv);
    // hid = gelu(ln2 @ w1^T + b1)  (fp16 out)
    k_gemm<1><<<dim3(784, 8), 256, GEMM_SMEM>>>(dA_ln2, dB_w1, mlp_b1, nullptr, p_hid, 1024, 256);
    // final = xres + hid @ w2^T + b2  (f32 out into g_short)
    k_gemm<3><<<dim3(784, 2), 256, GEMM_SMEM>>>(dA_hid, dB_w2, mlp_b2, p_xres, p_short, 256, 1024);
    // (B,HW,C) -> (B,C,HW)
    k_transpose_out<<<dim3(98, 8, 32), tb>>>(out);
}

// round 12
// speedup vs baseline: 4.6787x; 1.0079x over previous
#include <cuda_runtime.h>
#include <cuda.h>
#include <cuda_fp16.h>
#include <math.h>
#include <stdint.h>

#define B_     32
#define C_     256
#define H_     56
#define W_     56
#define HW_    3136
#define TOK    100352          // B_*H_*W_
#define NWIN   2048
#define NHEAD  8
#define HID    1024

// ---------------- scratch (device globals; fp16 views overlay float arrays) --
__device__ float g_short[(size_t)TOK * C_];        // f32: shortcut, then mlp2 out
__device__ float g_bufA [(size_t)TOK * C_];        // half: LN1(win order) -> attn out
__device__ float g_qkv  [(size_t)TOK * 3 * C_];    // half: qkv -> ln2 out
__device__ float g_xres [(size_t)TOK * C_];        // f32: x after attn residual
__device__ float g_hid  [(size_t)TOK * HID];       // half: mlp hidden
__device__ float g_wts  [786432];                  // half: transposed weights [N][K]

#define WOFF_QKV  0
#define WOFF_PROJ 196608
#define WOFF_W1   262144
#define WOFF_W2   524288

// window-order row m -> spatial token (for proj scatter epilogue)
__device__ __forceinline__ int win_token(int m) {
    int win = m / 49;
    int n   = m - win * 49;
    int b   = win >> 6;
    int r   = win & 63;
    int i   = n / 7;
    int j   = n - i * 7;
    int h = (r >> 3) * 7 + i + 3; if (h >= H_) h -= H_;
    int w = (r & 7)  * 7 + j + 3; if (w >= W_) w -= W_;
    return (b * H_ + h) * W_ + w;
}

// ---------------- ptx helpers ------------------------------------------------
__device__ __forceinline__ void mma_f16(float (&d)[4],
                                        uint32_t a0, uint32_t a1, uint32_t a2, uint32_t a3,
                                        uint32_t b0, uint32_t b1) {
    asm volatile(
        "mma.sync.aligned.m16n8k16.row.col.f32.f16.f16.f32 "
        "{%0,%1,%2,%3}, {%4,%5,%6,%7}, {%8,%9}, {%0,%1,%2,%3};\n"
        : "+f"(d[0]), "+f"(d[1]), "+f"(d[2]), "+f"(d[3])
        : "r"(a0), "r"(a1), "r"(a2), "r"(a3), "r"(b0), "r"(b1));
}
__device__ __forceinline__ uint32_t swz128(uint32_t b) { return b ^ ((b >> 3) & 0x70); }
__device__ __forceinline__ void ldsm4(uint32_t& r0, uint32_t& r1, uint32_t& r2, uint32_t& r3,
                                      uint32_t a) {
    asm volatile("ldmatrix.sync.aligned.m8n8.x4.shared.b16 {%0,%1,%2,%3}, [%4];"
                 : "=r"(r0), "=r"(r1), "=r"(r2), "=r"(r3) : "r"(a));
}
__device__ __forceinline__ void mbar_init(uint32_t a, uint32_t cnt) {
    asm volatile("mbarrier.init.shared.b64 [%0], %1;" :: "r"(a), "r"(cnt) : "memory");
}
__device__ __forceinline__ void mbar_expect(uint32_t a, uint32_t tx) {
    asm volatile("mbarrier.arrive.expect_tx.shared.b64 _, [%0], %1;" :: "r"(a), "r"(tx) : "memory");
}
__device__ __forceinline__ void mbar_wait(uint32_t a, uint32_t ph) {
    asm volatile(
        "{\n\t.reg .pred P1;\n\t"
        "WL%=:\n\t"
        "mbarrier.try_wait.parity.acquire.cta.shared::cta.b64 P1, [%0], %1, 0x989680;\n\t"
        "@P1 bra WD%=;\n\t"
        "bra WL%=;\n\t"
        "WD%=:\n\t}"
        :: "r"(a), "r"(ph) : "memory");
}
__device__ __forceinline__ void tma2d(uint32_t dst, const void* map, int x, int y, uint32_t mbar) {
    asm volatile(
        "cp.async.bulk.tensor.2d.shared::cta.global.tile.mbarrier::complete_tx::bytes "
        "[%0], [%1, {%2, %3}], [%4];"
        :: "r"(dst), "l"(map), "r"(x), "r"(y), "r"(mbar) : "memory");
}

// ---------------- weight round + transpose: dst[n][k] = fp16(src[k][n]) -----
__global__ void k_wt(const float* __restrict__ src, __half* __restrict__ dst, int K, int N) {
    __shared__ float t[32][33];
    int k0 = blockIdx.x * 32, n0 = blockIdx.y * 32;
    int tx = threadIdx.x, ty = threadIdx.y;
    #pragma unroll
    for (int j = ty; j < 32; j += 8)
        t[j][tx] = src[(size_t)(k0 + j) * N + n0 + tx];
    __syncthreads();
    #pragma unroll
    for (int j = ty; j < 32; j += 8)
        dst[(size_t)(n0 + j) * K + k0 + tx] = __float2half(t[tx][j]);
}

// ---------------- fused transpose + LN1, output fp16 in WINDOW order ---------
__global__ __launch_bounds__(256)
void k_tr_ln(const float* __restrict__ x, const float* __restrict__ gam,
             const float* __restrict__ bet) {
    __shared__ float tile[256][33];
    int b = blockIdx.y, hw0 = blockIdx.x * 32;
    int tid = threadIdx.x;
    int tx = tid & 31, ty = tid >> 5;
    for (int c = ty; c < 256; c += 8)
        tile[c][tx] = x[((size_t)(b * 256 + c)) * HW_ + hw0 + tx];
    __syncthreads();

    __half* winout = (__half*)g_bufA;
    int lane = tx;
    #pragma unroll
    for (int q = 0; q < 4; q++) {
        int tk = ty * 4 + q;
        float s = 0.f, ss = 0.f;
        #pragma unroll
        for (int ci = 0; ci < 8; ci++) {
            float v = tile[lane + ci * 32][tk];
            s += v; ss += v * v;
        }
        #pragma unroll
        for (int o = 16; o; o >>= 1) {
            s  += __shfl_xor_sync(0xffffffffu, s, o);
            ss += __shfl_xor_sync(0xffffffffu, ss, o);
        }
        float mean = s * (1.0f / C_);
        float var  = ss * (1.0f / C_) - mean * mean;
        float rstd = rsqrtf(var + 1e-5f);

        int hw = hw0 + tk;
        int t  = b * HW_ + hw;
        int h  = hw / W_, w = hw - h * W_;
        int hs = (h >= 3) ? h - 3 : h + 53;
        int ws = (w >= 3) ? w - 3 : w + 53;
        int m  = (b * 64 + (hs / 7) * 8 + (ws / 7)) * 49 + (hs % 7) * 7 + (ws % 7);

        for (int c = lane; c < 256; c += 32) {
            float v = tile[c][tk];
            g_short[(size_t)t * C_ + c] = v;
            winout[(size_t)m * C_ + c] = __float2half((v - mean) * rstd * gam[c] + bet[c]);
        }
    }
}

// ---------------- output transpose (B,HW,C) -> (B,C,HW), src g_short ---------
__global__ void k_transpose_out(float* __restrict__ out) {
    __shared__ float tile[32][33];
    int b = blockIdx.z, hw0 = blockIdx.x * 32, c0 = blockIdx.y * 32;
    int tx = threadIdx.x, ty = threadIdx.y;
    const float* src = g_short + ((size_t)b * HW_ + hw0) * C_ + c0;
    #pragma unroll
    for (int j = ty; j < 32; j += 8) tile[j][tx] = src[(size_t)j * C_ + tx];
    __syncthreads();
    float* dst = out + ((size_t)b * C_ + c0) * HW_ + hw0;
    #pragma unroll
    for (int j = ty; j < 32; j += 8) dst[(size_t)j * HW_ + tx] = tile[tx][j];
}

// ---------------- LN2 (f32 in, fp16 out) -------------------------------------
__global__ void k_ln(const float* __restrict__ x, const float* __restrict__ g,
                     const float* __restrict__ bb, __half* __restrict__ out) {
    int token = blockIdx.x;
    int tid = threadIdx.x;
    float4 v = ((const float4*)(x + (size_t)token * C_))[tid];
    float s  = v.x + v.y + v.z + v.w;
    float ss = v.x * v.x + v.y * v.y + v.z * v.z + v.w * v.w;
    #pragma unroll
    for (int o = 16; o; o >>= 1) {
        s  += __shfl_xor_sync(0xffffffffu, s, o);
        ss += __shfl_xor_sync(0xffffffffu, ss, o);
    }
    __shared__ float sh[4];
    if ((tid & 31) == 0) { sh[tid >> 5] = s; sh[2 + (tid >> 5)] = ss; }
    __syncthreads();
    s = sh[0] + sh[1]; ss = sh[2] + sh[3];
    float mean = s * (1.0f / C_);
    float var  = ss * (1.0f / C_) - mean * mean;
    float rstd = rsqrtf(var + 1e-5f);
    float4 gg = ((const float4*)g)[tid];
    float4 bv = ((const float4*)bb)[tid];
    __half2 h0 = __floats2half2_rn((v.x - mean) * rstd * gg.x + bv.x,
                                   (v.y - mean) * rstd * gg.y + bv.y);
    __half2 h1 = __floats2half2_rn((v.z - mean) * rstd * gg.z + bv.z,
                                   (v.w - mean) * rstd * gg.w + bv.w);
    __half2* op = (__half2*)(out + (size_t)token * C_);
    op[2 * tid]     = h0;
    op[2 * tid + 1] = h1;
}

// ---------------- TMA-fed fp16 GEMM 128x128, BK=64, 3-stage pipeline ---------
// A global: [Mrows][K] fp16. B global: transposed weights [N][K] fp16.
// Tiles: [128 rows][64 halfs] (128B rows) SW128 in smem; 2 TMA ops/stage.
// k-step offsets {0,32,64,96}B applied via XOR (swizzle-safe: base col bits
// [6:5] are clear and SW128's XOR field derives from bits [9:7]).
// EPI: 0 bias->half | 1 bias+GELU->half | 2 bias+scatter+extra->f32 | 3 bias+extra->f32
#define NS 3
#define STG_BYTES 16384                    // 128 rows * 128B per side per stage
#define GEMM_SMEM (NS * 2 * STG_BYTES + 64)

template<int EPI>
__global__ __launch_bounds__(256, 2)
void k_gemm(const __grid_constant__ CUtensorMap dA,
            const __grid_constant__ CUtensorMap dB,
            const float* __restrict__ bias, const float* __restrict__ extra,
            void* __restrict__ Cout, int N, int K)
{
    extern __shared__ __align__(1024) char smem[];
    uint32_t aBase = (uint32_t)__cvta_generic_to_shared(smem);
    uint32_t bBase = aBase + NS * STG_BYTES;
    uint32_t mBase = bBase + NS * STG_BYTES;

    int tid = threadIdx.x;
    int lane = tid & 31, wid = tid >> 5;
    int warpM = wid >> 1, warpN = wid & 1;
    int qrow = lane >> 2, qcol = lane & 3;
    int bm = blockIdx.x * 128, bn = blockIdx.y * 128;
    int niters = K >> 6;

    if (tid == 0) {
        #pragma unroll
        for (int s = 0; s < NS; s++) mbar_init(mBase + 8 * s, 1);
    }
    __syncthreads();

    if (tid == 0) {
        #pragma unroll
        for (int j = 0; j < NS - 1; j++) {
            mbar_expect(mBase + 8 * j, 2 * STG_BYTES);
            tma2d(aBase + j * STG_BYTES, &dA, j * 64, bm, mBase + 8 * j);
            tma2d(bBase + j * STG_BYTES, &dB, j * 64, bn, mBase + 8 * j);
        }
    }

    // per-thread ldmatrix base addresses (stage 0, k-step 0); byte-col in {0,16}
    uint32_t aAddr[2], bAddr[4];
    {
        int lr = lane & 7;
        #pragma unroll
        for (int mt = 0; mt < 2; mt++) {
            int row = warpM * 32 + mt * 16 + lr + ((lane & 8) ? 8 : 0);
            int c4  = (lane & 16) ? 16 : 0;
            aAddr[mt] = aBase + swz128((uint32_t)(row * 128 + c4));
        }
        int mq = lane >> 3;
        #pragma unroll
        for (int np = 0; np < 4; np++) {
            int row = warpN * 64 + (np * 2 + (mq >> 1)) * 8 + lr;
            int c4  = (mq & 1) * 16;
            bAddr[np] = bBase + swz128((uint32_t)(row * 128 + c4));
        }
    }

    float acc[2][8][4];
    #pragma unroll
    for (int mt = 0; mt < 2; mt++)
        #pragma unroll
        for (int nt = 0; nt < 8; nt++)
            #pragma unroll
            for (int e = 0; e < 4; e++) acc[mt][nt][e] = 0.f;

    int scur = 0, pcur = 0;            // compute cursor
    int spre = NS - 1;                 // prefetch stage cursor (j = i + NS-1)
    for (int i = 0; i < niters; i++) {
        mbar_wait(mBase + 8 * scur, pcur);
        uint32_t so = (uint32_t)scur * STG_BYTES;

        #pragma unroll
        for (int ks = 0; ks < 4; ks++) {        // 4 x k16 per stage (K=64)
            uint32_t kx = (uint32_t)(ks * 32);  // XOR-applied, swizzle-safe
            uint32_t af[2][4], bf[8][2];
            #pragma unroll
            for (int mt = 0; mt < 2; mt++)
                ldsm4(af[mt][0], af[mt][1], af[mt][2], af[mt][3],
                      (aAddr[mt] + so) ^ kx);
            #pragma unroll
            for (int np = 0; np < 4; np++)
                ldsm4(bf[2 * np][0], bf[2 * np][1], bf[2 * np + 1][0], bf[2 * np + 1][1],
                      (bAddr[np] + so) ^ kx);
            #pragma unroll
            for (int mt = 0; mt < 2; mt++)
                #pragma unroll
                for (int nt = 0; nt < 8; nt++)
                    mma_f16(acc[mt][nt], af[mt][0], af[mt][1], af[mt][2], af[mt][3],
                            bf[nt][0], bf[nt][1]);
        }
        __syncthreads();

        int j = i + NS - 1;
        if (j < niters && tid == 0) {
            mbar_expect(mBase + 8 * spre, 2 * STG_BYTES);
            tma2d(aBase + spre * STG_BYTES, &dA, j * 64, bm, mBase + 8 * spre);
            tma2d(bBase + spre * STG_BYTES, &dB, j * 64, bn, mBase + 8 * spre);
        }
        if (++scur == NS) { scur = 0; pcur ^= 1; }
        if (++spre == NS) spre = 0;
    }

    // -------- epilogue --------
    #pragma unroll
    for (int mt = 0; mt < 2; mt++) {
        #pragma unroll
        for (int half = 0; half < 2; half++) {
            int gr = bm + warpM * 32 + mt * 16 + qrow + half * 8;
            size_t orow = (EPI == 2) ? (size_t)win_token(gr) : (size_t)gr;
            #pragma unroll
            for (int nt = 0; nt < 8; nt++) {
                int col = bn + warpN * 64 + nt * 8 + 2 * qcol;
                float v0 = acc[mt][nt][2 * half + 0] + bias[col];
                float v1 = acc[mt][nt][2 * half + 1] + bias[col + 1];
                if (EPI == 1) {
                    v0 = 0.5f * v0 * (1.0f + erff(v0 * 0.7071067811865475f));
                    v1 = 0.5f * v1 * (1.0f + erff(v1 * 0.7071067811865475f));
                }
                if (EPI == 0 || EPI == 1) {
                    *(__half2*)((__half*)Cout + orow * N + col) = __floats2half2_rn(v0, v1);
                } else {
                    const float* ep = extra + orow * N + col;
                    v0 += ep[0];
                    v1 += ep[1];
                    *(float2*)((float*)Cout + orow * N + col) = make_float2(v0, v1);
                }
            }
        }
    }
}

// ---------------- windowed attention (fp16 IO via half2, f32 math) -----------
__global__ void __launch_bounds__(128)
k_attn(const __half* __restrict__ qkv, __half* __restrict__ out) {
    __shared__ float qs[49][36];
    __shared__ float ks[49][33];
    __shared__ float vs[49][33];
    __shared__ float S[49][50];
    int win  = blockIdx.x >> 3;
    int head = blockIdx.x & 7;
    int tid  = threadIdx.x;
    int lane = tid & 31;
    int wj   = tid >> 5;
    int base = win * 49;

    for (int idx = tid; idx < 49 * 16; idx += 128) {
        int n = idx >> 4, d2 = idx & 15;
        const __half2* p = (const __half2*)(qkv + (size_t)(base + n) * 768 + head * 32) + d2;
        float2 q2 = __half22float2(p[0]);
        float2 k2 = __half22float2(p[128]);
        float2 v2 = __half22float2(p[256]);
        qs[n][2 * d2] = q2.x; qs[n][2 * d2 + 1] = q2.y;
        ks[n][2 * d2] = k2.x; ks[n][2 * d2 + 1] = k2.y;
        vs[n][2 * d2] = v2.x; vs[n][2 * d2 + 1] = v2.y;
    }
    __syncthreads();

    const float scale = 0.1767766952966369f;

    #pragma unroll
    for (int pass = 0; pass < 2; pass++) {
        int m = pass * 32 + lane;
        bool act = (m < 49);
        int mm = act ? m : 48;
        float kreg[32];
        #pragma unroll
        for (int d = 0; d < 32; d++) kreg[d] = ks[mm][d];
        for (int n = wj; n < 49; n += 4) {
            float acc = 0.f;
            #pragma unroll
            for (int dq = 0; dq < 8; dq++) {
                float4 q4 = *(const float4*)&qs[n][dq * 4];
                acc += q4.x * kreg[dq * 4 + 0];
                acc += q4.y * kreg[dq * 4 + 1];
                acc += q4.z * kreg[dq * 4 + 2];
                acc += q4.w * kreg[dq * 4 + 3];
            }
            if (act) S[n][m] = acc * scale;
        }
    }
    __syncthreads();

    if (tid < 49) {
        float mx = -1e30f;
        #pragma unroll 7
        for (int m = 0; m < 49; m++) mx = fmaxf(mx, S[tid][m]);
        float sum = 0.f;
        #pragma unroll 7
        for (int m = 0; m < 49; m++) { float e = __expf(S[tid][m] - mx); S[tid][m] = e; sum += e; }
        float inv = 1.0f / sum;
        #pragma unroll 7
        for (int m = 0; m < 49; m++) S[tid][m] *= inv;
    }
    __syncthreads();

    float vreg[49];
    #pragma unroll
    for (int m = 0; m < 49; m++) vreg[m] = vs[m][lane];
    for (int n = wj; n < 49; n += 4) {
        float acc = 0.f;
        #pragma unroll
        for (int m = 0; m < 49; m++) acc += S[n][m] * vreg[m];
        out[(size_t)(base + n) * C_ + head * 32 + lane] = __float2half(acc);
    }
}

// ---------------- host: tensor-map encode ------------------------------------
typedef CUresult (*tmap_fn)(CUtensorMap*, CUtensorMapDataType, cuuint32_t, void*,
                            const cuuint64_t*, const cuuint64_t*, const cuuint32_t*,
                            const cuuint32_t*, CUtensorMapInterleave, CUtensorMapSwizzle,
                            CUtensorMapL2promotion, CUtensorMapFloatOOBfill);

static tmap_fn get_enc() {
    void* fn = nullptr;
    cudaDriverEntryPointQueryResult qr;
#if CUDART_VERSION >= 12050
    cudaGetDriverEntryPointByVersion("cuTensorMapEncodeTiled", &fn, 12000,
                                     cudaEnableDefault, &qr);
#else
    cudaGetDriverEntryPoint("cuTensorMapEncodeTiled", &fn, cudaEnableDefault, &qr);
#endif
    return (tmap_fn)fn;
}

static void enc2d(tmap_fn f, CUtensorMap* m, void* ptr, uint64_t innerK, uint64_t outerRows) {
    cuuint64_t dims[2]    = {innerK, outerRows};
    cuuint64_t strides[1] = {innerK * 2};
    cuuint32_t box[2]     = {64, 128};
    cuuint32_t el[2]      = {1, 1};
    f(m, CU_TENSOR_MAP_DATA_TYPE_FLOAT16, 2, ptr, dims, strides, box, el,
      CU_TENSOR_MAP_INTERLEAVE_NONE, CU_TENSOR_MAP_SWIZZLE_128B,
      CU_TENSOR_MAP_L2_PROMOTION_L2_128B, CU_TENSOR_MAP_FLOAT_OOB_FILL_NONE);
}

// ---------------- launch ----------------------------------------------------
extern "C" void kernel_launch(void* const* d_in, const int* in_sizes, int n_in,
                              void* d_out, int out_size) {
    const float* x      = (const float*)d_in[0];
    const float* n1_g   = (const float*)d_in[1];
    const float* n1_b   = (const float*)d_in[2];
    const float* qkv_w  = (const float*)d_in[3];
    const float* qkv_b  = (const float*)d_in[4];
    const float* proj_w = (const float*)d_in[5];
    const float* proj_b = (const float*)d_in[6];
    const float* n2_g   = (const float*)d_in[7];
    const float* n2_b   = (const float*)d_in[8];
    const float* mlp_w1 = (const float*)d_in[9];
    const float* mlp_b1 = (const float*)d_in[10];
    const float* mlp_w2 = (const float*)d_in[11];
    const float* mlp_b2 = (const float*)d_in[12];
    float* out = (float*)d_out;

    float *p_short, *p_bufA, *p_qkv, *p_xres, *p_hid, *p_wts_f;
    cudaGetSymbolAddress((void**)&p_short, g_short);
    cudaGetSymbolAddress((void**)&p_bufA,  g_bufA);
    cudaGetSymbolAddress((void**)&p_qkv,   g_qkv);
    cudaGetSymbolAddress((void**)&p_xres,  g_xres);
    cudaGetSymbolAddress((void**)&p_hid,   g_hid);
    cudaGetSymbolAddress((void**)&p_wts_f, g_wts);
    __half* p_wts = (__half*)p_wts_f;

    tmap_fn enc = get_enc();
    CUtensorMap dA_bufA, dA_ln2, dA_hid, dB_qkv, dB_proj, dB_w1, dB_w2;
    enc2d(enc, &dA_bufA, p_bufA,            256,  TOK);   // LN1win / attn-out (half)
    enc2d(enc, &dA_ln2,  p_qkv,             256,  TOK);   // LN2 out (half)
    enc2d(enc, &dA_hid,  p_hid,             1024, TOK);   // hidden (half)
    enc2d(enc, &dB_qkv,  p_wts + WOFF_QKV,  256,  768);
    enc2d(enc, &dB_proj, p_wts + WOFF_PROJ, 256,  256);
    enc2d(enc, &dB_w1,   p_wts + WOFF_W1,   256,  1024);
    enc2d(enc, &dB_w2,   p_wts + WOFF_W2,   1024, 256);

    cudaFuncSetAttribute(k_gemm<0>, cudaFuncAttributeMaxDynamicSharedMemorySize, GEMM_SMEM);
    cudaFuncSetAttribute(k_gemm<1>, cudaFuncAttributeMaxDynamicSharedMemorySize, GEMM_SMEM);
    cudaFuncSetAttribute(k_gemm<2>, cudaFuncAttributeMaxDynamicSharedMemorySize, GEMM_SMEM);
    cudaFuncSetAttribute(k_gemm<3>, cudaFuncAttributeMaxDynamicSharedMemorySize, GEMM_SMEM);

    dim3 tb(32, 8);
    // weight round + transpose into fp16 [N][K]
    k_wt<<<dim3(8, 24),  tb>>>(qkv_w,  p_wts + WOFF_QKV,  256, 768);
    k_wt<<<dim3(8, 8),   tb>>>(proj_w, p_wts + WOFF_PROJ, 256, 256);
    k_wt<<<dim3(8, 32),  tb>>>(mlp_w1, p_wts + WOFF_W1,   256, 1024);
    k_wt<<<dim3(32, 8),  tb>>>(mlp_w2, p_wts + WOFF_W2,   1024, 256);

    // fused transpose + LN1 (shortcut f32 spatial; LN1 fp16 window order)
    k_tr_ln<<<dim3(98, 32), 256>>>(x, n1_g, n1_b);
    // qkv = winLN1 @ qkv_w^T + b  (fp16 out)
    k_gemm<0><<<dim3(784, 6), 256, GEMM_SMEM>>>(dA_bufA, dB_qkv, qkv_b, nullptr, p_qkv, 768, 256);
    // windowed MHSA (fp16 io)
    k_attn<<<NWIN * NHEAD, 128>>>((const __half*)p_qkv, (__half*)p_bufA);
    // xres = shortcut + scatter(attn_o @ proj_w^T + b)   (f32 out)
    k_gemm<2><<<dim3(784, 2), 256, GEMM_SMEM>>>(dA_bufA, dB_proj, proj_b, p_short, p_xres, 256, 256);
    // LN2 (fp16 out into g_qkv scratch)
    k_ln<<<TOK, 64>>>(p_xres, n2_g, n2_b, (__half*)p_qkv);
    // hid = gelu(ln2 @ w1^T + b1)  (fp16 out)
    k_gemm<1><<<dim3(784, 8), 256, GEMM_SMEM>>>(dA_ln2, dB_w1, mlp_b1, nullptr, p_hid, 1024, 256);
    // final = xres + hid @ w2^T + b2  (f32 out into g_short)
    k_gemm<3><<<dim3(784, 2), 256, GEMM_SMEM>>>(dA_hid, dB_w2, mlp_b2, p_xres, p_short, 256, 1024);
    // (B,HW,C) -> (B,C,HW)
    k_transpose_out<<<dim3(98, 8, 32), tb>>>(out);
}

// round 13
// speedup vs baseline: 5.0015x; 1.0690x over previous
#include <cuda_runtime.h>
#include <cuda.h>
#include <cuda_fp16.h>
#include <math.h>
#include <stdint.h>

#define B_     32
#define C_     256
#define H_     56
#define W_     56
#define HW_    3136
#define TOK    100352          // B_*H_*W_
#define NWIN   2048
#define NHEAD  8
#define HID    1024

// ---------------- scratch (device globals; fp16 views overlay float arrays) --
__device__ float g_short[(size_t)TOK * C_];        // f32: shortcut (spatial order)
__device__ float g_bufA [(size_t)TOK * C_];        // half: LN1(win order) -> attn out
__device__ float g_qkv  [(size_t)TOK * 3 * C_];    // half: qkv -> ln2 out
__device__ float g_xres [(size_t)TOK * C_];        // f32: x after attn residual
__device__ float g_hid  [(size_t)TOK * HID];       // half: mlp hidden
__device__ float g_wts  [786432];                  // half: transposed weights [N][K]

#define WOFF_QKV  0
#define WOFF_PROJ 196608
#define WOFF_W1   262144
#define WOFF_W2   524288

// window-order row m -> spatial token (for proj scatter epilogue)
__device__ __forceinline__ int win_token(int m) {
    int win = m / 49;
    int n   = m - win * 49;
    int b   = win >> 6;
    int r   = win & 63;
    int i   = n / 7;
    int j   = n - i * 7;
    int h = (r >> 3) * 7 + i + 3; if (h >= H_) h -= H_;
    int w = (r & 7)  * 7 + j + 3; if (w >= W_) w -= W_;
    return (b * H_ + h) * W_ + w;
}

// ---------------- ptx helpers ------------------------------------------------
__device__ __forceinline__ void mma_f16(float (&d)[4],
                                        uint32_t a0, uint32_t a1, uint32_t a2, uint32_t a3,
                                        uint32_t b0, uint32_t b1) {
    asm volatile(
        "mma.sync.aligned.m16n8k16.row.col.f32.f16.f16.f32 "
        "{%0,%1,%2,%3}, {%4,%5,%6,%7}, {%8,%9}, {%0,%1,%2,%3};\n"
        : "+f"(d[0]), "+f"(d[1]), "+f"(d[2]), "+f"(d[3])
        : "r"(a0), "r"(a1), "r"(a2), "r"(a3), "r"(b0), "r"(b1));
}
__device__ __forceinline__ uint32_t swz128(uint32_t b) { return b ^ ((b >> 3) & 0x70); }
__device__ __forceinline__ void ldsm4(uint32_t& r0, uint32_t& r1, uint32_t& r2, uint32_t& r3,
                                      uint32_t a) {
    asm volatile("ldmatrix.sync.aligned.m8n8.x4.shared.b16 {%0,%1,%2,%3}, [%4];"
                 : "=r"(r0), "=r"(r1), "=r"(r2), "=r"(r3) : "r"(a));
}
__device__ __forceinline__ void mbar_init(uint32_t a, uint32_t cnt) {
    asm volatile("mbarrier.init.shared.b64 [%0], %1;" :: "r"(a), "r"(cnt) : "memory");
}
__device__ __forceinline__ void mbar_expect(uint32_t a, uint32_t tx) {
    asm volatile("mbarrier.arrive.expect_tx.shared.b64 _, [%0], %1;" :: "r"(a), "r"(tx) : "memory");
}
__device__ __forceinline__ void mbar_wait(uint32_t a, uint32_t ph) {
    asm volatile(
        "{\n\t.reg .pred P1;\n\t"
        "WL%=:\n\t"
        "mbarrier.try_wait.parity.acquire.cta.shared::cta.b64 P1, [%0], %1, 0x989680;\n\t"
        "@P1 bra WD%=;\n\t"
        "bra WL%=;\n\t"
        "WD%=:\n\t}"
        :: "r"(a), "r"(ph) : "memory");
}
__device__ __forceinline__ void tma2d(uint32_t dst, const void* map, int x, int y, uint32_t mbar) {
    asm volatile(
        "cp.async.bulk.tensor.2d.shared::cta.global.tile.mbarrier::complete_tx::bytes "
        "[%0], [%1, {%2, %3}], [%4];"
        :: "r"(dst), "l"(map), "r"(x), "r"(y), "r"(mbar) : "memory");
}

// ---------------- merged weight round+transpose: dst[n][k] = fp16(src[k][n]) -
// 768 blocks: [0,192) qkv, [192,256) proj, [256,512) w1, [512,768) w2
__global__ void k_wt_all(const float* __restrict__ qkv_w, const float* __restrict__ proj_w,
                         const float* __restrict__ w1, const float* __restrict__ w2,
                         __half* __restrict__ dst) {
    __shared__ float t[32][33];
    int bid = blockIdx.x;
    const float* src; __half* d; int K, N, rel;
    if (bid < 192)      { src = qkv_w;  d = dst + WOFF_QKV;  K = 256;  N = 768;  rel = bid; }
    else if (bid < 256) { src = proj_w; d = dst + WOFF_PROJ; K = 256;  N = 256;  rel = bid - 192; }
    else if (bid < 512) { src = w1;     d = dst + WOFF_W1;   K = 256;  N = 1024; rel = bid - 256; }
    else                { src = w2;     d = dst + WOFF_W2;   K = 1024; N = 256;  rel = bid - 512; }
    int nkb = K >> 5;
    int k0 = (rel % nkb) * 32, n0 = (rel / nkb) * 32;
    int tx = threadIdx.x, ty = threadIdx.y;
    #pragma unroll
    for (int j = ty; j < 32; j += 8)
        t[j][tx] = src[(size_t)(k0 + j) * N + n0 + tx];
    __syncthreads();
    #pragma unroll
    for (int j = ty; j < 32; j += 8)
        d[(size_t)(n0 + j) * K + k0 + tx] = __float2half(t[tx][j]);
}

// ---------------- fused transpose + LN1, output fp16 in WINDOW order ---------
__global__ __launch_bounds__(256)
void k_tr_ln(const float* __restrict__ x, const float* __restrict__ gam,
             const float* __restrict__ bet) {
    __shared__ float tile[256][33];
    int b = blockIdx.y, hw0 = blockIdx.x * 32;
    int tid = threadIdx.x;
    int tx = tid & 31, ty = tid >> 5;
    for (int c = ty; c < 256; c += 8)
        tile[c][tx] = x[((size_t)(b * 256 + c)) * HW_ + hw0 + tx];
    __syncthreads();

    __half* winout = (__half*)g_bufA;
    int lane = tx;
    #pragma unroll
    for (int q = 0; q < 4; q++) {
        int tk = ty * 4 + q;
        float s = 0.f, ss = 0.f;
        #pragma unroll
        for (int ci = 0; ci < 8; ci++) {
            float v = tile[lane + ci * 32][tk];
            s += v; ss += v * v;
        }
        #pragma unroll
        for (int o = 16; o; o >>= 1) {
            s  += __shfl_xor_sync(0xffffffffu, s, o);
            ss += __shfl_xor_sync(0xffffffffu, ss, o);
        }
        float mean = s * (1.0f / C_);
        float var  = ss * (1.0f / C_) - mean * mean;
        float rstd = rsqrtf(var + 1e-5f);

        int hw = hw0 + tk;
        int t  = b * HW_ + hw;
        int h  = hw / W_, w = hw - h * W_;
        int hs = (h >= 3) ? h - 3 : h + 53;
        int ws = (w >= 3) ? w - 3 : w + 53;
        int m  = (b * 64 + (hs / 7) * 8 + (ws / 7)) * 49 + (hs % 7) * 7 + (ws % 7);

        for (int c = lane; c < 256; c += 32) {
            float v = tile[c][tk];
            g_short[(size_t)t * C_ + c] = v;
            winout[(size_t)m * C_ + c] = __float2half((v - mean) * rstd * gam[c] + bet[c]);
        }
    }
}

// ---------------- LN2 (f32 in, fp16 out) -------------------------------------
__global__ void k_ln(const float* __restrict__ x, const float* __restrict__ g,
                     const float* __restrict__ bb, __half* __restrict__ out) {
    int token = blockIdx.x;
    int tid = threadIdx.x;
    float4 v = ((const float4*)(x + (size_t)token * C_))[tid];
    float s  = v.x + v.y + v.z + v.w;
    float ss = v.x * v.x + v.y * v.y + v.z * v.z + v.w * v.w;
    #pragma unroll
    for (int o = 16; o; o >>= 1) {
        s  += __shfl_xor_sync(0xffffffffu, s, o);
        ss += __shfl_xor_sync(0xffffffffu, ss, o);
    }
    __shared__ float sh[4];
    if ((tid & 31) == 0) { sh[tid >> 5] = s; sh[2 + (tid >> 5)] = ss; }
    __syncthreads();
    s = sh[0] + sh[1]; ss = sh[2] + sh[3];
    float mean = s * (1.0f / C_);
    float var  = ss * (1.0f / C_) - mean * mean;
    float rstd = rsqrtf(var + 1e-5f);
    float4 gg = ((const float4*)g)[tid];
    float4 bv = ((const float4*)bb)[tid];
    __half2 h0 = __floats2half2_rn((v.x - mean) * rstd * gg.x + bv.x,
                                   (v.y - mean) * rstd * gg.y + bv.y);
    __half2 h1 = __floats2half2_rn((v.z - mean) * rstd * gg.z + bv.z,
                                   (v.w - mean) * rstd * gg.w + bv.w);
    __half2* op = (__half2*)(out + (size_t)token * C_);
    op[2 * tid]     = h0;
    op[2 * tid + 1] = h1;
}

// ---------------- TMA-fed fp16 GEMM 128x128, BK=64, 3-stage pipeline ---------
// Grid: blockIdx.x = N tile (fastest -> L2 reuse of A), blockIdx.y = M tile.
// EPI: 0 bias->half | 1 bias+GELU->half | 2 bias+scatter+extra->f32
//      3 bias+extra -> f32 TRANSPOSED write to (B,C,HW) output via smem staging
#define NS 3
#define STG_BYTES 16384                    // 128 rows * 128B per side per stage
#define GEMM_SMEM (NS * 2 * STG_BYTES + 64)

template<int EPI>
__global__ __launch_bounds__(256, 2)
void k_gemm(const __grid_constant__ CUtensorMap dA,
            const __grid_constant__ CUtensorMap dB,
            const float* __restrict__ bias, const float* __restrict__ extra,
            void* __restrict__ Cout, int N, int K)
{
    extern __shared__ __align__(1024) char smem[];
    uint32_t aBase = (uint32_t)__cvta_generic_to_shared(smem);
    uint32_t bBase = aBase + NS * STG_BYTES;
    uint32_t mBase = bBase + NS * STG_BYTES;

    int tid = threadIdx.x;
    int lane = tid & 31, wid = tid >> 5;
    int warpM = wid >> 1, warpN = wid & 1;
    int qrow = lane >> 2, qcol = lane & 3;
    int bm = blockIdx.y * 128, bn = blockIdx.x * 128;
    int niters = K >> 6;

    if (tid == 0) {
        #pragma unroll
        for (int s = 0; s < NS; s++) mbar_init(mBase + 8 * s, 1);
    }
    __syncthreads();

    if (tid == 0) {
        #pragma unroll
        for (int j = 0; j < NS - 1; j++) {
            mbar_expect(mBase + 8 * j, 2 * STG_BYTES);
            tma2d(aBase + j * STG_BYTES, &dA, j * 64, bm, mBase + 8 * j);
            tma2d(bBase + j * STG_BYTES, &dB, j * 64, bn, mBase + 8 * j);
        }
    }

    // per-thread ldmatrix base addresses (stage 0, k-step 0); byte-col in {0,16}
    uint32_t aAddr[2], bAddr[4];
    {
        int lr = lane & 7;
        #pragma unroll
        for (int mt = 0; mt < 2; mt++) {
            int row = warpM * 32 + mt * 16 + lr + ((lane & 8) ? 8 : 0);
            int c4  = (lane & 16) ? 16 : 0;
            aAddr[mt] = aBase + swz128((uint32_t)(row * 128 + c4));
        }
        int mq = lane >> 3;
        #pragma unroll
        for (int np = 0; np < 4; np++) {
            int row = warpN * 64 + (np * 2 + (mq >> 1)) * 8 + lr;
            int c4  = (mq & 1) * 16;
            bAddr[np] = bBase + swz128((uint32_t)(row * 128 + c4));
        }
    }

    float acc[2][8][4];
    #pragma unroll
    for (int mt = 0; mt < 2; mt++)
        #pragma unroll
        for (int nt = 0; nt < 8; nt++)
            #pragma unroll
            for (int e = 0; e < 4; e++) acc[mt][nt][e] = 0.f;

    int scur = 0, pcur = 0;
    int spre = NS - 1;
    for (int i = 0; i < niters; i++) {
        mbar_wait(mBase + 8 * scur, pcur);
        uint32_t so = (uint32_t)scur * STG_BYTES;

        #pragma unroll
        for (int ks = 0; ks < 4; ks++) {
            uint32_t kx = (uint32_t)(ks * 32);  // XOR-applied, swizzle-safe
            uint32_t af[2][4], bf[8][2];
            #pragma unroll
            for (int mt = 0; mt < 2; mt++)
                ldsm4(af[mt][0], af[mt][1], af[mt][2], af[mt][3],
                      (aAddr[mt] + so) ^ kx);
            #pragma unroll
            for (int np = 0; np < 4; np++)
                ldsm4(bf[2 * np][0], bf[2 * np][1], bf[2 * np + 1][0], bf[2 * np + 1][1],
                      (bAddr[np] + so) ^ kx);
            #pragma unroll
            for (int mt = 0; mt < 2; mt++)
                #pragma unroll
                for (int nt = 0; nt < 8; nt++)
                    mma_f16(acc[mt][nt], af[mt][0], af[mt][1], af[mt][2], af[mt][3],
                            bf[nt][0], bf[nt][1]);
        }
        __syncthreads();

        int j = i + NS - 1;
        if (j < niters && tid == 0) {
            mbar_expect(mBase + 8 * spre, 2 * STG_BYTES);
            tma2d(aBase + spre * STG_BYTES, &dA, j * 64, bm, mBase + 8 * spre);
            tma2d(bBase + spre * STG_BYTES, &dB, j * 64, bn, mBase + 8 * spre);
        }
        if (++scur == NS) { scur = 0; pcur ^= 1; }
        if (++spre == NS) spre = 0;
    }

    // -------- epilogue --------
    if (EPI == 3) {
        // bias + extra, then transposed (B,C,HW) write through smem staging
        float* St = (float*)smem;                      // [col][row], stride 130
        #pragma unroll
        for (int mt = 0; mt < 2; mt++) {
            #pragma unroll
            for (int half = 0; half < 2; half++) {
                int rl = warpM * 32 + mt * 16 + qrow + half * 8;
                int gr = bm + rl;
                #pragma unroll
                for (int nt = 0; nt < 8; nt++) {
                    int cl  = warpN * 64 + nt * 8 + 2 * qcol;
                    int col = bn + cl;
                    const float* ep = extra + (size_t)gr * N + col;
                    float v0 = acc[mt][nt][2 * half + 0] + bias[col]     + ep[0];
                    float v1 = acc[mt][nt][2 * half + 1] + bias[col + 1] + ep[1];
                    St[cl * 130 + rl]       = v0;
                    St[(cl + 1) * 130 + rl] = v1;
                }
            }
        }
        __syncthreads();
        int bseg[4], hwseg[4];
        #pragma unroll
        for (int seg = 0; seg < 4; seg++) {
            int t = bm + seg * 32 + lane;
            bseg[seg]  = t / HW_;
            hwseg[seg] = t - bseg[seg] * HW_;
        }
        float* outp = (float*)Cout;
        #pragma unroll
        for (int cc = 0; cc < 16; cc++) {
            int cl = wid * 16 + cc;
            int gc = bn + cl;
            #pragma unroll
            for (int seg = 0; seg < 4; seg++)
                outp[((size_t)(bseg[seg] * 256 + gc)) * HW_ + hwseg[seg]] =
                    St[cl * 130 + seg * 32 + lane];
        }
    } else {
        #pragma unroll
        for (int mt = 0; mt < 2; mt++) {
            #pragma unroll
            for (int half = 0; half < 2; half++) {
                int gr = bm + warpM * 32 + mt * 16 + qrow + half * 8;
                size_t orow = (EPI == 2) ? (size_t)win_token(gr) : (size_t)gr;
                #pragma unroll
                for (int nt = 0; nt < 8; nt++) {
                    int col = bn + warpN * 64 + nt * 8 + 2 * qcol;
                    float v0 = acc[mt][nt][2 * half + 0] + bias[col];
                    float v1 = acc[mt][nt][2 * half + 1] + bias[col + 1];
                    if (EPI == 1) {
                        v0 = 0.5f * v0 * (1.0f + erff(v0 * 0.7071067811865475f));
                        v1 = 0.5f * v1 * (1.0f + erff(v1 * 0.7071067811865475f));
                    }
                    if (EPI == 0 || EPI == 1) {
                        *(__half2*)((__half*)Cout + orow * N + col) = __floats2half2_rn(v0, v1);
                    } else {
                        const float* ep = extra + orow * N + col;
                        v0 += ep[0];
                        v1 += ep[1];
                        *(float2*)((float*)Cout + orow * N + col) = make_float2(v0, v1);
                    }
                }
            }
        }
    }
}

// ---------------- windowed attention (fp16 IO via half2, f32 math) -----------
__global__ void __launch_bounds__(128)
k_attn(const __half* __restrict__ qkv, __half* __restrict__ out) {
    __shared__ float qs[49][36];
    __shared__ float ks[49][33];
    __shared__ float vs[49][33];
    __shared__ float S[49][50];
    int win  = blockIdx.x >> 3;
    int head = blockIdx.x & 7;
    int tid  = threadIdx.x;
    int lane = tid & 31;
    int wj   = tid >> 5;
    int base = win * 49;

    for (int idx = tid; idx < 49 * 16; idx += 128) {
        int n = idx >> 4, d2 = idx & 15;
        const __half2* p = (const __half2*)(qkv + (size_t)(base + n) * 768 + head * 32) + d2;
        float2 q2 = __half22float2(p[0]);
        float2 k2 = __half22float2(p[128]);
        float2 v2 = __half22float2(p[256]);
        qs[n][2 * d2] = q2.x; qs[n][2 * d2 + 1] = q2.y;
        ks[n][2 * d2] = k2.x; ks[n][2 * d2 + 1] = k2.y;
        vs[n][2 * d2] = v2.x; vs[n][2 * d2 + 1] = v2.y;
    }
    __syncthreads();

    const float scale = 0.1767766952966369f;

    #pragma unroll
    for (int pass = 0; pass < 2; pass++) {
        int m = pass * 32 + lane;
        bool act = (m < 49);
        int mm = act ? m : 48;
        float kreg[32];
        #pragma unroll
        for (int d = 0; d < 32; d++) kreg[d] = ks[mm][d];
        for (int n = wj; n < 49; n += 4) {
            float acc = 0.f;
            #pragma unroll
            for (int dq = 0; dq < 8; dq++) {
                float4 q4 = *(const float4*)&qs[n][dq * 4];
                acc += q4.x * kreg[dq * 4 + 0];
                acc += q4.y * kreg[dq * 4 + 1];
                acc += q4.z * kreg[dq * 4 + 2];
                acc += q4.w * kreg[dq * 4 + 3];
            }
            if (act) S[n][m] = acc * scale;
        }
    }
    __syncthreads();

    if (tid < 49) {
        float mx = -1e30f;
        #pragma unroll 7
        for (int m = 0; m < 49; m++) mx = fmaxf(mx, S[tid][m]);
        float sum = 0.f;
        #pragma unroll 7
        for (int m = 0; m < 49; m++) { float e = __expf(S[tid][m] - mx); S[tid][m] = e; sum += e; }
        float inv = 1.0f / sum;
        #pragma unroll 7
        for (int m = 0; m < 49; m++) S[tid][m] *= inv;
    }
    __syncthreads();

    float vreg[49];
    #pragma unroll
    for (int m = 0; m < 49; m++) vreg[m] = vs[m][lane];
    for (int n = wj; n < 49; n += 4) {
        float acc = 0.f;
        #pragma unroll
        for (int m = 0; m < 49; m++) acc += S[n][m] * vreg[m];
        out[(size_t)(base + n) * C_ + head * 32 + lane] = __float2half(acc);
    }
}

// ---------------- host: tensor-map encode ------------------------------------
typedef CUresult (*tmap_fn)(CUtensorMap*, CUtensorMapDataType, cuuint32_t, void*,
                            const cuuint64_t*, const cuuint64_t*, const cuuint32_t*,
                            const cuuint32_t*, CUtensorMapInterleave, CUtensorMapSwizzle,
                            CUtensorMapL2promotion, CUtensorMapFloatOOBfill);

static tmap_fn get_enc() {
    void* fn = nullptr;
    cudaDriverEntryPointQueryResult qr;
#if CUDART_VERSION >= 12050
    cudaGetDriverEntryPointByVersion("cuTensorMapEncodeTiled", &fn, 12000,
                                     cudaEnableDefault, &qr);
#else
    cudaGetDriverEntryPoint("cuTensorMapEncodeTiled", &fn, cudaEnableDefault, &qr);
#endif
    return (tmap_fn)fn;
}

static void enc2d(tmap_fn f, CUtensorMap* m, void* ptr, uint64_t innerK, uint64_t outerRows) {
    cuuint64_t dims[2]    = {innerK, outerRows};
    cuuint64_t strides[1] = {innerK * 2};
    cuuint32_t box[2]     = {64, 128};
    cuuint32_t el[2]      = {1, 1};
    f(m, CU_TENSOR_MAP_DATA_TYPE_FLOAT16, 2, ptr, dims, strides, box, el,
      CU_TENSOR_MAP_INTERLEAVE_NONE, CU_TENSOR_MAP_SWIZZLE_128B,
      CU_TENSOR_MAP_L2_PROMOTION_L2_128B, CU_TENSOR_MAP_FLOAT_OOB_FILL_NONE);
}

// ---------------- launch ----------------------------------------------------
extern "C" void kernel_launch(void* const* d_in, const int* in_sizes, int n_in,
                              void* d_out, int out_size) {
    const float* x      = (const float*)d_in[0];
    const float* n1_g   = (const float*)d_in[1];
    const float* n1_b   = (const float*)d_in[2];
    const float* qkv_w  = (const float*)d_in[3];
    const float* qkv_b  = (const float*)d_in[4];
    const float* proj_w = (const float*)d_in[5];
    const float* proj_b = (const float*)d_in[6];
    const float* n2_g   = (const float*)d_in[7];
    const float* n2_b   = (const float*)d_in[8];
    const float* mlp_w1 = (const float*)d_in[9];
    const float* mlp_b1 = (const float*)d_in[10];
    const float* mlp_w2 = (const float*)d_in[11];
    const float* mlp_b2 = (const float*)d_in[12];
    float* out = (float*)d_out;

    float *p_short, *p_bufA, *p_qkv, *p_xres, *p_hid, *p_wts_f;
    cudaGetSymbolAddress((void**)&p_short, g_short);
    cudaGetSymbolAddress((void**)&p_bufA,  g_bufA);
    cudaGetSymbolAddress((void**)&p_qkv,   g_qkv);
    cudaGetSymbolAddress((void**)&p_xres,  g_xres);
    cudaGetSymbolAddress((void**)&p_hid,   g_hid);
    cudaGetSymbolAddress((void**)&p_wts_f, g_wts);
    __half* p_wts = (__half*)p_wts_f;

    tmap_fn enc = get_enc();
    CUtensorMap dA_bufA, dA_ln2, dA_hid, dB_qkv, dB_proj, dB_w1, dB_w2;
    enc2d(enc, &dA_bufA, p_bufA,            256,  TOK);   // LN1win / attn-out (half)
    enc2d(enc, &dA_ln2,  p_qkv,             256,  TOK);   // LN2 out (half)
    enc2d(enc, &dA_hid,  p_hid,             1024, TOK);   // hidden (half)
    enc2d(enc, &dB_qkv,  p_wts + WOFF_QKV,  256,  768);
    enc2d(enc, &dB_proj, p_wts + WOFF_PROJ, 256,  256);
    enc2d(enc, &dB_w1,   p_wts + WOFF_W1,   256,  1024);
    enc2d(enc, &dB_w2,   p_wts + WOFF_W2,   1024, 256);

    cudaFuncSetAttribute(k_gemm<0>, cudaFuncAttributeMaxDynamicSharedMemorySize, GEMM_SMEM);
    cudaFuncSetAttribute(k_gemm<1>, cudaFuncAttributeMaxDynamicSharedMemorySize, GEMM_SMEM);
    cudaFuncSetAttribute(k_gemm<2>, cudaFuncAttributeMaxDynamicSharedMemorySize, GEMM_SMEM);
    cudaFuncSetAttribute(k_gemm<3>, cudaFuncAttributeMaxDynamicSharedMemorySize, GEMM_SMEM);

    dim3 tb(32, 8);
    // weight round + transpose into fp16 [N][K] (single merged launch)
    k_wt_all<<<768, tb>>>(qkv_w, proj_w, mlp_w1, mlp_w2, p_wts);

    // fused transpose + LN1 (shortcut f32 spatial; LN1 fp16 window order)
    k_tr_ln<<<dim3(98, 32), 256>>>(x, n1_g, n1_b);
    // qkv = winLN1 @ qkv_w^T + b  (fp16 out); bn fastest for A L2 reuse
    k_gemm<0><<<dim3(6, 784), 256, GEMM_SMEM>>>(dA_bufA, dB_qkv, qkv_b, nullptr, p_qkv, 768, 256);
    // windowed MHSA (fp16 io)
    k_attn<<<NWIN * NHEAD, 128>>>((const __half*)p_qkv, (__half*)p_bufA);
    // xres = shortcut + scatter(attn_o @ proj_w^T + b)   (f32 out)
    k_gemm<2><<<dim3(2, 784), 256, GEMM_SMEM>>>(dA_bufA, dB_proj, proj_b, p_short, p_xres, 256, 256);
    // LN2 (fp16 out into g_qkv scratch)
    k_ln<<<TOK, 64>>>(p_xres, n2_g, n2_b, (__half*)p_qkv);
    // hid = gelu(ln2 @ w1^T + b1)  (fp16 out)
    k_gemm<1><<<dim3(8, 784), 256, GEMM_SMEM>>>(dA_ln2, dB_w1, mlp_b1, nullptr, p_hid, 1024, 256);
    // final = xres + hid @ w2^T + b2, written DIRECTLY transposed to (B,C,HW) out
    k_gemm<3><<<dim3(2, 784), 256, GEMM_SMEM>>>(dA_hid, dB_w2, mlp_b2, p_xres, out, 256, 1024);
}

// round 15
// speedup vs baseline: 5.2677x; 1.0532x over previous
#include <cuda_runtime.h>
#include <cuda.h>
#include <cuda_fp16.h>
#include <math.h>
#include <stdint.h>

#define B_     32
#define C_     256
#define H_     56
#define W_     56
#define HW_    3136
#define TOK    100352          // B_*H_*W_
#define NWIN   2048
#define NHEAD  8
#define HID    1024

// ---------------- scratch (device globals; fp16 views overlay float arrays) --
__device__ float g_short[(size_t)TOK * C_];        // f32: shortcut (spatial order)
__device__ float g_bufA [(size_t)TOK * C_];        // half: LN1(win order) -> attn out
__device__ float g_qkv  [(size_t)TOK * 3 * C_];    // half: qkv -> ln2 out
__device__ float g_xres [(size_t)TOK * C_];        // f32: x after attn residual
__device__ float g_hid  [(size_t)TOK * HID];       // half: mlp hidden
__device__ float g_wts  [786432];                  // half: transposed weights [N][K]

#define WOFF_QKV  0
#define WOFF_PROJ 196608
#define WOFF_W1   262144
#define WOFF_W2   524288

// window-order row m -> spatial token (for proj scatter epilogue)
__device__ __forceinline__ int win_token(int m) {
    int win = m / 49;
    int n   = m - win * 49;
    int b   = win >> 6;
    int r   = win & 63;
    int i   = n / 7;
    int j   = n - i * 7;
    int h = (r >> 3) * 7 + i + 3; if (h >= H_) h -= H_;
    int w = (r & 7)  * 7 + j + 3; if (w >= W_) w -= W_;
    return (b * H_ + h) * W_ + w;
}

// ---------------- ptx helpers ------------------------------------------------
__device__ __forceinline__ void mma_f16(float (&d)[4],
                                        uint32_t a0, uint32_t a1, uint32_t a2, uint32_t a3,
                                        uint32_t b0, uint32_t b1) {
    asm volatile(
        "mma.sync.aligned.m16n8k16.row.col.f32.f16.f16.f32 "
        "{%0,%1,%2,%3}, {%4,%5,%6,%7}, {%8,%9}, {%0,%1,%2,%3};\n"
        : "+f"(d[0]), "+f"(d[1]), "+f"(d[2]), "+f"(d[3])
        : "r"(a0), "r"(a1), "r"(a2), "r"(a3), "r"(b0), "r"(b1));
}
__device__ __forceinline__ uint32_t swz128(uint32_t b) { return b ^ ((b >> 3) & 0x70); }
__device__ __forceinline__ void ldsm4(uint32_t& r0, uint32_t& r1, uint32_t& r2, uint32_t& r3,
                                      uint32_t a) {
    asm volatile("ldmatrix.sync.aligned.m8n8.x4.shared.b16 {%0,%1,%2,%3}, [%4];"
                 : "=r"(r0), "=r"(r1), "=r"(r2), "=r"(r3) : "r"(a));
}
__device__ __forceinline__ void mbar_init(uint32_t a, uint32_t cnt) {
    asm volatile("mbarrier.init.shared.b64 [%0], %1;" :: "r"(a), "r"(cnt) : "memory");
}
__device__ __forceinline__ void mbar_expect(uint32_t a, uint32_t tx) {
    asm volatile("mbarrier.arrive.expect_tx.shared.b64 _, [%0], %1;" :: "r"(a), "r"(tx) : "memory");
}
__device__ __forceinline__ void mbar_wait(uint32_t a, uint32_t ph) {
    asm volatile(
        "{\n\t.reg .pred P1;\n\t"
        "WL%=:\n\t"
        "mbarrier.try_wait.parity.acquire.cta.shared::cta.b64 P1, [%0], %1, 0x989680;\n\t"
        "@P1 bra WD%=;\n\t"
        "bra WL%=;\n\t"
        "WD%=:\n\t}"
        :: "r"(a), "r"(ph) : "memory");
}
__device__ __forceinline__ void tma2d(uint32_t dst, const void* map, int x, int y, uint32_t mbar) {
    asm volatile(
        "cp.async.bulk.tensor.2d.shared::cta.global.tile.mbarrier::complete_tx::bytes "
        "[%0], [%1, {%2, %3}], [%4];"
        :: "r"(dst), "l"(map), "r"(x), "r"(y), "r"(mbar) : "memory");
}

// ---------------- merged weight round+transpose: dst[n][k] = fp16(src[k][n]) -
// 768 blocks: [0,192) qkv, [192,256) proj, [256,512) w1, [512,768) w2
__global__ void k_wt_all(const float* __restrict__ qkv_w, const float* __restrict__ proj_w,
                         const float* __restrict__ w1, const float* __restrict__ w2,
                         __half* __restrict__ dst) {
    __shared__ float t[32][33];
    int bid = blockIdx.x;
    const float* src; __half* d; int K, N, rel;
    if (bid < 192)      { src = qkv_w;  d = dst + WOFF_QKV;  K = 256;  N = 768;  rel = bid; }
    else if (bid < 256) { src = proj_w; d = dst + WOFF_PROJ; K = 256;  N = 256;  rel = bid - 192; }
    else if (bid < 512) { src = w1;     d = dst + WOFF_W1;   K = 256;  N = 1024; rel = bid - 256; }
    else                { src = w2;     d = dst + WOFF_W2;   K = 1024; N = 256;  rel = bid - 512; }
    int nkb = K >> 5;
    int k0 = (rel % nkb) * 32, n0 = (rel / nkb) * 32;
    int tx = threadIdx.x, ty = threadIdx.y;
    #pragma unroll
    for (int j = ty; j < 32; j += 8)
        t[j][tx] = src[(size_t)(k0 + j) * N + n0 + tx];
    __syncthreads();
    #pragma unroll
    for (int j = ty; j < 32; j += 8)
        d[(size_t)(n0 + j) * K + k0 + tx] = __float2half(t[tx][j]);
}

// ---------------- fused transpose + LN1, output fp16 in WINDOW order ---------
__global__ __launch_bounds__(256)
void k_tr_ln(const float* __restrict__ x, const float* __restrict__ gam,
             const float* __restrict__ bet) {
    __shared__ float tile[256][33];
    int b = blockIdx.y, hw0 = blockIdx.x * 32;
    int tid = threadIdx.x;
    int tx = tid & 31, ty = tid >> 5;
    for (int c = ty; c < 256; c += 8)
        tile[c][tx] = x[((size_t)(b * 256 + c)) * HW_ + hw0 + tx];
    __syncthreads();

    __half* winout = (__half*)g_bufA;
    int lane = tx;
    #pragma unroll
    for (int q = 0; q < 4; q++) {
        int tk = ty * 4 + q;
        float s = 0.f, ss = 0.f;
        #pragma unroll
        for (int ci = 0; ci < 8; ci++) {
            float v = tile[lane + ci * 32][tk];
            s += v; ss += v * v;
        }
        #pragma unroll
        for (int o = 16; o; o >>= 1) {
            s  += __shfl_xor_sync(0xffffffffu, s, o);
            ss += __shfl_xor_sync(0xffffffffu, ss, o);
        }
        float mean = s * (1.0f / C_);
        float var  = ss * (1.0f / C_) - mean * mean;
        float rstd = rsqrtf(var + 1e-5f);

        int hw = hw0 + tk;
        int t  = b * HW_ + hw;
        int h  = hw / W_, w = hw - h * W_;
        int hs = (h >= 3) ? h - 3 : h + 53;
        int ws = (w >= 3) ? w - 3 : w + 53;
        int m  = (b * 64 + (hs / 7) * 8 + (ws / 7)) * 49 + (hs % 7) * 7 + (ws % 7);

        for (int c = lane; c < 256; c += 32) {
            float v = tile[c][tk];
            g_short[(size_t)t * C_ + c] = v;
            winout[(size_t)m * C_ + c] = __float2half((v - mean) * rstd * gam[c] + bet[c]);
        }
    }
}

// ---------------- LN2 (f32 in, fp16 out) -------------------------------------
__global__ void k_ln(const float* __restrict__ x, const float* __restrict__ g,
                     const float* __restrict__ bb, __half* __restrict__ out) {
    int token = blockIdx.x;
    int tid = threadIdx.x;
    float4 v = ((const float4*)(x + (size_t)token * C_))[tid];
    float s  = v.x + v.y + v.z + v.w;
    float ss = v.x * v.x + v.y * v.y + v.z * v.z + v.w * v.w;
    #pragma unroll
    for (int o = 16; o; o >>= 1) {
        s  += __shfl_xor_sync(0xffffffffu, s, o);
        ss += __shfl_xor_sync(0xffffffffu, ss, o);
    }
    __shared__ float sh[4];
    if ((tid & 31) == 0) { sh[tid >> 5] = s; sh[2 + (tid >> 5)] = ss; }
    __syncthreads();
    s = sh[0] + sh[1]; ss = sh[2] + sh[3];
    float mean = s * (1.0f / C_);
    float var  = ss * (1.0f / C_) - mean * mean;
    float rstd = rsqrtf(var + 1e-5f);
    float4 gg = ((const float4*)g)[tid];
    float4 bv = ((const float4*)bb)[tid];
    __half2 h0 = __floats2half2_rn((v.x - mean) * rstd * gg.x + bv.x,
                                   (v.y - mean) * rstd * gg.y + bv.y);
    __half2 h1 = __floats2half2_rn((v.z - mean) * rstd * gg.z + bv.z,
                                   (v.w - mean) * rstd * gg.w + bv.w);
    __half2* op = (__half2*)(out + (size_t)token * C_);
    op[2 * tid]     = h0;
    op[2 * tid + 1] = h1;
}

// ---------------- TMA-fed fp16 GEMM 128x128, BK=64, 3-stage pipeline ---------
// Grid: blockIdx.x = N tile (fastest -> L2 reuse of A), blockIdx.y = M tile.
// EPI: 0 bias->half | 1 bias+GELU->half | 2 bias+scatter+extra->f32
//      3 bias+extra -> f32 TRANSPOSED write to (B,C,HW) output via smem staging
#define NS 3
#define STG_BYTES 16384                    // 128 rows * 128B per side per stage
#define GEMM_SMEM (NS * 2 * STG_BYTES + 64)

template<int EPI>
__global__ __launch_bounds__(256, 2)
void k_gemm(const __grid_constant__ CUtensorMap dA,
            const __grid_constant__ CUtensorMap dB,
            const float* __restrict__ bias, const float* __restrict__ extra,
            void* __restrict__ Cout, int N, int K)
{
    extern __shared__ __align__(1024) char smem[];
    uint32_t aBase = (uint32_t)__cvta_generic_to_shared(smem);
    uint32_t bBase = aBase + NS * STG_BYTES;
    uint32_t mBase = bBase + NS * STG_BYTES;

    int tid = threadIdx.x;
    int lane = tid & 31, wid = tid >> 5;
    int warpM = wid >> 1, warpN = wid & 1;
    int qrow = lane >> 2, qcol = lane & 3;
    int bm = blockIdx.y * 128, bn = blockIdx.x * 128;
    int niters = K >> 6;

    if (tid == 0) {
        #pragma unroll
        for (int s = 0; s < NS; s++) mbar_init(mBase + 8 * s, 1);
    }
    __syncthreads();

    if (tid == 0) {
        #pragma unroll
        for (int j = 0; j < NS - 1; j++) {
            mbar_expect(mBase + 8 * j, 2 * STG_BYTES);
            tma2d(aBase + j * STG_BYTES, &dA, j * 64, bm, mBase + 8 * j);
            tma2d(bBase + j * STG_BYTES, &dB, j * 64, bn, mBase + 8 * j);
        }
    }

    // per-thread ldmatrix base addresses (stage 0, k-step 0); byte-col in {0,16}
    uint32_t aAddr[2], bAddr[4];
    {
        int lr = lane & 7;
        #pragma unroll
        for (int mt = 0; mt < 2; mt++) {
            int row = warpM * 32 + mt * 16 + lr + ((lane & 8) ? 8 : 0);
            int c4  = (lane & 16) ? 16 : 0;
            aAddr[mt] = aBase + swz128((uint32_t)(row * 128 + c4));
        }
        int mq = lane >> 3;
        #pragma unroll
        for (int np = 0; np < 4; np++) {
            int row = warpN * 64 + (np * 2 + (mq >> 1)) * 8 + lr;
            int c4  = (mq & 1) * 16;
            bAddr[np] = bBase + swz128((uint32_t)(row * 128 + c4));
        }
    }

    float acc[2][8][4];
    #pragma unroll
    for (int mt = 0; mt < 2; mt++)
        #pragma unroll
        for (int nt = 0; nt < 8; nt++)
            #pragma unroll
            for (int e = 0; e < 4; e++) acc[mt][nt][e] = 0.f;

    int scur = 0, pcur = 0;
    int spre = NS - 1;
    for (int i = 0; i < niters; i++) {
        mbar_wait(mBase + 8 * scur, pcur);
        uint32_t so = (uint32_t)scur * STG_BYTES;

        #pragma unroll
        for (int ks = 0; ks < 4; ks++) {
            uint32_t kx = (uint32_t)(ks * 32);  // XOR-applied, swizzle-safe
            uint32_t af[2][4], bf[8][2];
            #pragma unroll
            for (int mt = 0; mt < 2; mt++)
                ldsm4(af[mt][0], af[mt][1], af[mt][2], af[mt][3],
                      (aAddr[mt] + so) ^ kx);
            #pragma unroll
            for (int np = 0; np < 4; np++)
                ldsm4(bf[2 * np][0], bf[2 * np][1], bf[2 * np + 1][0], bf[2 * np + 1][1],
                      (bAddr[np] + so) ^ kx);
            #pragma unroll
            for (int mt = 0; mt < 2; mt++)
                #pragma unroll
                for (int nt = 0; nt < 8; nt++)
                    mma_f16(acc[mt][nt], af[mt][0], af[mt][1], af[mt][2], af[mt][3],
                            bf[nt][0], bf[nt][1]);
        }
        __syncthreads();

        int j = i + NS - 1;
        if (j < niters && tid == 0) {
            mbar_expect(mBase + 8 * spre, 2 * STG_BYTES);
            tma2d(aBase + spre * STG_BYTES, &dA, j * 64, bm, mBase + 8 * spre);
            tma2d(bBase + spre * STG_BYTES, &dB, j * 64, bn, mBase + 8 * spre);
        }
        if (++scur == NS) { scur = 0; pcur ^= 1; }
        if (++spre == NS) spre = 0;
    }

    // -------- epilogue --------
    if (EPI == 3) {
        // bias + extra, then transposed (B,C,HW) write through smem staging
        float* St = (float*)smem;                      // [col][row], stride 130
        #pragma unroll
        for (int mt = 0; mt < 2; mt++) {
            #pragma unroll
            for (int half = 0; half < 2; half++) {
                int rl = warpM * 32 + mt * 16 + qrow + half * 8;
                int gr = bm + rl;
                #pragma unroll
                for (int nt = 0; nt < 8; nt++) {
                    int cl  = warpN * 64 + nt * 8 + 2 * qcol;
                    int col = bn + cl;
                    const float* ep = extra + (size_t)gr * N + col;
                    float v0 = acc[mt][nt][2 * half + 0] + bias[col]     + ep[0];
                    float v1 = acc[mt][nt][2 * half + 1] + bias[col + 1] + ep[1];
                    St[cl * 130 + rl]       = v0;
                    St[(cl + 1) * 130 + rl] = v1;
                }
            }
        }
        __syncthreads();
        int bseg[4], hwseg[4];
        #pragma unroll
        for (int seg = 0; seg < 4; seg++) {
            int t = bm + seg * 32 + lane;
            bseg[seg]  = t / HW_;
            hwseg[seg] = t - bseg[seg] * HW_;
        }
        float* outp = (float*)Cout;
        #pragma unroll
        for (int cc = 0; cc < 16; cc++) {
            int cl = wid * 16 + cc;
            int gc = bn + cl;
            #pragma unroll
            for (int seg = 0; seg < 4; seg++)
                outp[((size_t)(bseg[seg] * 256 + gc)) * HW_ + hwseg[seg]] =
                    St[cl * 130 + seg * 32 + lane];
        }
    } else {
        #pragma unroll
        for (int mt = 0; mt < 2; mt++) {
            #pragma unroll
            for (int half = 0; half < 2; half++) {
                int gr = bm + warpM * 32 + mt * 16 + qrow + half * 8;
                size_t orow = (EPI == 2) ? (size_t)win_token(gr) : (size_t)gr;
                #pragma unroll
                for (int nt = 0; nt < 8; nt++) {
                    int col = bn + warpN * 64 + nt * 8 + 2 * qcol;
                    float v0 = acc[mt][nt][2 * half + 0] + bias[col];
                    float v1 = acc[mt][nt][2 * half + 1] + bias[col + 1];
                    if (EPI == 1) {
                        v0 = 0.5f * v0 * (1.0f + erff(v0 * 0.7071067811865475f));
                        v1 = 0.5f * v1 * (1.0f + erff(v1 * 0.7071067811865475f));
                    }
                    if (EPI == 0 || EPI == 1) {
                        *(__half2*)((__half*)Cout + orow * N + col) = __floats2half2_rn(v0, v1);
                    } else {
                        const float* ep = extra + orow * N + col;
                        v0 += ep[0];
                        v1 += ep[1];
                        *(float2*)((float*)Cout + orow * N + col) = make_float2(v0, v1);
                    }
                }
            }
        }
    }
}

// ---------------- windowed attention (wavefront-minimized, aligned smem) -----
// Per (window, head) block, 128 threads / 4 warps.
// QK: lane holds K rows lane AND lane+32 in registers (fp16 smem, uint4 loads);
//     q rows broadcast-read ONCE per n as float4.
// softmax + SV: S rows read as float4 (stride 52, 48 vectorized + 1 scalar).
// All smem arrays explicitly 16B-aligned (static __shared__ only guarantees
// element-type alignment -> round-14 "misaligned address").
__global__ void __launch_bounds__(128)
k_attn(const __half* __restrict__ qkv, __half* __restrict__ out) {
    __shared__ __align__(16) float  qs[49][36];    // rows 144B, float4 reads
    __shared__ __align__(16) __half ks[49][40];    // rows 80B, uint4 reads
    __shared__ __align__(16) float  vs[49][34];    // rows 136B, float2 access
    __shared__ __align__(16) float  S [49][52];    // rows 208B, float4 reads
    int win  = blockIdx.x >> 3;
    int head = blockIdx.x & 7;
    int tid  = threadIdx.x;
    int lane = tid & 31;
    int wj   = tid >> 5;
    int base = win * 49;

    for (int idx = tid; idx < 49 * 16; idx += 128) {
        int n = idx >> 4, d2 = idx & 15;
        const __half2* p = (const __half2*)(qkv + (size_t)(base + n) * 768 + head * 32) + d2;
        __half2 qh = p[0];
        __half2 kh = p[128];
        __half2 vh = p[256];
        *(float2*)&qs[n][2 * d2]  = __half22float2(qh);
        *(__half2*)&ks[n][2 * d2] = kh;
        *(float2*)&vs[n][2 * d2]  = __half22float2(vh);
    }
    __syncthreads();

    const float scale = 0.1767766952966369f;   // 1/sqrt(32)
    bool hasB = (lane + 32 < 49);
    int mB = hasB ? lane + 32 : 48;

    // both K rows into registers (4 uint4 loads per row)
    float kregA[32], kregB[32];
    #pragma unroll
    for (int j = 0; j < 4; j++) {
        uint4 a = *(const uint4*)&ks[lane][j * 8];
        uint4 b = *(const uint4*)&ks[mB][j * 8];
        const __half2* ah = (const __half2*)&a;
        const __half2* bh = (const __half2*)&b;
        #pragma unroll
        for (int t = 0; t < 4; t++) {
            float2 fa = __half22float2(ah[t]);
            float2 fb = __half22float2(bh[t]);
            kregA[j * 8 + 2 * t]     = fa.x;
            kregA[j * 8 + 2 * t + 1] = fa.y;
            kregB[j * 8 + 2 * t]     = fb.x;
            kregB[j * 8 + 2 * t + 1] = fb.y;
        }
    }

    for (int n = wj; n < 49; n += 4) {
        float accA = 0.f, accB = 0.f;
        #pragma unroll
        for (int dq = 0; dq < 8; dq++) {
            float4 q4 = *(const float4*)&qs[n][dq * 4];   // broadcast, once per n
            accA += q4.x * kregA[4 * dq + 0];
            accA += q4.y * kregA[4 * dq + 1];
            accA += q4.z * kregA[4 * dq + 2];
            accA += q4.w * kregA[4 * dq + 3];
            accB += q4.x * kregB[4 * dq + 0];
            accB += q4.y * kregB[4 * dq + 1];
            accB += q4.z * kregB[4 * dq + 2];
            accB += q4.w * kregB[4 * dq + 3];
        }
        S[n][lane] = accA * scale;
        if (hasB) S[n][32 + lane] = accB * scale;
    }
    __syncthreads();

    // softmax rows (threads 0..48), float4 over 48 + scalar element 48
    if (tid < 49) {
        float* row = S[tid];
        float mx = row[48];
        #pragma unroll
        for (int m4 = 0; m4 < 12; m4++) {
            float4 v = *(const float4*)&row[m4 * 4];
            mx = fmaxf(mx, fmaxf(fmaxf(v.x, v.y), fmaxf(v.z, v.w)));
        }
        float sum = 0.f;
        #pragma unroll
        for (int m4 = 0; m4 < 12; m4++) {
            float4 v = *(const float4*)&row[m4 * 4];
            v.x = __expf(v.x - mx); v.y = __expf(v.y - mx);
            v.z = __expf(v.z - mx); v.w = __expf(v.w - mx);
            sum += v.x + v.y + v.z + v.w;
            *(float4*)&row[m4 * 4] = v;
        }
        float e48 = __expf(row[48] - mx);
        sum += e48;
        float inv = 1.0f / sum;
        #pragma unroll
        for (int m4 = 0; m4 < 12; m4++) {
            float4 v = *(const float4*)&row[m4 * 4];
            v.x *= inv; v.y *= inv; v.z *= inv; v.w *= inv;
            *(float4*)&row[m4 * 4] = v;
        }
        row[48] = e48 * inv;
    }
    __syncthreads();

    // S @ V: lane = dim d, V column in registers, S rows via float4 broadcast
    float vreg[49];
    #pragma unroll
    for (int m = 0; m < 49; m++) vreg[m] = vs[m][lane];
    for (int n = wj; n < 49; n += 4) {
        float acc = 0.f;
        #pragma unroll
        for (int m4 = 0; m4 < 12; m4++) {
            float4 s4 = *(const float4*)&S[n][m4 * 4];
            acc += s4.x * vreg[4 * m4 + 0];
            acc += s4.y * vreg[4 * m4 + 1];
            acc += s4.z * vreg[4 * m4 + 2];
            acc += s4.w * vreg[4 * m4 + 3];
        }
        acc += S[n][48] * vreg[48];
        out[(size_t)(base + n) * C_ + head * 32 + lane] = __float2half(acc);
    }
}

// ---------------- host: tensor-map encode ------------------------------------
typedef CUresult (*tmap_fn)(CUtensorMap*, CUtensorMapDataType, cuuint32_t, void*,
                            const cuuint64_t*, const cuuint64_t*, const cuuint32_t*,
                            const cuuint32_t*, CUtensorMapInterleave, CUtensorMapSwizzle,
                            CUtensorMapL2promotion, CUtensorMapFloatOOBfill);

static tmap_fn get_enc() {
    void* fn = nullptr;
    cudaDriverEntryPointQueryResult qr;
#if CUDART_VERSION >= 12050
    cudaGetDriverEntryPointByVersion("cuTensorMapEncodeTiled", &fn, 12000,
                                     cudaEnableDefault, &qr);
#else
    cudaGetDriverEntryPoint("cuTensorMapEncodeTiled", &fn, cudaEnableDefault, &qr);
#endif
    return (tmap_fn)fn;
}

static void enc2d(tmap_fn f, CUtensorMap* m, void* ptr, uint64_t innerK, uint64_t outerRows) {
    cuuint64_t dims[2]    = {innerK, outerRows};
    cuuint64_t strides[1] = {innerK * 2};
    cuuint32_t box[2]     = {64, 128};
    cuuint32_t el[2]      = {1, 1};
    f(m, CU_TENSOR_MAP_DATA_TYPE_FLOAT16, 2, ptr, dims, strides, box, el,
      CU_TENSOR_MAP_INTERLEAVE_NONE, CU_TENSOR_MAP_SWIZZLE_128B,
      CU_TENSOR_MAP_L2_PROMOTION_L2_128B, CU_TENSOR_MAP_FLOAT_OOB_FILL_NONE);
}

// ---------------- launch ----------------------------------------------------
extern "C" void kernel_launch(void* const* d_in, const int* in_sizes, int n_in,
                              void* d_out, int out_size) {
    const float* x      = (const float*)d_in[0];
    const float* n1_g   = (const float*)d_in[1];
    const float* n1_b   = (const float*)d_in[2];
    const float* qkv_w  = (const float*)d_in[3];
    const float* qkv_b  = (const float*)d_in[4];
    const float* proj_w = (const float*)d_in[5];
    const float* proj_b = (const float*)d_in[6];
    const float* n2_g   = (const float*)d_in[7];
    const float* n2_b   = (const float*)d_in[8];
    const float* mlp_w1 = (const float*)d_in[9];
    const float* mlp_b1 = (const float*)d_in[10];
    const float* mlp_w2 = (const float*)d_in[11];
    const float* mlp_b2 = (const float*)d_in[12];
    float* out = (float*)d_out;

    float *p_short, *p_bufA, *p_qkv, *p_xres, *p_hid, *p_wts_f;
    cudaGetSymbolAddress((void**)&p_short, g_short);
    cudaGetSymbolAddress((void**)&p_bufA,  g_bufA);
    cudaGetSymbolAddress((void**)&p_qkv,   g_qkv);
    cudaGetSymbolAddress((void**)&p_xres,  g_xres);
    cudaGetSymbolAddress((void**)&p_hid,   g_hid);
    cudaGetSymbolAddress((void**)&p_wts_f, g_wts);
    __half* p_wts = (__half*)p_wts_f;

    tmap_fn enc = get_enc();
    CUtensorMap dA_bufA, dA_ln2, dA_hid, dB_qkv, dB_proj, dB_w1, dB_w2;
    enc2d(enc, &dA_bufA, p_bufA,            256,  TOK);   // LN1win / attn-out (half)
    enc2d(enc, &dA_ln2,  p_qkv,             256,  TOK);   // LN2 out (half)
    enc2d(enc, &dA_hid,  p_hid,             1024, TOK);   // hidden (half)
    enc2d(enc, &dB_qkv,  p_wts + WOFF_QKV,  256,  768);
    enc2d(enc, &dB_proj, p_wts + WOFF_PROJ, 256,  256);
    enc2d(enc, &dB_w1,   p_wts + WOFF_W1,   256,  1024);
    enc2d(enc, &dB_w2,   p_wts + WOFF_W2,   1024, 256);

    cudaFuncSetAttribute(k_gemm<0>, cudaFuncAttributeMaxDynamicSharedMemorySize, GEMM_SMEM);
    cudaFuncSetAttribute(k_gemm<1>, cudaFuncAttributeMaxDynamicSharedMemorySize, GEMM_SMEM);
    cudaFuncSetAttribute(k_gemm<2>, cudaFuncAttributeMaxDynamicSharedMemorySize, GEMM_SMEM);
    cudaFuncSetAttribute(k_gemm<3>, cudaFuncAttributeMaxDynamicSharedMemorySize, GEMM_SMEM);

    dim3 tb(32, 8);
    // weight round + transpose into fp16 [N][K] (single merged launch)
    k_wt_all<<<768, tb>>>(qkv_w, proj_w, mlp_w1, mlp_w2, p_wts);

    // fused transpose + LN1 (shortcut f32 spatial; LN1 fp16 window order)
    k_tr_ln<<<dim3(98, 32), 256>>>(x, n1_g, n1_b);
    // qkv = winLN1 @ qkv_w^T + b  (fp16 out); bn fastest for A L2 reuse
    k_gemm<0><<<dim3(6, 784), 256, GEMM_SMEM>>>(dA_bufA, dB_qkv, qkv_b, nullptr, p_qkv, 768, 256);
    // windowed MHSA (fp16 io)
    k_attn<<<NWIN * NHEAD, 128>>>((const __half*)p_qkv, (__half*)p_bufA);
    // xres = shortcut + scatter(attn_o @ proj_w^T + b)   (f32 out)
    k_gemm<2><<<dim3(2, 784), 256, GEMM_SMEM>>>(dA_bufA, dB_proj, proj_b, p_short, p_xres, 256, 256);
    // LN2 (fp16 out into g_qkv scratch)
    k_ln<<<TOK, 64>>>(p_xres, n2_g, n2_b, (__half*)p_qkv);
    // hid = gelu(ln2 @ w1^T + b1)  (fp16 out)
    k_gemm<1><<<dim3(8, 784), 256, GEMM_SMEM>>>(dA_ln2, dB_w1, mlp_b1, nullptr, p_hid, 1024, 256);
    // final = xres + hid @ w2^T + b2, written DIRECTLY transposed to (B,C,HW) out
    k_gemm<3><<<dim3(2, 784), 256, GEMM_SMEM>>>(dA_hid, dB_w2, mlp_b2, p_xres, out, 256, 1024);
}

// round 16
// speedup vs baseline: 5.9368x; 1.1270x over previous
#include <cuda_runtime.h>
#include <cuda.h>
#include <cuda_fp16.h>
#include <math.h>
#include <stdint.h>

#define B_     32
#define C_     256
#define H_     56
#define W_     56
#define HW_    3136
#define TOK    100352          // B_*H_*W_
#define NWIN   2048
#define NHEAD  8
#define HID    1024

// ---------------- scratch (device globals; fp16 views overlay float arrays) --
__device__ float g_short[(size_t)TOK * C_];        // f32: shortcut (spatial order)
__device__ float g_bufA [(size_t)TOK * C_];        // half: LN1(win order) -> attn out
__device__ float g_qkv  [(size_t)TOK * 3 * C_];    // half: qkv -> ln2 out
__device__ float g_xres [(size_t)TOK * C_];        // f32: x after attn residual
__device__ float g_hid  [(size_t)TOK * HID];       // half: mlp hidden
__device__ float g_wts  [786432];                  // half: transposed weights [N][K]

#define WOFF_QKV  0
#define WOFF_PROJ 196608
#define WOFF_W1   262144
#define WOFF_W2   524288

// window-order row m -> spatial token (for proj scatter epilogue)
__device__ __forceinline__ int win_token(int m) {
    int win = m / 49;
    int n   = m - win * 49;
    int b   = win >> 6;
    int r   = win & 63;
    int i   = n / 7;
    int j   = n - i * 7;
    int h = (r >> 3) * 7 + i + 3; if (h >= H_) h -= H_;
    int w = (r & 7)  * 7 + j + 3; if (w >= W_) w -= W_;
    return (b * H_ + h) * W_ + w;
}

// ---------------- ptx helpers ------------------------------------------------
__device__ __forceinline__ void mma_f16(float (&d)[4],
                                        uint32_t a0, uint32_t a1, uint32_t a2, uint32_t a3,
                                        uint32_t b0, uint32_t b1) {
    asm volatile(
        "mma.sync.aligned.m16n8k16.row.col.f32.f16.f16.f32 "
        "{%0,%1,%2,%3}, {%4,%5,%6,%7}, {%8,%9}, {%0,%1,%2,%3};\n"
        : "+f"(d[0]), "+f"(d[1]), "+f"(d[2]), "+f"(d[3])
        : "r"(a0), "r"(a1), "r"(a2), "r"(a3), "r"(b0), "r"(b1));
}
__device__ __forceinline__ uint32_t swz128(uint32_t b) { return b ^ ((b >> 3) & 0x70); }
__device__ __forceinline__ void ldsm4(uint32_t& r0, uint32_t& r1, uint32_t& r2, uint32_t& r3,
                                      uint32_t a) {
    asm volatile("ldmatrix.sync.aligned.m8n8.x4.shared.b16 {%0,%1,%2,%3}, [%4];"
                 : "=r"(r0), "=r"(r1), "=r"(r2), "=r"(r3) : "r"(a));
}
__device__ __forceinline__ void mbar_init(uint32_t a, uint32_t cnt) {
    asm volatile("mbarrier.init.shared.b64 [%0], %1;" :: "r"(a), "r"(cnt) : "memory");
}
__device__ __forceinline__ void mbar_expect(uint32_t a, uint32_t tx) {
    asm volatile("mbarrier.arrive.expect_tx.shared.b64 _, [%0], %1;" :: "r"(a), "r"(tx) : "memory");
}
__device__ __forceinline__ void mbar_wait(uint32_t a, uint32_t ph) {
    asm volatile(
        "{\n\t.reg .pred P1;\n\t"
        "WL%=:\n\t"
        "mbarrier.try_wait.parity.acquire.cta.shared::cta.b64 P1, [%0], %1, 0x989680;\n\t"
        "@P1 bra WD%=;\n\t"
        "bra WL%=;\n\t"
        "WD%=:\n\t}"
        :: "r"(a), "r"(ph) : "memory");
}
__device__ __forceinline__ void tma2d(uint32_t dst, const void* map, int x, int y, uint32_t mbar) {
    asm volatile(
        "cp.async.bulk.tensor.2d.shared::cta.global.tile.mbarrier::complete_tx::bytes "
        "[%0], [%1, {%2, %3}], [%4];"
        :: "r"(dst), "l"(map), "r"(x), "r"(y), "r"(mbar) : "memory");
}

// ---------------- merged weight round+transpose: dst[n][k] = fp16(src[k][n]) -
// 768 blocks: [0,192) qkv, [192,256) proj, [256,512) w1, [512,768) w2
__global__ void k_wt_all(const float* __restrict__ qkv_w, const float* __restrict__ proj_w,
                         const float* __restrict__ w1, const float* __restrict__ w2,
                         __half* __restrict__ dst) {
    __shared__ float t[32][33];
    int bid = blockIdx.x;
    const float* src; __half* d; int K, N, rel;
    if (bid < 192)      { src = qkv_w;  d = dst + WOFF_QKV;  K = 256;  N = 768;  rel = bid; }
    else if (bid < 256) { src = proj_w; d = dst + WOFF_PROJ; K = 256;  N = 256;  rel = bid - 192; }
    else if (bid < 512) { src = w1;     d = dst + WOFF_W1;   K = 256;  N = 1024; rel = bid - 256; }
    else                { src = w2;     d = dst + WOFF_W2;   K = 1024; N = 256;  rel = bid - 512; }
    int nkb = K >> 5;
    int k0 = (rel % nkb) * 32, n0 = (rel / nkb) * 32;
    int tx = threadIdx.x, ty = threadIdx.y;
    #pragma unroll
    for (int j = ty; j < 32; j += 8)
        t[j][tx] = src[(size_t)(k0 + j) * N + n0 + tx];
    __syncthreads();
    #pragma unroll
    for (int j = ty; j < 32; j += 8)
        d[(size_t)(n0 + j) * K + k0 + tx] = __float2half(t[tx][j]);
}

// ---------------- fused transpose + LN1, output fp16 in WINDOW order ---------
__global__ __launch_bounds__(256)
void k_tr_ln(const float* __restrict__ x, const float* __restrict__ gam,
             const float* __restrict__ bet) {
    __shared__ float tile[256][33];
    int b = blockIdx.y, hw0 = blockIdx.x * 32;
    int tid = threadIdx.x;
    int tx = tid & 31, ty = tid >> 5;
    for (int c = ty; c < 256; c += 8)
        tile[c][tx] = x[((size_t)(b * 256 + c)) * HW_ + hw0 + tx];
    __syncthreads();

    __half* winout = (__half*)g_bufA;
    int lane = tx;
    #pragma unroll
    for (int q = 0; q < 4; q++) {
        int tk = ty * 4 + q;
        float s = 0.f, ss = 0.f;
        #pragma unroll
        for (int ci = 0; ci < 8; ci++) {
            float v = tile[lane + ci * 32][tk];
            s += v; ss += v * v;
        }
        #pragma unroll
        for (int o = 16; o; o >>= 1) {
            s  += __shfl_xor_sync(0xffffffffu, s, o);
            ss += __shfl_xor_sync(0xffffffffu, ss, o);
        }
        float mean = s * (1.0f / C_);
        float var  = ss * (1.0f / C_) - mean * mean;
        float rstd = rsqrtf(var + 1e-5f);

        int hw = hw0 + tk;
        int t  = b * HW_ + hw;
        int h  = hw / W_, w = hw - h * W_;
        int hs = (h >= 3) ? h - 3 : h + 53;
        int ws = (w >= 3) ? w - 3 : w + 53;
        int m  = (b * 64 + (hs / 7) * 8 + (ws / 7)) * 49 + (hs % 7) * 7 + (ws % 7);

        for (int c = lane; c < 256; c += 32) {
            float v = tile[c][tk];
            g_short[(size_t)t * C_ + c] = v;
            winout[(size_t)m * C_ + c] = __float2half((v - mean) * rstd * gam[c] + bet[c]);
        }
    }
}

// ---------------- LN2 (f32 in, fp16 out) -------------------------------------
__global__ void k_ln(const float* __restrict__ x, const float* __restrict__ g,
                     const float* __restrict__ bb, __half* __restrict__ out) {
    int token = blockIdx.x;
    int tid = threadIdx.x;
    float4 v = ((const float4*)(x + (size_t)token * C_))[tid];
    float s  = v.x + v.y + v.z + v.w;
    float ss = v.x * v.x + v.y * v.y + v.z * v.z + v.w * v.w;
    #pragma unroll
    for (int o = 16; o; o >>= 1) {
        s  += __shfl_xor_sync(0xffffffffu, s, o);
        ss += __shfl_xor_sync(0xffffffffu, ss, o);
    }
    __shared__ float sh[4];
    if ((tid & 31) == 0) { sh[tid >> 5] = s; sh[2 + (tid >> 5)] = ss; }
    __syncthreads();
    s = sh[0] + sh[1]; ss = sh[2] + sh[3];
    float mean = s * (1.0f / C_);
    float var  = ss * (1.0f / C_) - mean * mean;
    float rstd = rsqrtf(var + 1e-5f);
    float4 gg = ((const float4*)g)[tid];
    float4 bv = ((const float4*)bb)[tid];
    __half2 h0 = __floats2half2_rn((v.x - mean) * rstd * gg.x + bv.x,
                                   (v.y - mean) * rstd * gg.y + bv.y);
    __half2 h1 = __floats2half2_rn((v.z - mean) * rstd * gg.z + bv.z,
                                   (v.w - mean) * rstd * gg.w + bv.w);
    __half2* op = (__half2*)(out + (size_t)token * C_);
    op[2 * tid]     = h0;
    op[2 * tid + 1] = h1;
}

// ---------------- TMA-fed fp16 GEMM 128x128, BK=64, 3-stage pipeline ---------
// Grid: blockIdx.x = N tile (fastest -> L2 reuse of A), blockIdx.y = M tile.
// EPI: 0 bias->half | 1 bias+GELU->half | 2 bias+scatter+extra->f32
//      3 bias+extra -> f32 TRANSPOSED write to (B,C,HW) output via smem staging
#define NS 3
#define STG_BYTES 16384                    // 128 rows * 128B per side per stage
#define GEMM_SMEM (NS * 2 * STG_BYTES + 64)

template<int EPI>
__global__ __launch_bounds__(256, 2)
void k_gemm(const __grid_constant__ CUtensorMap dA,
            const __grid_constant__ CUtensorMap dB,
            const float* __restrict__ bias, const float* __restrict__ extra,
            void* __restrict__ Cout, int N, int K)
{
    extern __shared__ __align__(1024) char smem[];
    uint32_t aBase = (uint32_t)__cvta_generic_to_shared(smem);
    uint32_t bBase = aBase + NS * STG_BYTES;
    uint32_t mBase = bBase + NS * STG_BYTES;

    int tid = threadIdx.x;
    int lane = tid & 31, wid = tid >> 5;
    int warpM = wid >> 1, warpN = wid & 1;
    int qrow = lane >> 2, qcol = lane & 3;
    int bm = blockIdx.y * 128, bn = blockIdx.x * 128;
    int niters = K >> 6;

    if (tid == 0) {
        #pragma unroll
        for (int s = 0; s < NS; s++) mbar_init(mBase + 8 * s, 1);
    }
    __syncthreads();

    if (tid == 0) {
        #pragma unroll
        for (int j = 0; j < NS - 1; j++) {
            mbar_expect(mBase + 8 * j, 2 * STG_BYTES);
            tma2d(aBase + j * STG_BYTES, &dA, j * 64, bm, mBase + 8 * j);
            tma2d(bBase + j * STG_BYTES, &dB, j * 64, bn, mBase + 8 * j);
        }
    }

    // per-thread ldmatrix base addresses (stage 0, k-step 0); byte-col in {0,16}
    uint32_t aAddr[2], bAddr[4];
    {
        int lr = lane & 7;
        #pragma unroll
        for (int mt = 0; mt < 2; mt++) {
            int row = warpM * 32 + mt * 16 + lr + ((lane & 8) ? 8 : 0);
            int c4  = (lane & 16) ? 16 : 0;
            aAddr[mt] = aBase + swz128((uint32_t)(row * 128 + c4));
        }
        int mq = lane >> 3;
        #pragma unroll
        for (int np = 0; np < 4; np++) {
            int row = warpN * 64 + (np * 2 + (mq >> 1)) * 8 + lr;
            int c4  = (mq & 1) * 16;
            bAddr[np] = bBase + swz128((uint32_t)(row * 128 + c4));
        }
    }

    float acc[2][8][4];
    #pragma unroll
    for (int mt = 0; mt < 2; mt++)
        #pragma unroll
        for (int nt = 0; nt < 8; nt++)
            #pragma unroll
            for (int e = 0; e < 4; e++) acc[mt][nt][e] = 0.f;

    int scur = 0, pcur = 0;
    int spre = NS - 1;
    for (int i = 0; i < niters; i++) {
        mbar_wait(mBase + 8 * scur, pcur);
        uint32_t so = (uint32_t)scur * STG_BYTES;

        #pragma unroll
        for (int ks = 0; ks < 4; ks++) {
            uint32_t kx = (uint32_t)(ks * 32);  // XOR-applied, swizzle-safe
            uint32_t af[2][4], bf[8][2];
            #pragma unroll
            for (int mt = 0; mt < 2; mt++)
                ldsm4(af[mt][0], af[mt][1], af[mt][2], af[mt][3],
                      (aAddr[mt] + so) ^ kx);
            #pragma unroll
            for (int np = 0; np < 4; np++)
                ldsm4(bf[2 * np][0], bf[2 * np][1], bf[2 * np + 1][0], bf[2 * np + 1][1],
                      (bAddr[np] + so) ^ kx);
            #pragma unroll
            for (int mt = 0; mt < 2; mt++)
                #pragma unroll
                for (int nt = 0; nt < 8; nt++)
                    mma_f16(acc[mt][nt], af[mt][0], af[mt][1], af[mt][2], af[mt][3],
                            bf[nt][0], bf[nt][1]);
        }
        __syncthreads();

        int j = i + NS - 1;
        if (j < niters && tid == 0) {
            mbar_expect(mBase + 8 * spre, 2 * STG_BYTES);
            tma2d(aBase + spre * STG_BYTES, &dA, j * 64, bm, mBase + 8 * spre);
            tma2d(bBase + spre * STG_BYTES, &dB, j * 64, bn, mBase + 8 * spre);
        }
        if (++scur == NS) { scur = 0; pcur ^= 1; }
        if (++spre == NS) spre = 0;
    }

    // -------- epilogue --------
    if (EPI == 3) {
        // bias + extra, then transposed (B,C,HW) write through smem staging
        float* St = (float*)smem;                      // [col][row], stride 130
        #pragma unroll
        for (int mt = 0; mt < 2; mt++) {
            #pragma unroll
            for (int half = 0; half < 2; half++) {
                int rl = warpM * 32 + mt * 16 + qrow + half * 8;
                int gr = bm + rl;
                #pragma unroll
                for (int nt = 0; nt < 8; nt++) {
                    int cl  = warpN * 64 + nt * 8 + 2 * qcol;
                    int col = bn + cl;
                    const float* ep = extra + (size_t)gr * N + col;
                    float v0 = acc[mt][nt][2 * half + 0] + bias[col]     + ep[0];
                    float v1 = acc[mt][nt][2 * half + 1] + bias[col + 1] + ep[1];
                    St[cl * 130 + rl]       = v0;
                    St[(cl + 1) * 130 + rl] = v1;
                }
            }
        }
        __syncthreads();
        int bseg[4], hwseg[4];
        #pragma unroll
        for (int seg = 0; seg < 4; seg++) {
            int t = bm + seg * 32 + lane;
            bseg[seg]  = t / HW_;
            hwseg[seg] = t - bseg[seg] * HW_;
        }
        float* outp = (float*)Cout;
        #pragma unroll
        for (int cc = 0; cc < 16; cc++) {
            int cl = wid * 16 + cc;
            int gc = bn + cl;
            #pragma unroll
            for (int seg = 0; seg < 4; seg++)
                outp[((size_t)(bseg[seg] * 256 + gc)) * HW_ + hwseg[seg]] =
                    St[cl * 130 + seg * 32 + lane];
        }
    } else {
        #pragma unroll
        for (int mt = 0; mt < 2; mt++) {
            #pragma unroll
            for (int half = 0; half < 2; half++) {
                int gr = bm + warpM * 32 + mt * 16 + qrow + half * 8;
                size_t orow = (EPI == 2) ? (size_t)win_token(gr) : (size_t)gr;
                #pragma unroll
                for (int nt = 0; nt < 8; nt++) {
                    int col = bn + warpN * 64 + nt * 8 + 2 * qcol;
                    float v0 = acc[mt][nt][2 * half + 0] + bias[col];
                    float v1 = acc[mt][nt][2 * half + 1] + bias[col + 1];
                    if (EPI == 1) {
                        v0 = 0.5f * v0 * (1.0f + erff(v0 * 0.7071067811865475f));
                        v1 = 0.5f * v1 * (1.0f + erff(v1 * 0.7071067811865475f));
                    }
                    if (EPI == 0 || EPI == 1) {
                        *(__half2*)((__half*)Cout + orow * N + col) = __floats2half2_rn(v0, v1);
                    } else {
                        const float* ep = extra + orow * N + col;
                        v0 += ep[0];
                        v1 += ep[1];
                        *(float2*)((float*)Cout + orow * N + col) = make_float2(v0, v1);
                    }
                }
            }
        }
    }
}

// ---------------- windowed attention via mma (tensor-core path) --------------
// One block per (window, head), 128 threads = 4 warps; warp w owns query rows
// 16w..16w+15 (padded 49->64). S = QK^T by mma (SW128 smem, proven GEMM frag
// maps), softmax in accumulator registers (mask keys>=49, quad-shfl max/sum),
// P stored fp16, O = P*V^T by mma (V staged transposed [d][key]).
__global__ void __launch_bounds__(128)
k_attn(const __half* __restrict__ qkv, __half* __restrict__ out) {
    __shared__ __align__(128) __half qs[64 * 64];
    __shared__ __align__(128) __half ks[64 * 64];
    __shared__ __align__(128) __half vt[32 * 64];   // [d][key]
    __shared__ __align__(128) __half P [64 * 64];   // [query][key]
    int win  = blockIdx.x >> 3;
    int head = blockIdx.x & 7;
    int tid  = threadIdx.x;
    int lane = tid & 31;
    int w    = tid >> 5;
    int base = win * 49;

    uint32_t qsB = (uint32_t)__cvta_generic_to_shared(qs);
    uint32_t ksB = (uint32_t)__cvta_generic_to_shared(ks);
    uint32_t vtB = (uint32_t)__cvta_generic_to_shared(vt);
    uint32_t PB  = (uint32_t)__cvta_generic_to_shared(P);

    // zero V key-padding cols 49..63 (P is exactly 0 there; avoid 0*NaN)
    for (int i = tid; i < 32 * 15; i += 128) {
        int d = i / 15, m = 49 + (i - (i / 15) * 15);
        *(__half*)((char*)vt + swz128((uint32_t)(d * 128 + m * 2))) = __ushort_as_half(0);
    }
    // stage Q,K row-major SW128; V transposed [d][key]
    for (int idx = tid; idx < 49 * 16; idx += 128) {
        int n = idx >> 4, d2 = idx & 15;
        const __half2* p = (const __half2*)(qkv + (size_t)(base + n) * 768 + head * 32) + d2;
        __half2 qh = p[0], kh = p[128], vh = p[256];
        *(__half2*)((char*)qs + swz128((uint32_t)(n * 128 + d2 * 4))) = qh;
        *(__half2*)((char*)ks + swz128((uint32_t)(n * 128 + d2 * 4))) = kh;
        *(__half*)((char*)vt + swz128((uint32_t)((2 * d2)     * 128 + n * 2))) = __low2half(vh);
        *(__half*)((char*)vt + swz128((uint32_t)((2 * d2 + 1) * 128 + n * 2))) = __high2half(vh);
    }
    __syncthreads();

    int lr = lane & 7;
    int arow = 16 * w + lr + ((lane & 8) ? 8 : 0);
    int acol = (lane & 16) ? 16 : 0;
    uint32_t aQ = qsB + swz128((uint32_t)(arow * 128 + acol));
    uint32_t aP = PB  + swz128((uint32_t)(arow * 128 + acol));
    int mq = lane >> 3;
    int brow = (mq >> 1) * 8 + lr;                 // within an n16 group
    int bcol = (mq & 1) * 16;

    // ---- S = Q K^T : 8 n8-tiles of keys ----
    float acc[8][4];
    #pragma unroll
    for (int t = 0; t < 8; t++)
        #pragma unroll
        for (int e = 0; e < 4; e++) acc[t][e] = 0.f;

    uint32_t a0[4], a1[4];
    ldsm4(a0[0], a0[1], a0[2], a0[3], aQ);         // k (=d) chunk 0
    ldsm4(a1[0], a1[1], a1[2], a1[3], aQ ^ 32);    // k chunk 1
    #pragma unroll
    for (int t = 0; t < 4; t++) {
        uint32_t bk = ksB + swz128((uint32_t)((16 * t + brow) * 128 + bcol));
        uint32_t b4[4];
        ldsm4(b4[0], b4[1], b4[2], b4[3], bk);
        mma_f16(acc[2 * t],     a0[0], a0[1], a0[2], a0[3], b4[0], b4[1]);
        mma_f16(acc[2 * t + 1], a0[0], a0[1], a0[2], a0[3], b4[2], b4[3]);
        ldsm4(b4[0], b4[1], b4[2], b4[3], bk ^ 32);
        mma_f16(acc[2 * t],     a1[0], a1[1], a1[2], a1[3], b4[0], b4[1]);
        mma_f16(acc[2 * t + 1], a1[0], a1[1], a1[2], a1[3], b4[2], b4[3]);
    }

    // ---- in-register softmax (rows r0 = 16w+qrow, r1 = r0+8) ----
    int qrow = lane >> 2, qcol = lane & 3;
    const float scale = 0.1767766952966369f;       // 1/sqrt(32)
    float mx0 = -1e30f, mx1 = -1e30f;
    #pragma unroll
    for (int j = 0; j < 8; j++) {
        int c0 = 8 * j + 2 * qcol;
        acc[j][0] = (c0     < 49) ? acc[j][0] * scale : -1e30f;
        acc[j][1] = (c0 + 1 < 49) ? acc[j][1] * scale : -1e30f;
        acc[j][2] = (c0     < 49) ? acc[j][2] * scale : -1e30f;
        acc[j][3] = (c0 + 1 < 49) ? acc[j][3] * scale : -1e30f;
        mx0 = fmaxf(mx0, fmaxf(acc[j][0], acc[j][1]));
        mx1 = fmaxf(mx1, fmaxf(acc[j][2], acc[j][3]));
    }
    mx0 = fmaxf(mx0, __shfl_xor_sync(0xffffffffu, mx0, 1));
    mx0 = fmaxf(mx0, __shfl_xor_sync(0xffffffffu, mx0, 2));
    mx1 = fmaxf(mx1, __shfl_xor_sync(0xffffffffu, mx1, 1));
    mx1 = fmaxf(mx1, __shfl_xor_sync(0xffffffffu, mx1, 2));
    float s0 = 0.f, s1 = 0.f;
    #pragma unroll
    for (int j = 0; j < 8; j++) {
        acc[j][0] = __expf(acc[j][0] - mx0);
        acc[j][1] = __expf(acc[j][1] - mx0);
        acc[j][2] = __expf(acc[j][2] - mx1);
        acc[j][3] = __expf(acc[j][3] - mx1);
        s0 += acc[j][0] + acc[j][1];
        s1 += acc[j][2] + acc[j][3];
    }
    s0 += __shfl_xor_sync(0xffffffffu, s0, 1);
    s0 += __shfl_xor_sync(0xffffffffu, s0, 2);
    s1 += __shfl_xor_sync(0xffffffffu, s1, 1);
    s1 += __shfl_xor_sync(0xffffffffu, s1, 2);
    float i0 = 1.0f / s0, i1 = 1.0f / s1;
    int r0 = 16 * w + qrow, r1 = r0 + 8;
    #pragma unroll
    for (int j = 0; j < 8; j++) {
        int c0 = 8 * j + 2 * qcol;
        *(__half2*)((char*)P + swz128((uint32_t)(r0 * 128 + c0 * 2))) =
            __floats2half2_rn(acc[j][0] * i0, acc[j][1] * i0);
        *(__half2*)((char*)P + swz128((uint32_t)(r1 * 128 + c0 * 2))) =
            __floats2half2_rn(acc[j][2] * i1, acc[j][3] * i1);
    }
    __syncwarp();   // warp reads only its own P rows

    // ---- O = P * V^T : k = keys (4 chunks), n = dims (4 n8-tiles) ----
    float o[4][4];
    #pragma unroll
    for (int t = 0; t < 4; t++)
        #pragma unroll
        for (int e = 0; e < 4; e++) o[t][e] = 0.f;
    #pragma unroll
    for (int kt = 0; kt < 4; kt++) {
        uint32_t pa[4];
        ldsm4(pa[0], pa[1], pa[2], pa[3], aP ^ (uint32_t)(kt * 32));
        #pragma unroll
        for (int np = 0; np < 2; np++) {
            uint32_t b4[4];
            ldsm4(b4[0], b4[1], b4[2], b4[3],
                  (vtB + swz128((uint32_t)((np * 16 + brow) * 128 + bcol))) ^ (uint32_t)(kt * 32));
            mma_f16(o[2 * np],     pa[0], pa[1], pa[2], pa[3], b4[0], b4[1]);
            mma_f16(o[2 * np + 1], pa[0], pa[1], pa[2], pa[3], b4[2], b4[3]);
        }
    }
    #pragma unroll
    for (int nt = 0; nt < 4; nt++) {
        int d = 8 * nt + 2 * qcol;
        if (r0 < 49)
            *(__half2*)(out + (size_t)(base + r0) * 256 + head * 32 + d) =
                __floats2half2_rn(o[nt][0], o[nt][1]);
        if (r1 < 49)
            *(__half2*)(out + (size_t)(base + r1) * 256 + head * 32 + d) =
                __floats2half2_rn(o[nt][2], o[nt][3]);
    }
}

// ---------------- host: tensor-map encode ------------------------------------
typedef CUresult (*tmap_fn)(CUtensorMap*, CUtensorMapDataType, cuuint32_t, void*,
                            const cuuint64_t*, const cuuint64_t*, const cuuint32_t*,
                            const cuuint32_t*, CUtensorMapInterleave, CUtensorMapSwizzle,
                            CUtensorMapL2promotion, CUtensorMapFloatOOBfill);

static tmap_fn get_enc() {
    void* fn = nullptr;
    cudaDriverEntryPointQueryResult qr;
#if CUDART_VERSION >= 12050
    cudaGetDriverEntryPointByVersion("cuTensorMapEncodeTiled", &fn, 12000,
                                     cudaEnableDefault, &qr);
#else
    cudaGetDriverEntryPoint("cuTensorMapEncodeTiled", &fn, cudaEnableDefault, &qr);
#endif
    return (tmap_fn)fn;
}

static void enc2d(tmap_fn f, CUtensorMap* m, void* ptr, uint64_t innerK, uint64_t outerRows) {
    cuuint64_t dims[2]    = {innerK, outerRows};
    cuuint64_t strides[1] = {innerK * 2};
    cuuint32_t box[2]     = {64, 128};
    cuuint32_t el[2]      = {1, 1};
    f(m, CU_TENSOR_MAP_DATA_TYPE_FLOAT16, 2, ptr, dims, strides, box, el,
      CU_TENSOR_MAP_INTERLEAVE_NONE, CU_TENSOR_MAP_SWIZZLE_128B,
      CU_TENSOR_MAP_L2_PROMOTION_L2_128B, CU_TENSOR_MAP_FLOAT_OOB_FILL_NONE);
}

// ---------------- launch ----------------------------------------------------
extern "C" void kernel_launch(void* const* d_in, const int* in_sizes, int n_in,
                              void* d_out, int out_size) {
    const float* x      = (const float*)d_in[0];
    const float* n1_g   = (const float*)d_in[1];
    const float* n1_b   = (const float*)d_in[2];
    const float* qkv_w  = (const float*)d_in[3];
    const float* qkv_b  = (const float*)d_in[4];
    const float* proj_w = (const float*)d_in[5];
    const float* proj_b = (const float*)d_in[6];
    const float* n2_g   = (const float*)d_in[7];
    const float* n2_b   = (const float*)d_in[8];
    const float* mlp_w1 = (const float*)d_in[9];
    const float* mlp_b1 = (const float*)d_in[10];
    const float* mlp_w2 = (const float*)d_in[11];
    const float* mlp_b2 = (const float*)d_in[12];
    float* out = (float*)d_out;

    float *p_short, *p_bufA, *p_qkv, *p_xres, *p_hid, *p_wts_f;
    cudaGetSymbolAddress((void**)&p_short, g_short);
    cudaGetSymbolAddress((void**)&p_bufA,  g_bufA);
    cudaGetSymbolAddress((void**)&p_qkv,   g_qkv);
    cudaGetSymbolAddress((void**)&p_xres,  g_xres);
    cudaGetSymbolAddress((void**)&p_hid,   g_hid);
    cudaGetSymbolAddress((void**)&p_wts_f, g_wts);
    __half* p_wts = (__half*)p_wts_f;

    tmap_fn enc = get_enc();
    CUtensorMap dA_bufA, dA_ln2, dA_hid, dB_qkv, dB_proj, dB_w1, dB_w2;
    enc2d(enc, &dA_bufA, p_bufA,            256,  TOK);
    enc2d(enc, &dA_ln2,  p_qkv,             256,  TOK);
    enc2d(enc, &dA_hid,  p_hid,             1024, TOK);
    enc2d(enc, &dB_qkv,  p_wts + WOFF_QKV,  256,  768);
    enc2d(enc, &dB_proj, p_wts + WOFF_PROJ, 256,  256);
    enc2d(enc, &dB_w1,   p_wts + WOFF_W1,   256,  1024);
    enc2d(enc, &dB_w2,   p_wts + WOFF_W2,   1024, 256);

    cudaFuncSetAttribute(k_gemm<0>, cudaFuncAttributeMaxDynamicSharedMemorySize, GEMM_SMEM);
    cudaFuncSetAttribute(k_gemm<1>, cudaFuncAttributeMaxDynamicSharedMemorySize, GEMM_SMEM);
    cudaFuncSetAttribute(k_gemm<2>, cudaFuncAttributeMaxDynamicSharedMemorySize, GEMM_SMEM);
    cudaFuncSetAttribute(k_gemm<3>, cudaFuncAttributeMaxDynamicSharedMemorySize, GEMM_SMEM);

    dim3 tb(32, 8);
    // weight round + transpose into fp16 [N][K] (single merged launch)
    k_wt_all<<<768, tb>>>(qkv_w, proj_w, mlp_w1, mlp_w2, p_wts);

    // fused transpose + LN1 (shortcut f32 spatial; LN1 fp16 window order)
    k_tr_ln<<<dim3(98, 32), 256>>>(x, n1_g, n1_b);
    // qkv = winLN1 @ qkv_w^T + b  (fp16 out); bn fastest for A L2 reuse
    k_gemm<0><<<dim3(6, 784), 256, GEMM_SMEM>>>(dA_bufA, dB_qkv, qkv_b, nullptr, p_qkv, 768, 256);
    // windowed MHSA (tensor-core path)
    k_attn<<<NWIN * NHEAD, 128>>>((const __half*)p_qkv, (__half*)p_bufA);
    // xres = shortcut + scatter(attn_o @ proj_w^T + b)   (f32 out)
    k_gemm<2><<<dim3(2, 784), 256, GEMM_SMEM>>>(dA_bufA, dB_proj, proj_b, p_short, p_xres, 256, 256);
    // LN2 (fp16 out into g_qkv scratch)
    k_ln<<<TOK, 64>>>(p_xres, n2_g, n2_b, (__half*)p_qkv);
    // hid = gelu(ln2 @ w1^T + b1)  (fp16 out)
    k_gemm<1><<<dim3(8, 784), 256, GEMM_SMEM>>>(dA_ln2, dB_w1, mlp_b1, nullptr, p_hid, 1024, 256);
    // final = xres + hid @ w2^T + b2, written DIRECTLY transposed to (B,C,HW) out
    k_gemm<3><<<dim3(2, 784), 256, GEMM_SMEM>>>(dA_hid, dB_w2, mlp_b2, p_xres, out, 256, 1024);
}

// round 17
// speedup vs baseline: 6.1279x; 1.0322x over previous
#include <cuda_runtime.h>
#include <cuda.h>
#include <cuda_fp16.h>
#include <math.h>
#include <stdint.h>

#define B_     32
#define C_     256
#define H_     56
#define W_     56
#define HW_    3136
#define TOK    100352          // B_*H_*W_
#define NWIN   2048
#define NHEAD  8
#define HID    1024

// ---------------- scratch (device globals; fp16 views overlay float arrays) --
__device__ float g_short[(size_t)TOK * C_ / 2];    // half: shortcut (spatial order)
__device__ float g_bufA [(size_t)TOK * C_];        // half: LN1(win order) -> attn out
__device__ float g_qkv  [(size_t)TOK * 3 * C_];    // half: qkv -> ln2 out
__device__ float g_xres [(size_t)TOK * C_ / 2];    // half: x after attn residual
__device__ float g_hid  [(size_t)TOK * HID];       // half: mlp hidden
__device__ float g_wts  [786432];                  // half: transposed weights [N][K]

#define WOFF_QKV  0
#define WOFF_PROJ 196608
#define WOFF_W1   262144
#define WOFF_W2   524288

// window-order row m -> spatial token (for proj scatter epilogue)
__device__ __forceinline__ int win_token(int m) {
    int win = m / 49;
    int n   = m - win * 49;
    int b   = win >> 6;
    int r   = win & 63;
    int i   = n / 7;
    int j   = n - i * 7;
    int h = (r >> 3) * 7 + i + 3; if (h >= H_) h -= H_;
    int w = (r & 7)  * 7 + j + 3; if (w >= W_) w -= W_;
    return (b * H_ + h) * W_ + w;
}

// ---------------- ptx helpers ------------------------------------------------
__device__ __forceinline__ void mma_f16(float (&d)[4],
                                        uint32_t a0, uint32_t a1, uint32_t a2, uint32_t a3,
                                        uint32_t b0, uint32_t b1) {
    asm volatile(
        "mma.sync.aligned.m16n8k16.row.col.f32.f16.f16.f32 "
        "{%0,%1,%2,%3}, {%4,%5,%6,%7}, {%8,%9}, {%0,%1,%2,%3};\n"
        : "+f"(d[0]), "+f"(d[1]), "+f"(d[2]), "+f"(d[3])
        : "r"(a0), "r"(a1), "r"(a2), "r"(a3), "r"(b0), "r"(b1));
}
__device__ __forceinline__ uint32_t swz128(uint32_t b) { return b ^ ((b >> 3) & 0x70); }
__device__ __forceinline__ void ldsm4(uint32_t& r0, uint32_t& r1, uint32_t& r2, uint32_t& r3,
                                      uint32_t a) {
    asm volatile("ldmatrix.sync.aligned.m8n8.x4.shared.b16 {%0,%1,%2,%3}, [%4];"
                 : "=r"(r0), "=r"(r1), "=r"(r2), "=r"(r3) : "r"(a));
}
__device__ __forceinline__ void mbar_init(uint32_t a, uint32_t cnt) {
    asm volatile("mbarrier.init.shared.b64 [%0], %1;" :: "r"(a), "r"(cnt) : "memory");
}
__device__ __forceinline__ void mbar_expect(uint32_t a, uint32_t tx) {
    asm volatile("mbarrier.arrive.expect_tx.shared.b64 _, [%0], %1;" :: "r"(a), "r"(tx) : "memory");
}
__device__ __forceinline__ void mbar_wait(uint32_t a, uint32_t ph) {
    asm volatile(
        "{\n\t.reg .pred P1;\n\t"
        "WL%=:\n\t"
        "mbarrier.try_wait.parity.acquire.cta.shared::cta.b64 P1, [%0], %1, 0x989680;\n\t"
        "@P1 bra WD%=;\n\t"
        "bra WL%=;\n\t"
        "WD%=:\n\t}"
        :: "r"(a), "r"(ph) : "memory");
}
__device__ __forceinline__ void tma2d(uint32_t dst, const void* map, int x, int y, uint32_t mbar) {
    asm volatile(
        "cp.async.bulk.tensor.2d.shared::cta.global.tile.mbarrier::complete_tx::bytes "
        "[%0], [%1, {%2, %3}], [%4];"
        :: "r"(dst), "l"(map), "r"(x), "r"(y), "r"(mbar) : "memory");
}

// ---------------- merged weight round+transpose: dst[n][k] = fp16(src[k][n]) -
// 768 blocks: [0,192) qkv, [192,256) proj, [256,512) w1, [512,768) w2
__global__ void k_wt_all(const float* __restrict__ qkv_w, const float* __restrict__ proj_w,
                         const float* __restrict__ w1, const float* __restrict__ w2,
                         __half* __restrict__ dst) {
    __shared__ float t[32][33];
    int bid = blockIdx.x;
    const float* src; __half* d; int K, N, rel;
    if (bid < 192)      { src = qkv_w;  d = dst + WOFF_QKV;  K = 256;  N = 768;  rel = bid; }
    else if (bid < 256) { src = proj_w; d = dst + WOFF_PROJ; K = 256;  N = 256;  rel = bid - 192; }
    else if (bid < 512) { src = w1;     d = dst + WOFF_W1;   K = 256;  N = 1024; rel = bid - 256; }
    else                { src = w2;     d = dst + WOFF_W2;   K = 1024; N = 256;  rel = bid - 512; }
    int nkb = K >> 5;
    int k0 = (rel % nkb) * 32, n0 = (rel / nkb) * 32;
    int tx = threadIdx.x, ty = threadIdx.y;
    #pragma unroll
    for (int j = ty; j < 32; j += 8)
        t[j][tx] = src[(size_t)(k0 + j) * N + n0 + tx];
    __syncthreads();
    #pragma unroll
    for (int j = ty; j < 32; j += 8)
        d[(size_t)(n0 + j) * K + k0 + tx] = __float2half(t[tx][j]);
}

// ---------------- fused transpose + LN1; shortcut fp16 + LN1 fp16 window -----
__global__ __launch_bounds__(256)
void k_tr_ln(const float* __restrict__ x, const float* __restrict__ gam,
             const float* __restrict__ bet) {
    __shared__ float tile[256][33];
    int b = blockIdx.y, hw0 = blockIdx.x * 32;
    int tid = threadIdx.x;
    int tx = tid & 31, ty = tid >> 5;
    for (int c = ty; c < 256; c += 8)
        tile[c][tx] = x[((size_t)(b * 256 + c)) * HW_ + hw0 + tx];
    __syncthreads();

    __half* winout = (__half*)g_bufA;
    __half* shout  = (__half*)g_short;
    int lane = tx;
    #pragma unroll
    for (int q = 0; q < 4; q++) {
        int tk = ty * 4 + q;
        float s = 0.f, ss = 0.f;
        #pragma unroll
        for (int ci = 0; ci < 8; ci++) {
            float v = tile[lane + ci * 32][tk];
            s += v; ss += v * v;
        }
        #pragma unroll
        for (int o = 16; o; o >>= 1) {
            s  += __shfl_xor_sync(0xffffffffu, s, o);
            ss += __shfl_xor_sync(0xffffffffu, ss, o);
        }
        float mean = s * (1.0f / C_);
        float var  = ss * (1.0f / C_) - mean * mean;
        float rstd = rsqrtf(var + 1e-5f);

        int hw = hw0 + tk;
        int t  = b * HW_ + hw;
        int h  = hw / W_, w = hw - h * W_;
        int hs = (h >= 3) ? h - 3 : h + 53;
        int ws = (w >= 3) ? w - 3 : w + 53;
        int m  = (b * 64 + (hs / 7) * 8 + (ws / 7)) * 49 + (hs % 7) * 7 + (ws % 7);

        for (int c = lane; c < 256; c += 32) {
            float v = tile[c][tk];
            shout[(size_t)t * C_ + c] = __float2half(v);
            winout[(size_t)m * C_ + c] = __float2half((v - mean) * rstd * gam[c] + bet[c]);
        }
    }
}

// ---------------- LN2 (fp16 in, fp16 out) ------------------------------------
__global__ void k_ln(const __half* __restrict__ x, const float* __restrict__ g,
                     const float* __restrict__ bb, __half* __restrict__ out) {
    int token = blockIdx.x;
    int tid = threadIdx.x;
    const __half2* xp = (const __half2*)(x + (size_t)token * C_);
    float2 a0 = __half22float2(xp[2 * tid]);
    float2 a1 = __half22float2(xp[2 * tid + 1]);
    float4 v = make_float4(a0.x, a0.y, a1.x, a1.y);
    float s  = v.x + v.y + v.z + v.w;
    float ss = v.x * v.x + v.y * v.y + v.z * v.z + v.w * v.w;
    #pragma unroll
    for (int o = 16; o; o >>= 1) {
        s  += __shfl_xor_sync(0xffffffffu, s, o);
        ss += __shfl_xor_sync(0xffffffffu, ss, o);
    }
    __shared__ float sh[4];
    if ((tid & 31) == 0) { sh[tid >> 5] = s; sh[2 + (tid >> 5)] = ss; }
    __syncthreads();
    s = sh[0] + sh[1]; ss = sh[2] + sh[3];
    float mean = s * (1.0f / C_);
    float var  = ss * (1.0f / C_) - mean * mean;
    float rstd = rsqrtf(var + 1e-5f);
    float4 gg = ((const float4*)g)[tid];
    float4 bv = ((const float4*)bb)[tid];
    __half2 h0 = __floats2half2_rn((v.x - mean) * rstd * gg.x + bv.x,
                                   (v.y - mean) * rstd * gg.y + bv.y);
    __half2 h1 = __floats2half2_rn((v.z - mean) * rstd * gg.z + bv.z,
                                   (v.w - mean) * rstd * gg.w + bv.w);
    __half2* op = (__half2*)(out + (size_t)token * C_);
    op[2 * tid]     = h0;
    op[2 * tid + 1] = h1;
}

// ---------------- TMA-fed fp16 GEMM 128x128, BK=64, 3-stage pipeline ---------
// Grid: blockIdx.x = N tile (fastest -> L2 reuse of A), blockIdx.y = M tile.
// EPI: 0 bias->half | 1 bias+GELU->half
//      2 bias + scatter(win_token) + extra(half) -> half
//      3 bias + extra(half) -> f32 TRANSPOSED write to (B,C,HW) via smem staging
#define NS 3
#define STG_BYTES 16384                    // 128 rows * 128B per side per stage
#define GEMM_SMEM (NS * 2 * STG_BYTES + 64)

template<int EPI>
__global__ __launch_bounds__(256, 2)
void k_gemm(const __grid_constant__ CUtensorMap dA,
            const __grid_constant__ CUtensorMap dB,
            const float* __restrict__ bias, const void* __restrict__ extra,
            void* __restrict__ Cout, int N, int K)
{
    extern __shared__ __align__(1024) char smem[];
    uint32_t aBase = (uint32_t)__cvta_generic_to_shared(smem);
    uint32_t bBase = aBase + NS * STG_BYTES;
    uint32_t mBase = bBase + NS * STG_BYTES;

    int tid = threadIdx.x;
    int lane = tid & 31, wid = tid >> 5;
    int warpM = wid >> 1, warpN = wid & 1;
    int qrow = lane >> 2, qcol = lane & 3;
    int bm = blockIdx.y * 128, bn = blockIdx.x * 128;
    int niters = K >> 6;

    if (tid == 0) {
        #pragma unroll
        for (int s = 0; s < NS; s++) mbar_init(mBase + 8 * s, 1);
    }
    __syncthreads();

    if (tid == 0) {
        #pragma unroll
        for (int j = 0; j < NS - 1; j++) {
            mbar_expect(mBase + 8 * j, 2 * STG_BYTES);
            tma2d(aBase + j * STG_BYTES, &dA, j * 64, bm, mBase + 8 * j);
            tma2d(bBase + j * STG_BYTES, &dB, j * 64, bn, mBase + 8 * j);
        }
    }

    // per-thread ldmatrix base addresses (stage 0, k-step 0); byte-col in {0,16}
    uint32_t aAddr[2], bAddr[4];
    {
        int lr = lane & 7;
        #pragma unroll
        for (int mt = 0; mt < 2; mt++) {
            int row = warpM * 32 + mt * 16 + lr + ((lane & 8) ? 8 : 0);
            int c4  = (lane & 16) ? 16 : 0;
            aAddr[mt] = aBase + swz128((uint32_t)(row * 128 + c4));
        }
        int mq = lane >> 3;
        #pragma unroll
        for (int np = 0; np < 4; np++) {
            int row = warpN * 64 + (np * 2 + (mq >> 1)) * 8 + lr;
            int c4  = (mq & 1) * 16;
            bAddr[np] = bBase + swz128((uint32_t)(row * 128 + c4));
        }
    }

    float acc[2][8][4];
    #pragma unroll
    for (int mt = 0; mt < 2; mt++)
        #pragma unroll
        for (int nt = 0; nt < 8; nt++)
            #pragma unroll
            for (int e = 0; e < 4; e++) acc[mt][nt][e] = 0.f;

    int scur = 0, pcur = 0;
    int spre = NS - 1;
    for (int i = 0; i < niters; i++) {
        mbar_wait(mBase + 8 * scur, pcur);
        uint32_t so = (uint32_t)scur * STG_BYTES;

        #pragma unroll
        for (int ks = 0; ks < 4; ks++) {
            uint32_t kx = (uint32_t)(ks * 32);  // XOR-applied, swizzle-safe
            uint32_t af[2][4], bf[8][2];
            #pragma unroll
            for (int mt = 0; mt < 2; mt++)
                ldsm4(af[mt][0], af[mt][1], af[mt][2], af[mt][3],
                      (aAddr[mt] + so) ^ kx);
            #pragma unroll
            for (int np = 0; np < 4; np++)
                ldsm4(bf[2 * np][0], bf[2 * np][1], bf[2 * np + 1][0], bf[2 * np + 1][1],
                      (bAddr[np] + so) ^ kx);
            #pragma unroll
            for (int mt = 0; mt < 2; mt++)
                #pragma unroll
                for (int nt = 0; nt < 8; nt++)
                    mma_f16(acc[mt][nt], af[mt][0], af[mt][1], af[mt][2], af[mt][3],
                            bf[nt][0], bf[nt][1]);
        }
        __syncthreads();

        int j = i + NS - 1;
        if (j < niters && tid == 0) {
            mbar_expect(mBase + 8 * spre, 2 * STG_BYTES);
            tma2d(aBase + spre * STG_BYTES, &dA, j * 64, bm, mBase + 8 * spre);
            tma2d(bBase + spre * STG_BYTES, &dB, j * 64, bn, mBase + 8 * spre);
        }
        if (++scur == NS) { scur = 0; pcur ^= 1; }
        if (++spre == NS) spre = 0;
    }

    // -------- epilogue --------
    if (EPI == 3) {
        // bias + extra(half), then transposed (B,C,HW) write through smem staging
        float* St = (float*)smem;                      // [col][row], stride 130
        #pragma unroll
        for (int mt = 0; mt < 2; mt++) {
            #pragma unroll
            for (int half = 0; half < 2; half++) {
                int rl = warpM * 32 + mt * 16 + qrow + half * 8;
                int gr = bm + rl;
                #pragma unroll
                for (int nt = 0; nt < 8; nt++) {
                    int cl  = warpN * 64 + nt * 8 + 2 * qcol;
                    int col = bn + cl;
                    float2 e = __half22float2(
                        *(const __half2*)((const __half*)extra + (size_t)gr * N + col));
                    float v0 = acc[mt][nt][2 * half + 0] + bias[col]     + e.x;
                    float v1 = acc[mt][nt][2 * half + 1] + bias[col + 1] + e.y;
                    St[cl * 130 + rl]       = v0;
                    St[(cl + 1) * 130 + rl] = v1;
                }
            }
        }
        __syncthreads();
        int bseg[4], hwseg[4];
        #pragma unroll
        for (int seg = 0; seg < 4; seg++) {
            int t = bm + seg * 32 + lane;
            bseg[seg]  = t / HW_;
            hwseg[seg] = t - bseg[seg] * HW_;
        }
        float* outp = (float*)Cout;
        #pragma unroll
        for (int cc = 0; cc < 16; cc++) {
            int cl = wid * 16 + cc;
            int gc = bn + cl;
            #pragma unroll
            for (int seg = 0; seg < 4; seg++)
                outp[((size_t)(bseg[seg] * 256 + gc)) * HW_ + hwseg[seg]] =
                    St[cl * 130 + seg * 32 + lane];
        }
    } else {
        #pragma unroll
        for (int mt = 0; mt < 2; mt++) {
            #pragma unroll
            for (int half = 0; half < 2; half++) {
                int gr = bm + warpM * 32 + mt * 16 + qrow + half * 8;
                size_t orow = (EPI == 2) ? (size_t)win_token(gr) : (size_t)gr;
                #pragma unroll
                for (int nt = 0; nt < 8; nt++) {
                    int col = bn + warpN * 64 + nt * 8 + 2 * qcol;
                    float v0 = acc[mt][nt][2 * half + 0] + bias[col];
                    float v1 = acc[mt][nt][2 * half + 1] + bias[col + 1];
                    if (EPI == 1) {
                        v0 = 0.5f * v0 * (1.0f + erff(v0 * 0.7071067811865475f));
                        v1 = 0.5f * v1 * (1.0f + erff(v1 * 0.7071067811865475f));
                    }
                    if (EPI == 2) {
                        float2 e = __half22float2(
                            *(const __half2*)((const __half*)extra + orow * N + col));
                        v0 += e.x;
                        v1 += e.y;
                    }
                    *(__half2*)((__half*)Cout + orow * N + col) = __floats2half2_rn(v0, v1);
                }
            }
        }
    }
}

// ---------------- windowed attention via mma (tensor-core path) --------------
__global__ void __launch_bounds__(128)
k_attn(const __half* __restrict__ qkv, __half* __restrict__ out) {
    __shared__ __align__(128) __half qs[64 * 64];
    __shared__ __align__(128) __half ks[64 * 64];
    __shared__ __align__(128) __half vt[32 * 64];   // [d][key]
    __shared__ __align__(128) __half P [64 * 64];   // [query][key]
    int win  = blockIdx.x >> 3;
    int head = blockIdx.x & 7;
    int tid  = threadIdx.x;
    int lane = tid & 31;
    int w    = tid >> 5;
    int base = win * 49;

    uint32_t qsB = (uint32_t)__cvta_generic_to_shared(qs);
    uint32_t ksB = (uint32_t)__cvta_generic_to_shared(ks);
    uint32_t vtB = (uint32_t)__cvta_generic_to_shared(vt);
    uint32_t PB  = (uint32_t)__cvta_generic_to_shared(P);

    for (int i = tid; i < 32 * 15; i += 128) {
        int d = i / 15, m = 49 + (i - (i / 15) * 15);
        *(__half*)((char*)vt + swz128((uint32_t)(d * 128 + m * 2))) = __ushort_as_half(0);
    }
    for (int idx = tid; idx < 49 * 16; idx += 128) {
        int n = idx >> 4, d2 = idx & 15;
        const __half2* p = (const __half2*)(qkv + (size_t)(base + n) * 768 + head * 32) + d2;
        __half2 qh = p[0], kh = p[128], vh = p[256];
        *(__half2*)((char*)qs + swz128((uint32_t)(n * 128 + d2 * 4))) = qh;
        *(__half2*)((char*)ks + swz128((uint32_t)(n * 128 + d2 * 4))) = kh;
        *(__half*)((char*)vt + swz128((uint32_t)((2 * d2)     * 128 + n * 2))) = __low2half(vh);
        *(__half*)((char*)vt + swz128((uint32_t)((2 * d2 + 1) * 128 + n * 2))) = __high2half(vh);
    }
    __syncthreads();

    int lr = lane & 7;
    int arow = 16 * w + lr + ((lane & 8) ? 8 : 0);
    int acol = (lane & 16) ? 16 : 0;
    uint32_t aQ = qsB + swz128((uint32_t)(arow * 128 + acol));
    uint32_t aP = PB  + swz128((uint32_t)(arow * 128 + acol));
    int mq = lane >> 3;
    int brow = (mq >> 1) * 8 + lr;
    int bcol = (mq & 1) * 16;

    float acc[8][4];
    #pragma unroll
    for (int t = 0; t < 8; t++)
        #pragma unroll
        for (int e = 0; e < 4; e++) acc[t][e] = 0.f;

    uint32_t a0[4], a1[4];
    ldsm4(a0[0], a0[1], a0[2], a0[3], aQ);
    ldsm4(a1[0], a1[1], a1[2], a1[3], aQ ^ 32);
    #pragma unroll
    for (int t = 0; t < 4; t++) {
        uint32_t bk = ksB + swz128((uint32_t)((16 * t + brow) * 128 + bcol));
        uint32_t b4[4];
        ldsm4(b4[0], b4[1], b4[2], b4[3], bk);
        mma_f16(acc[2 * t],     a0[0], a0[1], a0[2], a0[3], b4[0], b4[1]);
        mma_f16(acc[2 * t + 1], a0[0], a0[1], a0[2], a0[3], b4[2], b4[3]);
        ldsm4(b4[0], b4[1], b4[2], b4[3], bk ^ 32);
        mma_f16(acc[2 * t],     a1[0], a1[1], a1[2], a1[3], b4[0], b4[1]);
        mma_f16(acc[2 * t + 1], a1[0], a1[1], a1[2], a1[3], b4[2], b4[3]);
    }

    int qrow = lane >> 2, qcol = lane & 3;
    const float scale = 0.1767766952966369f;
    float mx0 = -1e30f, mx1 = -1e30f;
    #pragma unroll
    for (int j = 0; j < 8; j++) {
        int c0 = 8 * j + 2 * qcol;
        acc[j][0] = (c0     < 49) ? acc[j][0] * scale : -1e30f;
        acc[j][1] = (c0 + 1 < 49) ? acc[j][1] * scale : -1e30f;
        acc[j][2] = (c0     < 49) ? acc[j][2] * scale : -1e30f;
        acc[j][3] = (c0 + 1 < 49) ? acc[j][3] * scale : -1e30f;
        mx0 = fmaxf(mx0, fmaxf(acc[j][0], acc[j][1]));
        mx1 = fmaxf(mx1, fmaxf(acc[j][2], acc[j][3]));
    }
    mx0 = fmaxf(mx0, __shfl_xor_sync(0xffffffffu, mx0, 1));
    mx0 = fmaxf(mx0, __shfl_xor_sync(0xffffffffu, mx0, 2));
    mx1 = fmaxf(mx1, __shfl_xor_sync(0xffffffffu, mx1, 1));
    mx1 = fmaxf(mx1, __shfl_xor_sync(0xffffffffu, mx1, 2));
    float s0 = 0.f, s1 = 0.f;
    #pragma unroll
    for (int j = 0; j < 8; j++) {
        acc[j][0] = __expf(acc[j][0] - mx0);
        acc[j][1] = __expf(acc[j][1] - mx0);
        acc[j][2] = __expf(acc[j][2] - mx1);
        acc[j][3] = __expf(acc[j][3] - mx1);
        s0 += acc[j][0] + acc[j][1];
        s1 += acc[j][2] + acc[j][3];
    }
    s0 += __shfl_xor_sync(0xffffffffu, s0, 1);
    s0 += __shfl_xor_sync(0xffffffffu, s0, 2);
    s1 += __shfl_xor_sync(0xffffffffu, s1, 1);
    s1 += __shfl_xor_sync(0xffffffffu, s1, 2);
    float i0 = 1.0f / s0, i1 = 1.0f / s1;
    int r0 = 16 * w + qrow, r1 = r0 + 8;
    #pragma unroll
    for (int j = 0; j < 8; j++) {
        int c0 = 8 * j + 2 * qcol;
        *(__half2*)((char*)P + swz128((uint32_t)(r0 * 128 + c0 * 2))) =
            __floats2half2_rn(acc[j][0] * i0, acc[j][1] * i0);
        *(__half2*)((char*)P + swz128((uint32_t)(r1 * 128 + c0 * 2))) =
            __floats2half2_rn(acc[j][2] * i1, acc[j][3] * i1);
    }
    __syncwarp();

    float o[4][4];
    #pragma unroll
    for (int t = 0; t < 4; t++)
        #pragma unroll
        for (int e = 0; e < 4; e++) o[t][e] = 0.f;
    #pragma unroll
    for (int kt = 0; kt < 4; kt++) {
        uint32_t pa[4];
        ldsm4(pa[0], pa[1], pa[2], pa[3], aP ^ (uint32_t)(kt * 32));
        #pragma unroll
        for (int np = 0; np < 2; np++) {
            uint32_t b4[4];
            ldsm4(b4[0], b4[1], b4[2], b4[3],
                  (vtB + swz128((uint32_t)((np * 16 + brow) * 128 + bcol))) ^ (uint32_t)(kt * 32));
            mma_f16(o[2 * np],     pa[0], pa[1], pa[2], pa[3], b4[0], b4[1]);
            mma_f16(o[2 * np + 1], pa[0], pa[1], pa[2], pa[3], b4[2], b4[3]);
        }
    }
    #pragma unroll
    for (int nt = 0; nt < 4; nt++) {
        int d = 8 * nt + 2 * qcol;
        if (r0 < 49)
            *(__half2*)(out + (size_t)(base + r0) * 256 + head * 32 + d) =
                __floats2half2_rn(o[nt][0], o[nt][1]);
        if (r1 < 49)
            *(__half2*)(out + (size_t)(base + r1) * 256 + head * 32 + d) =
                __floats2half2_rn(o[nt][2], o[nt][3]);
    }
}

// ---------------- host: tensor-map encode ------------------------------------
typedef CUresult (*tmap_fn)(CUtensorMap*, CUtensorMapDataType, cuuint32_t, void*,
                            const cuuint64_t*, const cuuint64_t*, const cuuint32_t*,
                            const cuuint32_t*, CUtensorMapInterleave, CUtensorMapSwizzle,
                            CUtensorMapL2promotion, CUtensorMapFloatOOBfill);

static tmap_fn get_enc() {
    void* fn = nullptr;
    cudaDriverEntryPointQueryResult qr;
#if CUDART_VERSION >= 12050
    cudaGetDriverEntryPointByVersion("cuTensorMapEncodeTiled", &fn, 12000,
                                     cudaEnableDefault, &qr);
#else
    cudaGetDriverEntryPoint("cuTensorMapEncodeTiled", &fn, cudaEnableDefault, &qr);
#endif
    return (tmap_fn)fn;
}

static void enc2d(tmap_fn f, CUtensorMap* m, void* ptr, uint64_t innerK, uint64_t outerRows) {
    cuuint64_t dims[2]    = {innerK, outerRows};
    cuuint64_t strides[1] = {innerK * 2};
    cuuint32_t box[2]     = {64, 128};
    cuuint32_t el[2]      = {1, 1};
    f(m, CU_TENSOR_MAP_DATA_TYPE_FLOAT16, 2, ptr, dims, strides, box, el,
      CU_TENSOR_MAP_INTERLEAVE_NONE, CU_TENSOR_MAP_SWIZZLE_128B,
      CU_TENSOR_MAP_L2_PROMOTION_L2_128B, CU_TENSOR_MAP_FLOAT_OOB_FILL_NONE);
}

// ---------------- launch ----------------------------------------------------
extern "C" void kernel_launch(void* const* d_in, const int* in_sizes, int n_in,
                              void* d_out, int out_size) {
    const float* x      = (const float*)d_in[0];
    const float* n1_g   = (const float*)d_in[1];
    const float* n1_b   = (const float*)d_in[2];
    const float* qkv_w  = (const float*)d_in[3];
    const float* qkv_b  = (const float*)d_in[4];
    const float* proj_w = (const float*)d_in[5];
    const float* proj_b = (const float*)d_in[6];
    const float* n2_g   = (const float*)d_in[7];
    const float* n2_b   = (const float*)d_in[8];
    const float* mlp_w1 = (const float*)d_in[9];
    const float* mlp_b1 = (const float*)d_in[10];
    const float* mlp_w2 = (const float*)d_in[11];
    const float* mlp_b2 = (const float*)d_in[12];
    float* out = (float*)d_out;

    float *p_short_f, *p_bufA, *p_qkv, *p_xres_f, *p_hid, *p_wts_f;
    cudaGetSymbolAddress((void**)&p_short_f, g_short);
    cudaGetSymbolAddress((void**)&p_bufA,  g_bufA);
    cudaGetSymbolAddress((void**)&p_qkv,   g_qkv);
    cudaGetSymbolAddress((void**)&p_xres_f, g_xres);
    cudaGetSymbolAddress((void**)&p_hid,   g_hid);
    cudaGetSymbolAddress((void**)&p_wts_f, g_wts);
    __half* p_wts   = (__half*)p_wts_f;
    __half* p_short = (__half*)p_short_f;
    __half* p_xres  = (__half*)p_xres_f;

    tmap_fn enc = get_enc();
    CUtensorMap dA_bufA, dA_ln2, dA_hid, dB_qkv, dB_proj, dB_w1, dB_w2;
    enc2d(enc, &dA_bufA, p_bufA,            256,  TOK);
    enc2d(enc, &dA_ln2,  p_qkv,             256,  TOK);
    enc2d(enc, &dA_hid,  p_hid,             1024, TOK);
    enc2d(enc, &dB_qkv,  p_wts + WOFF_QKV,  256,  768);
    enc2d(enc, &dB_proj, p_wts + WOFF_PROJ, 256,  256);
    enc2d(enc, &dB_w1,   p_wts + WOFF_W1,   256,  1024);
    enc2d(enc, &dB_w2,   p_wts + WOFF_W2,   1024, 256);

    cudaFuncSetAttribute(k_gemm<0>, cudaFuncAttributeMaxDynamicSharedMemorySize, GEMM_SMEM);
    cudaFuncSetAttribute(k_gemm<1>, cudaFuncAttributeMaxDynamicSharedMemorySize, GEMM_SMEM);
    cudaFuncSetAttribute(k_gemm<2>, cudaFuncAttributeMaxDynamicSharedMemorySize, GEMM_SMEM);
    cudaFuncSetAttribute(k_gemm<3>, cudaFuncAttributeMaxDynamicSharedMemorySize, GEMM_SMEM);

    dim3 tb(32, 8);
    // weight round + transpose into fp16 [N][K] (single merged launch)
    k_wt_all<<<768, tb>>>(qkv_w, proj_w, mlp_w1, mlp_w2, p_wts);

    // fused transpose + LN1 (shortcut fp16 spatial; LN1 fp16 window order)
    k_tr_ln<<<dim3(98, 32), 256>>>(x, n1_g, n1_b);
    // qkv = winLN1 @ qkv_w^T + b  (fp16 out); bn fastest for A L2 reuse
    k_gemm<0><<<dim3(6, 784), 256, GEMM_SMEM>>>(dA_bufA, dB_qkv, qkv_b, nullptr, p_qkv, 768, 256);
    // windowed MHSA (tensor-core path)
    k_attn<<<NWIN * NHEAD, 128>>>((const __half*)p_qkv, (__half*)p_bufA);
    // xres = shortcut + scatter(attn_o @ proj_w^T + b)   (fp16 out)
    k_gemm<2><<<dim3(2, 784), 256, GEMM_SMEM>>>(dA_bufA, dB_proj, proj_b, p_short, p_xres, 256, 256);
    // LN2 (fp16 in/out into g_qkv scratch)
    k_ln<<<TOK, 64>>>(p_xres, n2_g, n2_b, (__half*)p_qkv);
    // hid = gelu(ln2 @ w1^T + b1)  (fp16 out)
    k_gemm<1><<<dim3(8, 784), 256, GEMM_SMEM>>>(dA_ln2, dB_w1, mlp_b1, nullptr, p_hid, 1024, 256);
    // final = xres + hid @ w2^T + b2, written DIRECTLY transposed to (B,C,HW) out
    k_gemm<3><<<dim3(2, 784), 256, GEMM_SMEM>>>(dA_hid, dB_w2, mlp_b2, p_xres, out, 256, 1024);
}